// round 8
// baseline (speedup 1.0000x reference)
#include <cuda_runtime.h>
#include <cuda_bf16.h>
#include <math.h>
#include <stdint.h>

#define DMODEL 256
#define BATCH  128
#define NHEAD  4
#define DK     64

// scratch: x, q, k, v, ao  (5 chunks)
#define CHUNK (128ull * 512ull * 256ull)
__device__ float g_scratch[5ull * CHUNK];
// 13 weight matrices, transposed + split: per matrix 131072 bf16:
//   hi[n*256+k] at +0 (65536), lo at +65536.
__device__ __nv_bfloat16 g_wsplit[13ull * 131072ull];

// ---------------------------------------------------------------------------
__device__ __forceinline__ void mma16816(float* c,
                                         uint32_t a0, uint32_t a1, uint32_t a2, uint32_t a3,
                                         uint32_t b0, uint32_t b1) {
    asm volatile(
        "mma.sync.aligned.m16n8k16.row.col.f32.bf16.bf16.f32 "
        "{%0,%1,%2,%3},{%4,%5,%6,%7},{%8,%9},{%0,%1,%2,%3};"
        : "+f"(c[0]), "+f"(c[1]), "+f"(c[2]), "+f"(c[3])
        : "r"(a0), "r"(a1), "r"(a2), "r"(a3), "r"(b0), "r"(b1));
}

// ---------------------------------------------------------------------------
// Weight prep: W[256k,256n] fp32 -> hi/lo bf16 images [n][k] (col-major B).
// ---------------------------------------------------------------------------
struct WP { const float* p[13]; };

__global__ void prep_w(WP wp, __nv_bfloat16* dst) {
    const int mid = blockIdx.y;
    const float* W = wp.p[mid];
    __nv_bfloat16* hi = dst + (size_t)mid * 131072;
    __nv_bfloat16* lo = hi + 65536;
    int idx0 = blockIdx.x * 1024 + threadIdx.x;
    #pragma unroll
    for (int i = 0; i < 4; i++) {
        int idx = idx0 + i * 256;
        int k = idx >> 8, n = idx & 255;
        float x = W[idx];
        __nv_bfloat16 h = __float2bfloat16(x);
        hi[n * 256 + k] = h;
        lo[n * 256 + k] = __float2bfloat16(x - __bfloat162float(h));
    }
}

// ---------------------------------------------------------------------------
// HMMA GEMM: C[M,256] = A[M,256] @ W.
// Epilogues: (+bias,+relu) fp32 | (+bias+resid+LN) fp32 | split-bf16 (scale).
// CTA tile 128x256, 256 threads (2M x 4N warps), warp tile 64x64.
// ---------------------------------------------------------------------------
#define AST 264
#define BST 72
#define GEMM_DYN ((128 * AST * 2 + 256 * BST * 2) * 2)

__global__ __launch_bounds__(256) void gemm_tc(
    const float* __restrict__ A, const __nv_bfloat16* __restrict__ Wsp,
    const float* __restrict__ bias, const float* __restrict__ resid,
    const float* __restrict__ lng, const float* __restrict__ lnb,
    float* __restrict__ C, int relu,
    __nv_bfloat16* __restrict__ Cs, size_t plane, float scale)
{
    extern __shared__ __nv_bfloat16 dsm[];
    __nv_bfloat16* sAhi = dsm;
    __nv_bfloat16* sAlo = sAhi + 128 * AST;
    __nv_bfloat16* sBhi = sAlo + 128 * AST;
    __nv_bfloat16* sBlo = sBhi + 256 * BST;

    __shared__ float s_bias[256], s_g[256], s_b[256];
    __shared__ float s_sum[128], s_ssq[128];

    const int tid = threadIdx.x;
    const int wid = tid >> 5, lane = tid & 31;
    const int wm = wid >> 2, wn = wid & 3;
    const int lq = lane >> 2, lr = lane & 3;
    const int bm = blockIdx.x * 128;

    s_bias[tid] = bias ? bias[tid] : 0.f;
    if (resid) { s_g[tid] = lng[tid]; s_b[tid] = lnb[tid]; }
    if (tid < 128) { s_sum[tid] = 0.f; s_ssq[tid] = 0.f; }

    #pragma unroll
    for (int i = 0; i < 32; i++) {
        int it = tid + i * 256;
        int m = it >> 6, k4 = (it & 63) << 2;
        float4 a = *(const float4*)(A + (size_t)(bm + m) * 256 + k4);
        float h0 = __bfloat162float(__float2bfloat16(a.x));
        float h1 = __bfloat162float(__float2bfloat16(a.y));
        float h2 = __bfloat162float(__float2bfloat16(a.z));
        float h3 = __bfloat162float(__float2bfloat16(a.w));
        __nv_bfloat162 hA = __floats2bfloat162_rn(a.x, a.y);
        __nv_bfloat162 hB = __floats2bfloat162_rn(a.z, a.w);
        __nv_bfloat162 lA = __floats2bfloat162_rn(a.x - h0, a.y - h1);
        __nv_bfloat162 lB = __floats2bfloat162_rn(a.z - h2, a.w - h3);
        uint2 hv = make_uint2(*(uint32_t*)&hA, *(uint32_t*)&hB);
        uint2 lv = make_uint2(*(uint32_t*)&lA, *(uint32_t*)&lB);
        *(uint2*)(sAhi + m * AST + k4) = hv;
        *(uint2*)(sAlo + m * AST + k4) = lv;
    }

    float acc[4][8][4];
    #pragma unroll
    for (int mf = 0; mf < 4; mf++)
        #pragma unroll
        for (int nf = 0; nf < 8; nf++)
            #pragma unroll
            for (int j = 0; j < 4; j++) acc[mf][nf][j] = 0.f;

    const __nv_bfloat16* Whi = Wsp;
    const __nv_bfloat16* Wlo = Wsp + 65536;

    for (int kc = 0; kc < 4; kc++) {
        __syncthreads();
        #pragma unroll
        for (int i = 0; i < 8; i++) {
            int it = tid + i * 256;
            int n = it >> 3, k8 = (it & 7) << 3;
            *(uint4*)(sBhi + n * BST + k8) = *(const uint4*)(Whi + n * 256 + kc * 64 + k8);
            *(uint4*)(sBlo + n * BST + k8) = *(const uint4*)(Wlo + n * 256 + kc * 64 + k8);
        }
        __syncthreads();

        #pragma unroll
        for (int ks = 0; ks < 4; ks++) {
            const int ka = kc * 64 + ks * 16;
            const int kb = ks * 16;
            #pragma unroll
            for (int pass = 0; pass < 3; pass++) {
                const __nv_bfloat16* Ap = (pass == 2) ? sAlo : sAhi;
                const __nv_bfloat16* Bp = (pass == 1) ? sBlo : sBhi;
                uint32_t af[4][4];
                #pragma unroll
                for (int mf = 0; mf < 4; mf++) {
                    const __nv_bfloat16* ab = Ap + (wm * 64 + mf * 16 + lq) * AST + ka + lr * 2;
                    af[mf][0] = *(const uint32_t*)(ab);
                    af[mf][1] = *(const uint32_t*)(ab + 8 * AST);
                    af[mf][2] = *(const uint32_t*)(ab + 8);
                    af[mf][3] = *(const uint32_t*)(ab + 8 * AST + 8);
                }
                uint32_t bfr[8][2];
                #pragma unroll
                for (int nf = 0; nf < 8; nf++) {
                    const __nv_bfloat16* bb2 = Bp + (wn * 64 + nf * 8 + lq) * BST + kb + lr * 2;
                    bfr[nf][0] = *(const uint32_t*)(bb2);
                    bfr[nf][1] = *(const uint32_t*)(bb2 + 8);
                }
                #pragma unroll
                for (int mf = 0; mf < 4; mf++)
                    #pragma unroll
                    for (int nf = 0; nf < 8; nf++)
                        mma16816(acc[mf][nf], af[mf][0], af[mf][1], af[mf][2], af[mf][3],
                                 bfr[nf][0], bfr[nf][1]);
            }
        }
    }
    __syncthreads();

    if (resid) {
        #pragma unroll
        for (int mf = 0; mf < 4; mf++) {
            #pragma unroll
            for (int h = 0; h < 2; h++) {
                int r = wm * 64 + mf * 16 + lq + h * 8;
                const float* Rr = resid + (size_t)(bm + r) * 256;
                float ps = 0.f, pq = 0.f;
                #pragma unroll
                for (int nf = 0; nf < 8; nf++) {
                    int c = wn * 64 + nf * 8 + lr * 2;
                    float2 rv = *(const float2*)(Rr + c);
                    float v0 = acc[mf][nf][h * 2 + 0] + s_bias[c] + rv.x;
                    float v1 = acc[mf][nf][h * 2 + 1] + s_bias[c + 1] + rv.y;
                    acc[mf][nf][h * 2 + 0] = v0;
                    acc[mf][nf][h * 2 + 1] = v1;
                    ps += v0 + v1;
                    pq += v0 * v0 + v1 * v1;
                }
                ps += __shfl_xor_sync(0xffffffffu, ps, 1);
                ps += __shfl_xor_sync(0xffffffffu, ps, 2);
                pq += __shfl_xor_sync(0xffffffffu, pq, 1);
                pq += __shfl_xor_sync(0xffffffffu, pq, 2);
                if (lr == 0) {
                    atomicAdd(&s_sum[r], ps);
                    atomicAdd(&s_ssq[r], pq);
                }
            }
        }
        __syncthreads();
        if (tid < 128) {
            float mu = s_sum[tid] * (1.f / 256.f);
            float var = s_ssq[tid] * (1.f / 256.f) - mu * mu;
            s_sum[tid] = mu;
            s_ssq[tid] = rsqrtf(var + 1e-5f);
        }
        __syncthreads();
        #pragma unroll
        for (int mf = 0; mf < 4; mf++) {
            #pragma unroll
            for (int h = 0; h < 2; h++) {
                int r = wm * 64 + mf * 16 + lq + h * 8;
                float mu = s_sum[r], rs = s_ssq[r];
                float* Cr = C + (size_t)(bm + r) * 256;
                #pragma unroll
                for (int nf = 0; nf < 8; nf++) {
                    int c = wn * 64 + nf * 8 + lr * 2;
                    float2 o;
                    o.x = (acc[mf][nf][h * 2 + 0] - mu) * rs * s_g[c] + s_b[c];
                    o.y = (acc[mf][nf][h * 2 + 1] - mu) * rs * s_g[c + 1] + s_b[c + 1];
                    *(float2*)(Cr + c) = o;
                }
            }
        }
    } else if (Cs) {
        // split-bf16 store (hi plane + lo plane), scale folded (exact pow2)
        #pragma unroll
        for (int mf = 0; mf < 4; mf++) {
            #pragma unroll
            for (int h = 0; h < 2; h++) {
                int r = wm * 64 + mf * 16 + lq + h * 8;
                __nv_bfloat16* Cr = Cs + (size_t)(bm + r) * 256;
                #pragma unroll
                for (int nf = 0; nf < 8; nf++) {
                    int c = wn * 64 + nf * 8 + lr * 2;
                    float v0 = acc[mf][nf][h * 2 + 0] * scale;
                    float v1 = acc[mf][nf][h * 2 + 1] * scale;
                    __nv_bfloat162 hp = __floats2bfloat162_rn(v0, v1);
                    float r0 = v0 - __bfloat162float(__low2bfloat16(hp));
                    float r1 = v1 - __bfloat162float(__high2bfloat16(hp));
                    __nv_bfloat162 lp = __floats2bfloat162_rn(r0, r1);
                    *(__nv_bfloat162*)(Cr + c) = hp;
                    *(__nv_bfloat162*)(Cr + plane + c) = lp;
                }
            }
        }
    } else {
        #pragma unroll
        for (int mf = 0; mf < 4; mf++) {
            #pragma unroll
            for (int h = 0; h < 2; h++) {
                int r = wm * 64 + mf * 16 + lq + h * 8;
                float* Cr = C + (size_t)(bm + r) * 256;
                #pragma unroll
                for (int nf = 0; nf < 8; nf++) {
                    int c = wn * 64 + nf * 8 + lr * 2;
                    float2 o;
                    o.x = acc[mf][nf][h * 2 + 0] + s_bias[c];
                    o.y = acc[mf][nf][h * 2 + 1] + s_bias[c + 1];
                    if (relu) { o.x = fmaxf(o.x, 0.f); o.y = fmaxf(o.y, 0.f); }
                    *(float2*)(Cr + c) = o;
                }
            }
        }
    }
}

// ---------------------------------------------------------------------------
// HMMA attention. CTA = (32-q tile, head, batch). 8 warps (2 M x 4 N).
// Phase1: S = Q K^T (split-bf16 3-pass) -> fp32 smem scores [32][512].
// Softmax fp32. Phase2: per 64-key chunk convert P (gate+inv folded) to
// split bf16, V^T chunk to smem, O += P V (3-pass).
// Q pre-scaled by 1/8 at QKV-GEMM epilogue.
// ---------------------------------------------------------------------------
#define APAD 72
#define ATTN_DYN ((2*32*APAD + 2*64*APAD + 2*32*APAD) * 2 + 32*512*4)  // 102400

__global__ __launch_bounds__(256) void attn_tc(
    const __nv_bfloat16* __restrict__ Qsp, const __nv_bfloat16* __restrict__ Ksp,
    const __nv_bfloat16* __restrict__ Vsp, size_t plane,
    const float* __restrict__ AW, const int* __restrict__ Kcls,
    float* __restrict__ O, int S)
{
    extern __shared__ char smraw[];
    __nv_bfloat16* sQ  = (__nv_bfloat16*)smraw;          // [2][32][APAD]
    __nv_bfloat16* sKV = sQ + 2 * 32 * APAD;             // [2][64][APAD]
    float* sS = (float*)(sKV + 2 * 64 * APAD);           // [32][512]
    __nv_bfloat16* sP = (__nv_bfloat16*)(sS + 32 * 512); // [2][32][APAD]
    __shared__ float tw[6];
    __shared__ float s_inv[32];

    const int b = blockIdx.z, h = blockIdx.y, q0 = blockIdx.x * 32;
    const int tid = threadIdx.x, wid = tid >> 5, lane = tid & 31;
    const int lq = lane >> 2, lr = lane & 3;
    const int wm = wid >> 2, wn = wid & 3;
    if (tid < 6) tw[tid] = tanhf(AW[h * 6 + tid]);
    const int Kc = *Kcls;
    const int NK = S - 1;
    const size_t rowB = (size_t)b * S;
    const int col0 = h * 64;

    // Q tile: 32 rows x 64 cols, hi+lo
    #pragma unroll
    for (int p = 0; p < 2; p++) {
        const __nv_bfloat16* src = Qsp + p * plane;
        __nv_bfloat16* dst = sQ + p * 32 * APAD;
        for (int it = tid; it < 512; it += 256) {
            int r = it >> 4, c4 = (it & 15) * 4;
            uint2 v = make_uint2(0, 0);
            if (q0 + r < S)
                v = *(const uint2*)(src + (rowB + q0 + r) * 256 + col0 + c4);
            *(uint2*)(dst + r * APAD + c4) = v;
        }
    }

    const int SP = (S + 63) >> 6;

    // ---- phase 1: scores ----
    for (int t = 0; t < SP; t++) {
        int k0 = t * 64;
        __syncthreads();
        #pragma unroll
        for (int p = 0; p < 2; p++) {
            const __nv_bfloat16* src = Ksp + p * plane;
            __nv_bfloat16* dst = sKV + p * 64 * APAD;
            for (int it = tid; it < 1024; it += 256) {
                int r = it >> 4, c4 = (it & 15) * 4;
                uint2 v = make_uint2(0, 0);
                if (k0 + r < S)
                    v = *(const uint2*)(src + (rowB + k0 + r) * 256 + col0 + c4);
                *(uint2*)(dst + r * APAD + c4) = v;
            }
        }
        __syncthreads();

        float acc[2][4] = {};
        #pragma unroll
        for (int pass = 0; pass < 3; pass++) {
            const __nv_bfloat16* Ap = sQ + (pass == 2 ? 32 * APAD : 0);
            const __nv_bfloat16* Bp = sKV + (pass == 1 ? 64 * APAD : 0);
            #pragma unroll
            for (int ks = 0; ks < 4; ks++) {
                const __nv_bfloat16* ab = Ap + (wm * 16 + lq) * APAD + ks * 16 + lr * 2;
                uint32_t a0 = *(const uint32_t*)(ab);
                uint32_t a1 = *(const uint32_t*)(ab + 8 * APAD);
                uint32_t a2 = *(const uint32_t*)(ab + 8);
                uint32_t a3 = *(const uint32_t*)(ab + 8 * APAD + 8);
                #pragma unroll
                for (int nf = 0; nf < 2; nf++) {
                    const __nv_bfloat16* bb = Bp + (wn * 16 + nf * 8 + lq) * APAD + ks * 16 + lr * 2;
                    uint32_t b0 = *(const uint32_t*)(bb);
                    uint32_t b1 = *(const uint32_t*)(bb + 8);
                    mma16816(acc[nf], a0, a1, a2, a3, b0, b1);
                }
            }
        }
        #pragma unroll
        for (int nf = 0; nf < 2; nf++) {
            int col = k0 + wn * 16 + nf * 8 + lr * 2;
            *(float2*)(sS + (wm * 16 + lq) * 512 + col) = make_float2(acc[nf][0], acc[nf][1]);
            *(float2*)(sS + (wm * 16 + lq + 8) * 512 + col) = make_float2(acc[nf][2], acc[nf][3]);
        }
    }
    __syncthreads();

    // ---- softmax (fp32, rows per warp) ----
    #pragma unroll
    for (int rr = 0; rr < 4; rr++) {
        int r = wid * 4 + rr;
        int qg = q0 + r;
        float m = -1e30f;
        for (int c = lane; c < S; c += 32) m = fmaxf(m, sS[r * 512 + c]);
        #pragma unroll
        for (int o = 16; o; o >>= 1) m = fmaxf(m, __shfl_xor_sync(0xffffffffu, m, o));
        float sum = 0.f;
        for (int c = lane; c < S; c += 32) {
            float e = __expf(sS[r * 512 + c] - m);
            sS[r * 512 + c] = e;
            sum += e;
        }
        #pragma unroll
        for (int o = 16; o; o >>= 1) sum += __shfl_xor_sync(0xffffffffu, sum, o);
        if (lane == 0) s_inv[r] = (qg < S) ? 1.f / sum : 0.f;
    }
    __syncthreads();

    // ---- phase 2: O = P V ----
    float oacc[2][4] = {};
    const int rP = tid >> 3, cbP = (tid & 7) * 8;
    const int qgP = q0 + rP;
    const int qdiv = (qgP < S) ? qgP / Kc : 0;
    for (int t = 0; t < SP; t++) {
        int k0 = t * 64;
        __syncthreads();
        // V chunk transposed: sKV[d][key]
        #pragma unroll
        for (int p = 0; p < 2; p++) {
            const __nv_bfloat16* src = Vsp + p * plane;
            __nv_bfloat16* dst = sKV + p * 64 * APAD;
            for (int it = tid; it < 1024; it += 256) {
                int r = it >> 4, c4 = (it & 15) * 4;   // r=key, c4=d
                uint2 v = make_uint2(0, 0);
                if (k0 + r < S)
                    v = *(const uint2*)(src + (rowB + k0 + r) * 256 + col0 + c4);
                __nv_bfloat16 e[4];
                *(uint2*)e = v;
                dst[(c4 + 0) * APAD + r] = e[0];
                dst[(c4 + 1) * APAD + r] = e[1];
                dst[(c4 + 2) * APAD + r] = e[2];
                dst[(c4 + 3) * APAD + r] = e[3];
            }
        }
        // convert P chunk (gate + inv folded), split hi/lo
        {
            float inv = s_inv[rP];
            #pragma unroll
            for (int j = 0; j < 8; j++) {
                int c = k0 + cbP + j;
                float pval = 0.f;
                if (c < S) {
                    int cat;
                    if (qgP == NK)      cat = (c == NK) ? 5 : 4;
                    else if (c == NK)   cat = 3;
                    else if (qgP == c)  cat = 0;
                    else if (qdiv == c / Kc) cat = 1;
                    else                cat = 2;
                    pval = sS[rP * 512 + c] * inv * tw[cat];
                }
                __nv_bfloat16 hb = __float2bfloat16(pval);
                sP[rP * APAD + cbP + j] = hb;
                sP[32 * APAD + rP * APAD + cbP + j] =
                    __float2bfloat16(pval - __bfloat162float(hb));
            }
        }
        __syncthreads();

        #pragma unroll
        for (int pass = 0; pass < 3; pass++) {
            const __nv_bfloat16* Ap = sP + (pass == 2 ? 32 * APAD : 0);
            const __nv_bfloat16* Bp = sKV + (pass == 1 ? 64 * APAD : 0);
            #pragma unroll
            for (int ks = 0; ks < 4; ks++) {
                const __nv_bfloat16* ab = Ap + (wm * 16 + lq) * APAD + ks * 16 + lr * 2;
                uint32_t a0 = *(const uint32_t*)(ab);
                uint32_t a1 = *(const uint32_t*)(ab + 8 * APAD);
                uint32_t a2 = *(const uint32_t*)(ab + 8);
                uint32_t a3 = *(const uint32_t*)(ab + 8 * APAD + 8);
                #pragma unroll
                for (int nf = 0; nf < 2; nf++) {
                    const __nv_bfloat16* bb = Bp + (wn * 16 + nf * 8 + lq) * APAD + ks * 16 + lr * 2;
                    uint32_t b0 = *(const uint32_t*)(bb);
                    uint32_t b1 = *(const uint32_t*)(bb + 8);
                    mma16816(oacc[nf], a0, a1, a2, a3, b0, b1);
                }
            }
        }
    }

    #pragma unroll
    for (int nf = 0; nf < 2; nf++) {
        int col = col0 + wn * 16 + nf * 8 + lr * 2;
        int r0a = q0 + wm * 16 + lq;
        if (r0a < S)
            *(float2*)(O + (rowB + r0a) * 256 + col) = make_float2(oacc[nf][0], oacc[nf][1]);
        if (r0a + 8 < S)
            *(float2*)(O + (rowB + r0a + 8) * 256 + col) = make_float2(oacc[nf][2], oacc[nf][3]);
    }
}

// ---------------------------------------------------------------------------
extern "C" void kernel_launch(void* const* d_in, const int* in_sizes, int n_in,
                              void* d_out, int out_size) {
    const float* samples  = (const float*)d_in[0];
    const float* Wq       = (const float*)d_in[1];
    const float* Wk       = (const float*)d_in[2];
    const float* Wv       = (const float*)d_in[3];
    const float* attn_w   = (const float*)d_in[4];
    const float* mha_fc_w = (const float*)d_in[5];
    const float* mha_fc_b = (const float*)d_in[6];
    const float* mha_ln_g = (const float*)d_in[7];
    const float* mha_ln_b = (const float*)d_in[8];
    const float* d_fc1_w  = (const float*)d_in[9];
    const float* d_fc1_b  = (const float*)d_in[10];
    const float* d_fc2_w  = (const float*)d_in[11];
    const float* d_fc2_b  = (const float*)d_in[12];
    const float* d_ln_g   = (const float*)d_in[13];
    const float* d_ln_b   = (const float*)d_in[14];
    const float* out_fc_w = (const float*)d_in[15];
    const float* out_fc_b = (const float*)d_in[16];
    const float* out_ln_g = (const float*)d_in[17];
    const float* out_ln_b = (const float*)d_in[18];
    const int*   Kptr     = (const int*)d_in[20];

    const int S = in_sizes[0] / (BATCH * DMODEL);

    float* base = nullptr;
    cudaGetSymbolAddress((void**)&base, g_scratch);
    float* x  = base + 0 * CHUNK;
    float* qb = base + 1 * CHUNK;
    float* kb = base + 2 * CHUNK;
    float* vb = base + 3 * CHUNK;
    float* ao = base + 4 * CHUNK;

    __nv_bfloat16* qsp = (__nv_bfloat16*)qb;
    __nv_bfloat16* ksp = (__nv_bfloat16*)kb;
    __nv_bfloat16* vsp = (__nv_bfloat16*)vb;
    const size_t plane = (size_t)(BATCH * S) * 256;

    __nv_bfloat16* wsp = nullptr;
    cudaGetSymbolAddress((void**)&wsp, g_wsplit);

    cudaFuncSetAttribute(attn_tc, cudaFuncAttributeMaxDynamicSharedMemorySize, ATTN_DYN);
    cudaFuncSetAttribute(gemm_tc, cudaFuncAttributeMaxDynamicSharedMemorySize, GEMM_DYN);

    WP wp;
    wp.p[0] = Wq;        wp.p[1] = Wq + 65536;
    wp.p[2] = Wk;        wp.p[3] = Wk + 65536;
    wp.p[4] = Wv;        wp.p[5] = Wv + 65536;
    wp.p[6] = mha_fc_w;  wp.p[7] = mha_fc_w + 65536;
    wp.p[8] = d_fc1_w;   wp.p[9] = d_fc1_w + 65536;
    wp.p[10] = d_fc2_w;  wp.p[11] = d_fc2_w + 65536;
    wp.p[12] = out_fc_w;
    prep_w<<<dim3(64, 13), 256>>>(wp, wsp);

    dim3 ga((S + 31) / 32, NHEAD, BATCH);
    const int GR = S;

    for (int l = 0; l < 2; l++) {
        const float* xin = (l == 0) ? samples : x;
        gemm_tc<<<GR, 256, GEMM_DYN>>>(xin, wsp + (size_t)(0 + l) * 131072,
                                       nullptr, nullptr, nullptr, nullptr, nullptr, 0,
                                       qsp, plane, 0.125f);
        gemm_tc<<<GR, 256, GEMM_DYN>>>(xin, wsp + (size_t)(2 + l) * 131072,
                                       nullptr, nullptr, nullptr, nullptr, nullptr, 0,
                                       ksp, plane, 1.0f);
        gemm_tc<<<GR, 256, GEMM_DYN>>>(xin, wsp + (size_t)(4 + l) * 131072,
                                       nullptr, nullptr, nullptr, nullptr, nullptr, 0,
                                       vsp, plane, 1.0f);
        attn_tc<<<ga, 256, ATTN_DYN>>>(qsp, ksp, vsp, plane,
                                       attn_w + l * 24, Kptr, ao, S);
        gemm_tc<<<GR, 256, GEMM_DYN>>>(ao, wsp + (size_t)(6 + l) * 131072,
                                       mha_fc_b + l * 256, xin,
                                       mha_ln_g + l * 256, mha_ln_b + l * 256, x, 0,
                                       nullptr, 0, 1.f);
        gemm_tc<<<GR, 256, GEMM_DYN>>>(x, wsp + (size_t)(8 + l) * 131072,
                                       d_fc1_b + l * 256, nullptr, nullptr, nullptr, qb, 1,
                                       nullptr, 0, 1.f);
        gemm_tc<<<GR, 256, GEMM_DYN>>>(qb, wsp + (size_t)(10 + l) * 131072,
                                       d_fc2_b + l * 256, x,
                                       d_ln_g + l * 256, d_ln_b + l * 256, x, 0,
                                       nullptr, 0, 1.f);
    }
    gemm_tc<<<GR, 256, GEMM_DYN>>>(x, wsp + (size_t)12 * 131072,
                                   out_fc_b, samples, out_ln_g, out_ln_b,
                                   (float*)d_out, 0, nullptr, 0, 1.f);
}

// round 9
// speedup vs baseline: 1.0793x; 1.0793x over previous
#include <cuda_runtime.h>
#include <cuda_bf16.h>
#include <math.h>
#include <stdint.h>

#define DMODEL 256
#define BATCH  128
#define NHEAD  4
#define DK     64

#define CHUNK (128ull * 512ull * 256ull)
__device__ float g_scratch[5ull * CHUNK];
__device__ __nv_bfloat16 g_wsplit[13ull * 131072ull];

// ---------------------------------------------------------------------------
__device__ __forceinline__ uint32_t smem_u32(const void* p) {
    uint32_t a;
    asm("{ .reg .u64 t; cvta.to.shared.u64 t, %1; cvt.u32.u64 %0, t; }" : "=r"(a) : "l"(p));
    return a;
}
__device__ __forceinline__ void mma16816(float* c,
                                         uint32_t a0, uint32_t a1, uint32_t a2, uint32_t a3,
                                         uint32_t b0, uint32_t b1) {
    asm volatile(
        "mma.sync.aligned.m16n8k16.row.col.f32.bf16.bf16.f32 "
        "{%0,%1,%2,%3},{%4,%5,%6,%7},{%8,%9},{%0,%1,%2,%3};"
        : "+f"(c[0]), "+f"(c[1]), "+f"(c[2]), "+f"(c[3])
        : "r"(a0), "r"(a1), "r"(a2), "r"(a3), "r"(b0), "r"(b1));
}
__device__ __forceinline__ void ldsm4(uint32_t* r, uint32_t a) {
    asm volatile("ldmatrix.sync.aligned.m8n8.x4.shared.b16 {%0,%1,%2,%3}, [%4];"
        : "=r"(r[0]), "=r"(r[1]), "=r"(r[2]), "=r"(r[3]) : "r"(a));
}
__device__ __forceinline__ void ldsm4t(uint32_t* r, uint32_t a) {
    asm volatile("ldmatrix.sync.aligned.m8n8.x4.trans.shared.b16 {%0,%1,%2,%3}, [%4];"
        : "=r"(r[0]), "=r"(r[1]), "=r"(r[2]), "=r"(r[3]) : "r"(a));
}

// ---------------------------------------------------------------------------
struct WP { const float* p[13]; };

__global__ void prep_w(WP wp, __nv_bfloat16* dst) {
    const int mid = blockIdx.y;
    const float* W = wp.p[mid];
    __nv_bfloat16* hi = dst + (size_t)mid * 131072;
    __nv_bfloat16* lo = hi + 65536;
    int idx0 = blockIdx.x * 1024 + threadIdx.x;
    #pragma unroll
    for (int i = 0; i < 4; i++) {
        int idx = idx0 + i * 256;
        int k = idx >> 8, n = idx & 255;
        float x = W[idx];
        __nv_bfloat16 h = __float2bfloat16(x);
        hi[n * 256 + k] = h;
        lo[n * 256 + k] = __float2bfloat16(x - __bfloat162float(h));
    }
}

// ---------------------------------------------------------------------------
// HMMA GEMM with ldmatrix fragment loads.
// ---------------------------------------------------------------------------
#define AST 264
#define BST 72
#define GEMM_DYN ((128 * AST * 2 + 256 * BST * 2) * 2)

__global__ __launch_bounds__(256) void gemm_tc(
    const float* __restrict__ A, const __nv_bfloat16* __restrict__ Wsp,
    const float* __restrict__ bias, const float* __restrict__ resid,
    const float* __restrict__ lng, const float* __restrict__ lnb,
    float* __restrict__ C, int relu,
    __nv_bfloat16* __restrict__ Cs, size_t plane, float scale)
{
    extern __shared__ __nv_bfloat16 dsm[];
    __nv_bfloat16* sAhi = dsm;
    __nv_bfloat16* sAlo = sAhi + 128 * AST;
    __nv_bfloat16* sBhi = sAlo + 128 * AST;
    __nv_bfloat16* sBlo = sBhi + 256 * BST;

    __shared__ float s_bias[256], s_g[256], s_b[256];
    __shared__ float s_sum[128], s_ssq[128];

    const int tid = threadIdx.x;
    const int wid = tid >> 5, lane = tid & 31;
    const int wm = wid >> 2, wn = wid & 3;
    const int lq = lane >> 2, lr = lane & 3;
    const int bm = blockIdx.x * 128;

    const uint32_t aHiB = smem_u32(sAhi);
    const uint32_t aLoB = aHiB + 128 * AST * 2;
    const uint32_t bHiB = aLoB + 128 * AST * 2;
    const uint32_t bLoB = bHiB + 256 * BST * 2;
    // ldmatrix lane-address components
    const uint32_t aLM = ((uint32_t)((lane & 15) * AST) + ((lane >> 4) << 3)) * 2;
    const uint32_t bLM = ((uint32_t)((((lane >> 4) << 3) + (lane & 7)) * BST) + (((lane >> 3) & 1) << 3)) * 2;

    s_bias[tid] = bias ? bias[tid] : 0.f;
    if (resid) { s_g[tid] = lng[tid]; s_b[tid] = lnb[tid]; }
    if (tid < 128) { s_sum[tid] = 0.f; s_ssq[tid] = 0.f; }

    #pragma unroll
    for (int i = 0; i < 32; i++) {
        int it = tid + i * 256;
        int m = it >> 6, k4 = (it & 63) << 2;
        float4 a = *(const float4*)(A + (size_t)(bm + m) * 256 + k4);
        float h0 = __bfloat162float(__float2bfloat16(a.x));
        float h1 = __bfloat162float(__float2bfloat16(a.y));
        float h2 = __bfloat162float(__float2bfloat16(a.z));
        float h3 = __bfloat162float(__float2bfloat16(a.w));
        __nv_bfloat162 hA = __floats2bfloat162_rn(a.x, a.y);
        __nv_bfloat162 hB = __floats2bfloat162_rn(a.z, a.w);
        __nv_bfloat162 lA = __floats2bfloat162_rn(a.x - h0, a.y - h1);
        __nv_bfloat162 lB = __floats2bfloat162_rn(a.z - h2, a.w - h3);
        uint2 hv = make_uint2(*(uint32_t*)&hA, *(uint32_t*)&hB);
        uint2 lv = make_uint2(*(uint32_t*)&lA, *(uint32_t*)&lB);
        *(uint2*)(sAhi + m * AST + k4) = hv;
        *(uint2*)(sAlo + m * AST + k4) = lv;
    }

    float acc[4][8][4];
    #pragma unroll
    for (int mf = 0; mf < 4; mf++)
        #pragma unroll
        for (int nf = 0; nf < 8; nf++)
            #pragma unroll
            for (int j = 0; j < 4; j++) acc[mf][nf][j] = 0.f;

    const __nv_bfloat16* Whi = Wsp;
    const __nv_bfloat16* Wlo = Wsp + 65536;

    for (int kc = 0; kc < 4; kc++) {
        __syncthreads();
        #pragma unroll
        for (int i = 0; i < 8; i++) {
            int it = tid + i * 256;
            int n = it >> 3, k8 = (it & 7) << 3;
            *(uint4*)(sBhi + n * BST + k8) = *(const uint4*)(Whi + n * 256 + kc * 64 + k8);
            *(uint4*)(sBlo + n * BST + k8) = *(const uint4*)(Wlo + n * 256 + kc * 64 + k8);
        }
        __syncthreads();

        #pragma unroll
        for (int ks = 0; ks < 4; ks++) {
            const int ka = kc * 64 + ks * 16;
            const int kb = ks * 16;
            #pragma unroll
            for (int pass = 0; pass < 3; pass++) {
                const uint32_t aB = ((pass == 2) ? aLoB : aHiB) + ka * 2 + aLM;
                const uint32_t bB = ((pass == 1) ? bLoB : bHiB) + kb * 2 + bLM;
                uint32_t af[4][4];
                #pragma unroll
                for (int mf = 0; mf < 4; mf++)
                    ldsm4(af[mf], aB + (wm * 64 + mf * 16) * (AST * 2));
                uint32_t bfr[8][2];
                #pragma unroll
                for (int nb = 0; nb < 4; nb++) {
                    uint32_t t[4];
                    ldsm4(t, bB + (wn * 64 + nb * 16) * (BST * 2));
                    bfr[2 * nb][0] = t[0]; bfr[2 * nb][1] = t[1];
                    bfr[2 * nb + 1][0] = t[2]; bfr[2 * nb + 1][1] = t[3];
                }
                #pragma unroll
                for (int mf = 0; mf < 4; mf++)
                    #pragma unroll
                    for (int nf = 0; nf < 8; nf++)
                        mma16816(acc[mf][nf], af[mf][0], af[mf][1], af[mf][2], af[mf][3],
                                 bfr[nf][0], bfr[nf][1]);
            }
        }
    }
    __syncthreads();

    if (resid) {
        #pragma unroll
        for (int mf = 0; mf < 4; mf++) {
            #pragma unroll
            for (int h = 0; h < 2; h++) {
                int r = wm * 64 + mf * 16 + lq + h * 8;
                const float* Rr = resid + (size_t)(bm + r) * 256;
                float ps = 0.f, pq = 0.f;
                #pragma unroll
                for (int nf = 0; nf < 8; nf++) {
                    int c = wn * 64 + nf * 8 + lr * 2;
                    float2 rv = *(const float2*)(Rr + c);
                    float v0 = acc[mf][nf][h * 2 + 0] + s_bias[c] + rv.x;
                    float v1 = acc[mf][nf][h * 2 + 1] + s_bias[c + 1] + rv.y;
                    acc[mf][nf][h * 2 + 0] = v0;
                    acc[mf][nf][h * 2 + 1] = v1;
                    ps += v0 + v1;
                    pq += v0 * v0 + v1 * v1;
                }
                ps += __shfl_xor_sync(0xffffffffu, ps, 1);
                ps += __shfl_xor_sync(0xffffffffu, ps, 2);
                pq += __shfl_xor_sync(0xffffffffu, pq, 1);
                pq += __shfl_xor_sync(0xffffffffu, pq, 2);
                if (lr == 0) {
                    atomicAdd(&s_sum[r], ps);
                    atomicAdd(&s_ssq[r], pq);
                }
            }
        }
        __syncthreads();
        if (tid < 128) {
            float mu = s_sum[tid] * (1.f / 256.f);
            float var = s_ssq[tid] * (1.f / 256.f) - mu * mu;
            s_sum[tid] = mu;
            s_ssq[tid] = rsqrtf(var + 1e-5f);
        }
        __syncthreads();
        #pragma unroll
        for (int mf = 0; mf < 4; mf++) {
            #pragma unroll
            for (int h = 0; h < 2; h++) {
                int r = wm * 64 + mf * 16 + lq + h * 8;
                float mu = s_sum[r], rs = s_ssq[r];
                float* Cr = C + (size_t)(bm + r) * 256;
                #pragma unroll
                for (int nf = 0; nf < 8; nf++) {
                    int c = wn * 64 + nf * 8 + lr * 2;
                    float2 o;
                    o.x = (acc[mf][nf][h * 2 + 0] - mu) * rs * s_g[c] + s_b[c];
                    o.y = (acc[mf][nf][h * 2 + 1] - mu) * rs * s_g[c + 1] + s_b[c + 1];
                    *(float2*)(Cr + c) = o;
                }
            }
        }
    } else if (Cs) {
        #pragma unroll
        for (int mf = 0; mf < 4; mf++) {
            #pragma unroll
            for (int h = 0; h < 2; h++) {
                int r = wm * 64 + mf * 16 + lq + h * 8;
                __nv_bfloat16* Cr = Cs + (size_t)(bm + r) * 256;
                #pragma unroll
                for (int nf = 0; nf < 8; nf++) {
                    int c = wn * 64 + nf * 8 + lr * 2;
                    float v0 = acc[mf][nf][h * 2 + 0] * scale;
                    float v1 = acc[mf][nf][h * 2 + 1] * scale;
                    __nv_bfloat162 hp = __floats2bfloat162_rn(v0, v1);
                    float r0 = v0 - __bfloat162float(__low2bfloat16(hp));
                    float r1 = v1 - __bfloat162float(__high2bfloat16(hp));
                    __nv_bfloat162 lp = __floats2bfloat162_rn(r0, r1);
                    *(__nv_bfloat162*)(Cr + c) = hp;
                    *(__nv_bfloat162*)(Cr + plane + c) = lp;
                }
            }
        }
    } else {
        #pragma unroll
        for (int mf = 0; mf < 4; mf++) {
            #pragma unroll
            for (int h = 0; h < 2; h++) {
                int r = wm * 64 + mf * 16 + lq + h * 8;
                float* Cr = C + (size_t)(bm + r) * 256;
                #pragma unroll
                for (int nf = 0; nf < 8; nf++) {
                    int c = wn * 64 + nf * 8 + lr * 2;
                    float2 o;
                    o.x = acc[mf][nf][h * 2 + 0] + s_bias[c];
                    o.y = acc[mf][nf][h * 2 + 1] + s_bias[c + 1];
                    if (relu) { o.x = fmaxf(o.x, 0.f); o.y = fmaxf(o.y, 0.f); }
                    *(float2*)(Cr + c) = o;
                }
            }
        }
    }
}

// ---------------------------------------------------------------------------
// HMMA attention with ldmatrix + conflict-free score buffer.
// ---------------------------------------------------------------------------
#define APAD 72
#define SST  516
#define ATTN_DYN ((2*32*APAD + 2*64*APAD + 2*32*APAD) * 2 + 32*SST*4 + 512*4)

__global__ __launch_bounds__(256) void attn_tc(
    const __nv_bfloat16* __restrict__ Qsp, const __nv_bfloat16* __restrict__ Ksp,
    const __nv_bfloat16* __restrict__ Vsp, size_t plane,
    const float* __restrict__ AW, const int* __restrict__ Kcls,
    float* __restrict__ O, int S)
{
    extern __shared__ char smraw[];
    __nv_bfloat16* sQ  = (__nv_bfloat16*)smraw;            // [2][32][APAD]
    __nv_bfloat16* sKV = sQ + 2 * 32 * APAD;               // [2][64][APAD]
    float* sS = (float*)(sKV + 2 * 64 * APAD);             // [32][SST]
    __nv_bfloat16* sP = (__nv_bfloat16*)(sS + 32 * SST);   // [2][32][APAD]
    int* sCdiv = (int*)(sP + 2 * 32 * APAD);               // [512]
    __shared__ float tw[6];
    __shared__ float s_inv[32];

    const int b = blockIdx.z, h = blockIdx.y, q0 = blockIdx.x * 32;
    const int tid = threadIdx.x, wid = tid >> 5, lane = tid & 31;
    const int lq = lane >> 2, lr = lane & 3;
    const int wm = wid >> 2, wn = wid & 3;
    if (tid < 6) tw[tid] = tanhf(AW[h * 6 + tid]);
    const int Kc = *Kcls;
    const int NK = S - 1;
    const size_t rowB = (size_t)b * S;
    const int col0 = h * 64;

    sCdiv[tid] = tid / Kc;
    sCdiv[tid + 256] = (tid + 256) / Kc;

    const uint32_t sQB  = smem_u32(sQ);
    const uint32_t sKVB = smem_u32(sKV);
    const uint32_t sPB  = smem_u32(sP);
    const uint32_t PL_Q  = 32 * APAD * 2;   // bytes per plane
    const uint32_t PL_KV = 64 * APAD * 2;
    const uint32_t aLM = ((uint32_t)((lane & 15) * APAD) + ((lane >> 4) << 3)) * 2;
    const uint32_t bLM = ((uint32_t)((((lane >> 4) << 3) + (lane & 7)) * APAD) + (((lane >> 3) & 1) << 3)) * 2;
    const uint32_t vLM = ((uint32_t)(((((lane >> 3) & 1) << 3) + (lane & 7)) * APAD) + (((lane >> 4) & 1) << 3)) * 2;

    // Q tile
    #pragma unroll
    for (int p = 0; p < 2; p++) {
        const __nv_bfloat16* src = Qsp + p * plane;
        __nv_bfloat16* dst = sQ + p * 32 * APAD;
        for (int it = tid; it < 512; it += 256) {
            int r = it >> 4, c4 = (it & 15) * 4;
            uint2 v = make_uint2(0, 0);
            if (q0 + r < S)
                v = *(const uint2*)(src + (rowB + q0 + r) * 256 + col0 + c4);
            *(uint2*)(dst + r * APAD + c4) = v;
        }
    }

    const int SP = (S + 63) >> 6;

    // ---- phase 1: scores ----
    for (int t = 0; t < SP; t++) {
        int k0 = t * 64;
        __syncthreads();
        #pragma unroll
        for (int p = 0; p < 2; p++) {
            const __nv_bfloat16* src = Ksp + p * plane;
            __nv_bfloat16* dst = sKV + p * 64 * APAD;
            for (int it = tid; it < 1024; it += 256) {
                int r = it >> 4, c4 = (it & 15) * 4;
                uint2 v = make_uint2(0, 0);
                if (k0 + r < S)
                    v = *(const uint2*)(src + (rowB + k0 + r) * 256 + col0 + c4);
                *(uint2*)(dst + r * APAD + c4) = v;
            }
        }
        __syncthreads();

        float acc[2][4] = {};
        #pragma unroll
        for (int pass = 0; pass < 3; pass++) {
            const uint32_t aB = sQB + (pass == 2 ? PL_Q : 0) + (wm * 16) * (APAD * 2) + aLM;
            const uint32_t bB = sKVB + (pass == 1 ? PL_KV : 0) + (wn * 16) * (APAD * 2) + bLM;
            #pragma unroll
            for (int ks = 0; ks < 4; ks++) {
                uint32_t af[4], bf2[4];
                ldsm4(af, aB + ks * 32);
                ldsm4(bf2, bB + ks * 32);
                mma16816(acc[0], af[0], af[1], af[2], af[3], bf2[0], bf2[1]);
                mma16816(acc[1], af[0], af[1], af[2], af[3], bf2[2], bf2[3]);
            }
        }
        #pragma unroll
        for (int nf = 0; nf < 2; nf++) {
            int col = k0 + wn * 16 + nf * 8 + lr * 2;
            *(float2*)(sS + (wm * 16 + lq) * SST + col) = make_float2(acc[nf][0], acc[nf][1]);
            *(float2*)(sS + (wm * 16 + lq + 8) * SST + col) = make_float2(acc[nf][2], acc[nf][3]);
        }
    }
    __syncthreads();

    // ---- softmax ----
    #pragma unroll
    for (int rr = 0; rr < 4; rr++) {
        int r = wid * 4 + rr;
        int qg = q0 + r;
        float m = -1e30f;
        for (int c = lane; c < S; c += 32) m = fmaxf(m, sS[r * SST + c]);
        #pragma unroll
        for (int o = 16; o; o >>= 1) m = fmaxf(m, __shfl_xor_sync(0xffffffffu, m, o));
        float sum = 0.f;
        for (int c = lane; c < S; c += 32) {
            float e = __expf(sS[r * SST + c] - m);
            sS[r * SST + c] = e;
            sum += e;
        }
        #pragma unroll
        for (int o = 16; o; o >>= 1) sum += __shfl_xor_sync(0xffffffffu, sum, o);
        if (lane == 0) s_inv[r] = (qg < S) ? 1.f / sum : 0.f;
    }
    __syncthreads();

    // ---- phase 2: O = P V ----
    float oacc[2][4] = {};
    const int rP = tid >> 3, cbP = (tid & 7) * 8;
    const int qgP = q0 + rP;
    const int qdiv = (qgP < S) ? qgP / Kc : -1;
    for (int t = 0; t < SP; t++) {
        int k0 = t * 64;
        __syncthreads();
        // V chunk row-major [key][d]
        #pragma unroll
        for (int p = 0; p < 2; p++) {
            const __nv_bfloat16* src = Vsp + p * plane;
            __nv_bfloat16* dst = sKV + p * 64 * APAD;
            for (int it = tid; it < 1024; it += 256) {
                int r = it >> 4, c4 = (it & 15) * 4;
                uint2 v = make_uint2(0, 0);
                if (k0 + r < S)
                    v = *(const uint2*)(src + (rowB + k0 + r) * 256 + col0 + c4);
                *(uint2*)(dst + r * APAD + c4) = v;
            }
        }
        // convert P chunk
        {
            float inv = s_inv[rP];
            #pragma unroll
            for (int jj = 0; jj < 4; jj++) {
                float pv[2];
                #pragma unroll
                for (int u = 0; u < 2; u++) {
                    int c = k0 + cbP + jj * 2 + u;
                    float pval = 0.f;
                    if (c < S) {
                        int cat;
                        if (qgP == NK)      cat = (c == NK) ? 5 : 4;
                        else if (c == NK)   cat = 3;
                        else if (qgP == c)  cat = 0;
                        else if (qdiv == sCdiv[c]) cat = 1;
                        else                cat = 2;
                        pval = sS[rP * SST + c] * inv * tw[cat];
                    }
                    pv[u] = pval;
                }
                __nv_bfloat162 hp = __floats2bfloat162_rn(pv[0], pv[1]);
                float r0 = pv[0] - __bfloat162float(__low2bfloat16(hp));
                float r1 = pv[1] - __bfloat162float(__high2bfloat16(hp));
                __nv_bfloat162 lp = __floats2bfloat162_rn(r0, r1);
                *(uint32_t*)(sP + rP * APAD + cbP + jj * 2) = *(uint32_t*)&hp;
                *(uint32_t*)(sP + 32 * APAD + rP * APAD + cbP + jj * 2) = *(uint32_t*)&lp;
            }
        }
        __syncthreads();

        #pragma unroll
        for (int pass = 0; pass < 3; pass++) {
            const uint32_t aB = sPB + (pass == 2 ? PL_Q : 0) + (wm * 16) * (APAD * 2) + aLM;
            const uint32_t bB = sKVB + (pass == 1 ? PL_KV : 0) + (wn * 16) * 2 + vLM;
            #pragma unroll
            for (int ks = 0; ks < 4; ks++) {
                uint32_t af[4], bf2[4];
                ldsm4(af, aB + ks * 32);
                ldsm4t(bf2, bB + ks * 16 * (APAD * 2));
                mma16816(oacc[0], af[0], af[1], af[2], af[3], bf2[0], bf2[1]);
                mma16816(oacc[1], af[0], af[1], af[2], af[3], bf2[2], bf2[3]);
            }
        }
    }

    #pragma unroll
    for (int nf = 0; nf < 2; nf++) {
        int col = col0 + wn * 16 + nf * 8 + lr * 2;
        int r0a = q0 + wm * 16 + lq;
        if (r0a < S)
            *(float2*)(O + (rowB + r0a) * 256 + col) = make_float2(oacc[nf][0], oacc[nf][1]);
        if (r0a + 8 < S)
            *(float2*)(O + (rowB + r0a + 8) * 256 + col) = make_float2(oacc[nf][2], oacc[nf][3]);
    }
}

// ---------------------------------------------------------------------------
extern "C" void kernel_launch(void* const* d_in, const int* in_sizes, int n_in,
                              void* d_out, int out_size) {
    const float* samples  = (const float*)d_in[0];
    const float* Wq       = (const float*)d_in[1];
    const float* Wk       = (const float*)d_in[2];
    const float* Wv       = (const float*)d_in[3];
    const float* attn_w   = (const float*)d_in[4];
    const float* mha_fc_w = (const float*)d_in[5];
    const float* mha_fc_b = (const float*)d_in[6];
    const float* mha_ln_g = (const float*)d_in[7];
    const float* mha_ln_b = (const float*)d_in[8];
    const float* d_fc1_w  = (const float*)d_in[9];
    const float* d_fc1_b  = (const float*)d_in[10];
    const float* d_fc2_w  = (const float*)d_in[11];
    const float* d_fc2_b  = (const float*)d_in[12];
    const float* d_ln_g   = (const float*)d_in[13];
    const float* d_ln_b   = (const float*)d_in[14];
    const float* out_fc_w = (const float*)d_in[15];
    const float* out_fc_b = (const float*)d_in[16];
    const float* out_ln_g = (const float*)d_in[17];
    const float* out_ln_b = (const float*)d_in[18];
    const int*   Kptr     = (const int*)d_in[20];

    const int S = in_sizes[0] / (BATCH * DMODEL);

    float* base = nullptr;
    cudaGetSymbolAddress((void**)&base, g_scratch);
    float* x  = base + 0 * CHUNK;
    float* qb = base + 1 * CHUNK;
    float* kb = base + 2 * CHUNK;
    float* vb = base + 3 * CHUNK;
    float* ao = base + 4 * CHUNK;

    __nv_bfloat16* qsp = (__nv_bfloat16*)qb;
    __nv_bfloat16* ksp = (__nv_bfloat16*)kb;
    __nv_bfloat16* vsp = (__nv_bfloat16*)vb;
    const size_t plane = (size_t)(BATCH * S) * 256;

    __nv_bfloat16* wsp = nullptr;
    cudaGetSymbolAddress((void**)&wsp, g_wsplit);

    cudaFuncSetAttribute(attn_tc, cudaFuncAttributeMaxDynamicSharedMemorySize, ATTN_DYN);
    cudaFuncSetAttribute(gemm_tc, cudaFuncAttributeMaxDynamicSharedMemorySize, GEMM_DYN);

    WP wp;
    wp.p[0] = Wq;        wp.p[1] = Wq + 65536;
    wp.p[2] = Wk;        wp.p[3] = Wk + 65536;
    wp.p[4] = Wv;        wp.p[5] = Wv + 65536;
    wp.p[6] = mha_fc_w;  wp.p[7] = mha_fc_w + 65536;
    wp.p[8] = d_fc1_w;   wp.p[9] = d_fc1_w + 65536;
    wp.p[10] = d_fc2_w;  wp.p[11] = d_fc2_w + 65536;
    wp.p[12] = out_fc_w;
    prep_w<<<dim3(64, 13), 256>>>(wp, wsp);

    dim3 ga((S + 31) / 32, NHEAD, BATCH);
    const int GR = S;

    for (int l = 0; l < 2; l++) {
        const float* xin = (l == 0) ? samples : x;
        gemm_tc<<<GR, 256, GEMM_DYN>>>(xin, wsp + (size_t)(0 + l) * 131072,
                                       nullptr, nullptr, nullptr, nullptr, nullptr, 0,
                                       qsp, plane, 0.125f);
        gemm_tc<<<GR, 256, GEMM_DYN>>>(xin, wsp + (size_t)(2 + l) * 131072,
                                       nullptr, nullptr, nullptr, nullptr, nullptr, 0,
                                       ksp, plane, 1.0f);
        gemm_tc<<<GR, 256, GEMM_DYN>>>(xin, wsp + (size_t)(4 + l) * 131072,
                                       nullptr, nullptr, nullptr, nullptr, nullptr, 0,
                                       vsp, plane, 1.0f);
        attn_tc<<<ga, 256, ATTN_DYN>>>(qsp, ksp, vsp, plane,
                                       attn_w + l * 24, Kptr, ao, S);
        gemm_tc<<<GR, 256, GEMM_DYN>>>(ao, wsp + (size_t)(6 + l) * 131072,
                                       mha_fc_b + l * 256, xin,
                                       mha_ln_g + l * 256, mha_ln_b + l * 256, x, 0,
                                       nullptr, 0, 1.f);
        gemm_tc<<<GR, 256, GEMM_DYN>>>(x, wsp + (size_t)(8 + l) * 131072,
                                       d_fc1_b + l * 256, nullptr, nullptr, nullptr, qb, 1,
                                       nullptr, 0, 1.f);
        gemm_tc<<<GR, 256, GEMM_DYN>>>(qb, wsp + (size_t)(10 + l) * 131072,
                                       d_fc2_b + l * 256, x,
                                       d_ln_g + l * 256, d_ln_b + l * 256, x, 0,
                                       nullptr, 0, 1.f);
    }
    gemm_tc<<<GR, 256, GEMM_DYN>>>(x, wsp + (size_t)12 * 131072,
                                   out_fc_b, samples, out_ln_g, out_ln_b,
                                   (float*)d_out, 0, nullptr, 0, 1.f);
}

// round 10
// speedup vs baseline: 1.0977x; 1.0170x over previous
#include <cuda_runtime.h>
#include <cuda_bf16.h>
#include <cuda_fp16.h>
#include <math.h>
#include <stdint.h>

#define DMODEL 256
#define BATCH  128
#define NHEAD  4
#define DK     64

#define CHUNK (128ull * 512ull * 256ull)
__device__ float g_scratch[5ull * CHUNK];
__device__ __nv_bfloat16 g_wsplit[13ull * 131072ull];

// ---------------------------------------------------------------------------
__device__ __forceinline__ uint32_t smem_u32(const void* p) {
    uint32_t a;
    asm("{ .reg .u64 t; cvta.to.shared.u64 t, %1; cvt.u32.u64 %0, t; }" : "=r"(a) : "l"(p));
    return a;
}
__device__ __forceinline__ void mma16816(float* c,
                                         uint32_t a0, uint32_t a1, uint32_t a2, uint32_t a3,
                                         uint32_t b0, uint32_t b1) {
    asm volatile(
        "mma.sync.aligned.m16n8k16.row.col.f32.bf16.bf16.f32 "
        "{%0,%1,%2,%3},{%4,%5,%6,%7},{%8,%9},{%0,%1,%2,%3};"
        : "+f"(c[0]), "+f"(c[1]), "+f"(c[2]), "+f"(c[3])
        : "r"(a0), "r"(a1), "r"(a2), "r"(a3), "r"(b0), "r"(b1));
}
__device__ __forceinline__ void mma16816h(float* c,
                                          uint32_t a0, uint32_t a1, uint32_t a2, uint32_t a3,
                                          uint32_t b0, uint32_t b1) {
    asm volatile(
        "mma.sync.aligned.m16n8k16.row.col.f32.f16.f16.f32 "
        "{%0,%1,%2,%3},{%4,%5,%6,%7},{%8,%9},{%0,%1,%2,%3};"
        : "+f"(c[0]), "+f"(c[1]), "+f"(c[2]), "+f"(c[3])
        : "r"(a0), "r"(a1), "r"(a2), "r"(a3), "r"(b0), "r"(b1));
}
__device__ __forceinline__ void ldsm4(uint32_t* r, uint32_t a) {
    asm volatile("ldmatrix.sync.aligned.m8n8.x4.shared.b16 {%0,%1,%2,%3}, [%4];"
        : "=r"(r[0]), "=r"(r[1]), "=r"(r[2]), "=r"(r[3]) : "r"(a));
}
__device__ __forceinline__ void ldsm4t(uint32_t* r, uint32_t a) {
    asm volatile("ldmatrix.sync.aligned.m8n8.x4.trans.shared.b16 {%0,%1,%2,%3}, [%4];"
        : "=r"(r[0]), "=r"(r[1]), "=r"(r[2]), "=r"(r[3]) : "r"(a));
}

// ---------------------------------------------------------------------------
struct WP { const float* p[13]; };

__global__ void prep_w(WP wp, __nv_bfloat16* dst) {
    const int mid = blockIdx.y;
    const float* W = wp.p[mid];
    __nv_bfloat16* hi = dst + (size_t)mid * 131072;
    __nv_bfloat16* lo = hi + 65536;
    int idx0 = blockIdx.x * 1024 + threadIdx.x;
    #pragma unroll
    for (int i = 0; i < 4; i++) {
        int idx = idx0 + i * 256;
        int k = idx >> 8, n = idx & 255;
        float x = W[idx];
        __nv_bfloat16 h = __float2bfloat16(x);
        hi[n * 256 + k] = h;
        lo[n * 256 + k] = __float2bfloat16(x - __bfloat162float(h));
    }
}

// ---------------------------------------------------------------------------
#define AST 264
#define BST 72
#define GEMM_DYN ((128 * AST * 2 + 256 * BST * 2) * 2)

// shared mainloop: acc += A_smem @ W (3-pass split bf16)
__device__ __forceinline__ void gemm_mainloop(
    const __nv_bfloat16* __restrict__ Whi, __nv_bfloat16* sBhi, __nv_bfloat16* sBlo,
    uint32_t aHiB, uint32_t aLoB, uint32_t bHiB, uint32_t bLoB,
    uint32_t aLM, uint32_t bLM, int wm, int wn, int tid, float acc[4][8][4])
{
    const __nv_bfloat16* Wlo = Whi + 65536;
    for (int kc = 0; kc < 4; kc++) {
        __syncthreads();
        #pragma unroll
        for (int i = 0; i < 8; i++) {
            int it = tid + i * 256;
            int n = it >> 3, k8 = (it & 7) << 3;
            *(uint4*)(sBhi + n * BST + k8) = *(const uint4*)(Whi + n * 256 + kc * 64 + k8);
            *(uint4*)(sBlo + n * BST + k8) = *(const uint4*)(Wlo + n * 256 + kc * 64 + k8);
        }
        __syncthreads();
        #pragma unroll
        for (int ks = 0; ks < 4; ks++) {
            const int ka = kc * 64 + ks * 16;
            const int kb = ks * 16;
            #pragma unroll
            for (int pass = 0; pass < 3; pass++) {
                const uint32_t aB = ((pass == 2) ? aLoB : aHiB) + ka * 2 + aLM;
                const uint32_t bB = ((pass == 1) ? bLoB : bHiB) + kb * 2 + bLM;
                uint32_t af[4][4];
                #pragma unroll
                for (int mf = 0; mf < 4; mf++)
                    ldsm4(af[mf], aB + (wm * 64 + mf * 16) * (AST * 2));
                uint32_t bfr[8][2];
                #pragma unroll
                for (int nb = 0; nb < 4; nb++) {
                    uint32_t t[4];
                    ldsm4(t, bB + (wn * 64 + nb * 16) * (BST * 2));
                    bfr[2 * nb][0] = t[0]; bfr[2 * nb][1] = t[1];
                    bfr[2 * nb + 1][0] = t[2]; bfr[2 * nb + 1][1] = t[3];
                }
                #pragma unroll
                for (int mf = 0; mf < 4; mf++)
                    #pragma unroll
                    for (int nf = 0; nf < 8; nf++)
                        mma16816(acc[mf][nf], af[mf][0], af[mf][1], af[mf][2], af[mf][3],
                                 bfr[nf][0], bfr[nf][1]);
            }
        }
    }
}

__device__ __forceinline__ void load_split_A(
    const float* __restrict__ A, int bm, int tid,
    __nv_bfloat16* sAhi, __nv_bfloat16* sAlo)
{
    #pragma unroll
    for (int i = 0; i < 32; i++) {
        int it = tid + i * 256;
        int m = it >> 6, k4 = (it & 63) << 2;
        float4 a = *(const float4*)(A + (size_t)(bm + m) * 256 + k4);
        float h0 = __bfloat162float(__float2bfloat16(a.x));
        float h1 = __bfloat162float(__float2bfloat16(a.y));
        float h2 = __bfloat162float(__float2bfloat16(a.z));
        float h3 = __bfloat162float(__float2bfloat16(a.w));
        __nv_bfloat162 hA = __floats2bfloat162_rn(a.x, a.y);
        __nv_bfloat162 hB = __floats2bfloat162_rn(a.z, a.w);
        __nv_bfloat162 lA = __floats2bfloat162_rn(a.x - h0, a.y - h1);
        __nv_bfloat162 lB = __floats2bfloat162_rn(a.z - h2, a.w - h3);
        uint2 hv = make_uint2(*(uint32_t*)&hA, *(uint32_t*)&hB);
        uint2 lv = make_uint2(*(uint32_t*)&lA, *(uint32_t*)&lB);
        *(uint2*)(sAhi + m * AST + k4) = hv;
        *(uint2*)(sAlo + m * AST + k4) = lv;
    }
}

// ---------------------------------------------------------------------------
// dense GEMM (+bias/relu or +bias+resid+LN)
// ---------------------------------------------------------------------------
__global__ __launch_bounds__(256) void gemm_tc(
    const float* __restrict__ A, const __nv_bfloat16* __restrict__ Wsp,
    const float* __restrict__ bias, const float* __restrict__ resid,
    const float* __restrict__ lng, const float* __restrict__ lnb,
    float* __restrict__ C, int relu)
{
    extern __shared__ __nv_bfloat16 dsm[];
    __nv_bfloat16* sAhi = dsm;
    __nv_bfloat16* sAlo = sAhi + 128 * AST;
    __nv_bfloat16* sBhi = sAlo + 128 * AST;
    __nv_bfloat16* sBlo = sBhi + 256 * BST;

    __shared__ float s_bias[256], s_g[256], s_b[256];
    __shared__ float s_sum[128], s_ssq[128];

    const int tid = threadIdx.x;
    const int wid = tid >> 5, lane = tid & 31;
    const int wm = wid >> 2, wn = wid & 3;
    const int lq = lane >> 2, lr = lane & 3;
    const int bm = blockIdx.x * 128;

    const uint32_t aHiB = smem_u32(sAhi);
    const uint32_t aLoB = aHiB + 128 * AST * 2;
    const uint32_t bHiB = aLoB + 128 * AST * 2;
    const uint32_t bLoB = bHiB + 256 * BST * 2;
    const uint32_t aLM = ((uint32_t)((lane & 15) * AST) + ((lane >> 4) << 3)) * 2;
    const uint32_t bLM = ((uint32_t)((((lane >> 4) << 3) + (lane & 7)) * BST) + (((lane >> 3) & 1) << 3)) * 2;

    s_bias[tid] = bias ? bias[tid] : 0.f;
    if (resid) { s_g[tid] = lng[tid]; s_b[tid] = lnb[tid]; }
    if (tid < 128) { s_sum[tid] = 0.f; s_ssq[tid] = 0.f; }

    load_split_A(A, bm, tid, sAhi, sAlo);

    float acc[4][8][4];
    #pragma unroll
    for (int mf = 0; mf < 4; mf++)
        #pragma unroll
        for (int nf = 0; nf < 8; nf++)
            #pragma unroll
            for (int j = 0; j < 4; j++) acc[mf][nf][j] = 0.f;

    gemm_mainloop(Wsp, sBhi, sBlo, aHiB, aLoB, bHiB, bLoB, aLM, bLM, wm, wn, tid, acc);
    __syncthreads();

    if (resid) {
        #pragma unroll
        for (int mf = 0; mf < 4; mf++) {
            #pragma unroll
            for (int h = 0; h < 2; h++) {
                int r = wm * 64 + mf * 16 + lq + h * 8;
                const float* Rr = resid + (size_t)(bm + r) * 256;
                float ps = 0.f, pq = 0.f;
                #pragma unroll
                for (int nf = 0; nf < 8; nf++) {
                    int c = wn * 64 + nf * 8 + lr * 2;
                    float2 rv = *(const float2*)(Rr + c);
                    float v0 = acc[mf][nf][h * 2 + 0] + s_bias[c] + rv.x;
                    float v1 = acc[mf][nf][h * 2 + 1] + s_bias[c + 1] + rv.y;
                    acc[mf][nf][h * 2 + 0] = v0;
                    acc[mf][nf][h * 2 + 1] = v1;
                    ps += v0 + v1;
                    pq += v0 * v0 + v1 * v1;
                }
                ps += __shfl_xor_sync(0xffffffffu, ps, 1);
                ps += __shfl_xor_sync(0xffffffffu, ps, 2);
                pq += __shfl_xor_sync(0xffffffffu, pq, 1);
                pq += __shfl_xor_sync(0xffffffffu, pq, 2);
                if (lr == 0) {
                    atomicAdd(&s_sum[r], ps);
                    atomicAdd(&s_ssq[r], pq);
                }
            }
        }
        __syncthreads();
        if (tid < 128) {
            float mu = s_sum[tid] * (1.f / 256.f);
            float var = s_ssq[tid] * (1.f / 256.f) - mu * mu;
            s_sum[tid] = mu;
            s_ssq[tid] = rsqrtf(var + 1e-5f);
        }
        __syncthreads();
        #pragma unroll
        for (int mf = 0; mf < 4; mf++) {
            #pragma unroll
            for (int h = 0; h < 2; h++) {
                int r = wm * 64 + mf * 16 + lq + h * 8;
                float mu = s_sum[r], rs = s_ssq[r];
                float* Cr = C + (size_t)(bm + r) * 256;
                #pragma unroll
                for (int nf = 0; nf < 8; nf++) {
                    int c = wn * 64 + nf * 8 + lr * 2;
                    float2 o;
                    o.x = (acc[mf][nf][h * 2 + 0] - mu) * rs * s_g[c] + s_b[c];
                    o.y = (acc[mf][nf][h * 2 + 1] - mu) * rs * s_g[c + 1] + s_b[c + 1];
                    *(float2*)(Cr + c) = o;
                }
            }
        }
    } else {
        #pragma unroll
        for (int mf = 0; mf < 4; mf++) {
            #pragma unroll
            for (int h = 0; h < 2; h++) {
                int r = wm * 64 + mf * 16 + lq + h * 8;
                float* Cr = C + (size_t)(bm + r) * 256;
                #pragma unroll
                for (int nf = 0; nf < 8; nf++) {
                    int c = wn * 64 + nf * 8 + lr * 2;
                    float2 o;
                    o.x = acc[mf][nf][h * 2 + 0] + s_bias[c];
                    o.y = acc[mf][nf][h * 2 + 1] + s_bias[c + 1];
                    if (relu) { o.x = fmaxf(o.x, 0.f); o.y = fmaxf(o.y, 0.f); }
                    *(float2*)(Cr + c) = o;
                }
            }
        }
    }
}

// ---------------------------------------------------------------------------
// Fused QKV: split A once, run 3 mainloops. Q,K -> bf16 split; V -> f16 split.
// ---------------------------------------------------------------------------
__global__ __launch_bounds__(256) void qkv_tc(
    const float* __restrict__ A,
    const __nv_bfloat16* __restrict__ Wq_, const __nv_bfloat16* __restrict__ Wk_,
    const __nv_bfloat16* __restrict__ Wv_,
    __nv_bfloat16* __restrict__ Qs, __nv_bfloat16* __restrict__ Ks,
    __half* __restrict__ Vs, size_t plane)
{
    extern __shared__ __nv_bfloat16 dsm[];
    __nv_bfloat16* sAhi = dsm;
    __nv_bfloat16* sAlo = sAhi + 128 * AST;
    __nv_bfloat16* sBhi = sAlo + 128 * AST;
    __nv_bfloat16* sBlo = sBhi + 256 * BST;

    const int tid = threadIdx.x;
    const int wid = tid >> 5, lane = tid & 31;
    const int wm = wid >> 2, wn = wid & 3;
    const int lq = lane >> 2, lr = lane & 3;
    const int bm = blockIdx.x * 128;

    const uint32_t aHiB = smem_u32(sAhi);
    const uint32_t aLoB = aHiB + 128 * AST * 2;
    const uint32_t bHiB = aLoB + 128 * AST * 2;
    const uint32_t bLoB = bHiB + 256 * BST * 2;
    const uint32_t aLM = ((uint32_t)((lane & 15) * AST) + ((lane >> 4) << 3)) * 2;
    const uint32_t bLM = ((uint32_t)((((lane >> 4) << 3) + (lane & 7)) * BST) + (((lane >> 3) & 1) << 3)) * 2;

    load_split_A(A, bm, tid, sAhi, sAlo);

    const __nv_bfloat16* Ws[3] = {Wq_, Wk_, Wv_};
    for (int m = 0; m < 3; m++) {
        float acc[4][8][4];
        #pragma unroll
        for (int mf = 0; mf < 4; mf++)
            #pragma unroll
            for (int nf = 0; nf < 8; nf++)
                #pragma unroll
                for (int j = 0; j < 4; j++) acc[mf][nf][j] = 0.f;

        gemm_mainloop(Ws[m], sBhi, sBlo, aHiB, aLoB, bHiB, bLoB, aLM, bLM, wm, wn, tid, acc);

        if (m < 2) {
            float scale = (m == 0) ? 0.125f : 1.0f;
            __nv_bfloat16* Out = (m == 0) ? Qs : Ks;
            #pragma unroll
            for (int mf = 0; mf < 4; mf++) {
                #pragma unroll
                for (int h = 0; h < 2; h++) {
                    int r = wm * 64 + mf * 16 + lq + h * 8;
                    __nv_bfloat16* Cr = Out + (size_t)(bm + r) * 256;
                    #pragma unroll
                    for (int nf = 0; nf < 8; nf++) {
                        int c = wn * 64 + nf * 8 + lr * 2;
                        float v0 = acc[mf][nf][h * 2 + 0] * scale;
                        float v1 = acc[mf][nf][h * 2 + 1] * scale;
                        __nv_bfloat162 hp = __floats2bfloat162_rn(v0, v1);
                        float r0 = v0 - __bfloat162float(__low2bfloat16(hp));
                        float r1 = v1 - __bfloat162float(__high2bfloat16(hp));
                        __nv_bfloat162 lp = __floats2bfloat162_rn(r0, r1);
                        *(__nv_bfloat162*)(Cr + c) = hp;
                        *(__nv_bfloat162*)(Cr + plane + c) = lp;
                    }
                }
            }
        } else {
            #pragma unroll
            for (int mf = 0; mf < 4; mf++) {
                #pragma unroll
                for (int h = 0; h < 2; h++) {
                    int r = wm * 64 + mf * 16 + lq + h * 8;
                    __half* Cr = Vs + (size_t)(bm + r) * 256;
                    #pragma unroll
                    for (int nf = 0; nf < 8; nf++) {
                        int c = wn * 64 + nf * 8 + lr * 2;
                        float v0 = acc[mf][nf][h * 2 + 0];
                        float v1 = acc[mf][nf][h * 2 + 1];
                        __half2 hp = __floats2half2_rn(v0, v1);
                        float r0 = v0 - __half2float(__low2half(hp));
                        float r1 = v1 - __half2float(__high2half(hp));
                        __half2 lp = __floats2half2_rn(r0, r1);
                        *(__half2*)(Cr + c) = hp;
                        *(__half2*)(Cr + plane + c) = lp;
                    }
                }
            }
        }
    }
}

// ---------------------------------------------------------------------------
// HMMA attention, v2: f16x2 exp, gate fused into exp pass, P stored in-place
// in the score buffer (f16), 2-pass P·V with f16-split V.
// ---------------------------------------------------------------------------
#define APAD 72
#define SST  516
#define ATTN_DYN ((2*32*APAD + 2*64*APAD) * 2 + 32*SST*4)

__global__ __launch_bounds__(256) void attn_tc(
    const __nv_bfloat16* __restrict__ Qsp, const __nv_bfloat16* __restrict__ Ksp,
    const __half* __restrict__ Vsp, size_t plane,
    const float* __restrict__ AW, const int* __restrict__ Kcls,
    float* __restrict__ O, int S)
{
    extern __shared__ char smraw[];
    __nv_bfloat16* sQ  = (__nv_bfloat16*)smraw;            // [2][32][APAD] bf16
    __nv_bfloat16* sKV = sQ + 2 * 32 * APAD;               // [2][64][APAD] bf16/f16
    float* sS = (float*)(sKV + 2 * 64 * APAD);             // [32][SST] fp32 / f16 P
    __shared__ float tw[6];
    __shared__ float s_inv[32];

    const int b = blockIdx.z, h = blockIdx.y, q0 = blockIdx.x * 32;
    const int tid = threadIdx.x, wid = tid >> 5, lane = tid & 31;
    const int lq = lane >> 2, lr = lane & 3;
    const int wm = wid >> 2, wn = wid & 3;
    if (tid < 6) tw[tid] = tanhf(AW[h * 6 + tid]);
    const int Kc = *Kcls;
    const int NK = S - 1;
    const size_t rowB = (size_t)b * S;
    const int col0 = h * 64;

    const uint32_t sQB  = smem_u32(sQ);
    const uint32_t sKVB = smem_u32(sKV);
    const uint32_t sSB  = smem_u32(sS);
    const uint32_t PL_Q  = 32 * APAD * 2;
    const uint32_t PL_KV = 64 * APAD * 2;
    const uint32_t aLM = ((uint32_t)((lane & 15) * APAD) + ((lane >> 4) << 3)) * 2;
    const uint32_t bLM = ((uint32_t)((((lane >> 4) << 3) + (lane & 7)) * APAD) + (((lane >> 3) & 1) << 3)) * 2;
    const uint32_t vLM = ((uint32_t)(((((lane >> 3) & 1) << 3) + (lane & 7)) * APAD) + (((lane >> 4) & 1) << 3)) * 2;
    const uint32_t pLM = (uint32_t)(lane & 15) * (SST * 4) + ((lane >> 4) << 4);

    // Q tile (bf16 split planes)
    #pragma unroll
    for (int p = 0; p < 2; p++) {
        const __nv_bfloat16* src = Qsp + p * plane;
        __nv_bfloat16* dst = sQ + p * 32 * APAD;
        for (int it = tid; it < 512; it += 256) {
            int r = it >> 4, c4 = (it & 15) * 4;
            uint2 v = make_uint2(0, 0);
            if (q0 + r < S)
                v = *(const uint2*)(src + (rowB + q0 + r) * 256 + col0 + c4);
            *(uint2*)(dst + r * APAD + c4) = v;
        }
    }

    const int SP = (S + 63) >> 6;

    // ---- phase 1: scores ----
    for (int t = 0; t < SP; t++) {
        int k0 = t * 64;
        __syncthreads();
        #pragma unroll
        for (int p = 0; p < 2; p++) {
            const __nv_bfloat16* src = Ksp + p * plane;
            __nv_bfloat16* dst = sKV + p * 64 * APAD;
            for (int it = tid; it < 1024; it += 256) {
                int r = it >> 4, c4 = (it & 15) * 4;
                uint2 v = make_uint2(0, 0);
                if (k0 + r < S)
                    v = *(const uint2*)(src + (rowB + k0 + r) * 256 + col0 + c4);
                *(uint2*)(dst + r * APAD + c4) = v;
            }
        }
        __syncthreads();

        float acc[2][4] = {};
        #pragma unroll
        for (int pass = 0; pass < 3; pass++) {
            const uint32_t aB = sQB + (pass == 2 ? PL_Q : 0) + (wm * 16) * (APAD * 2) + aLM;
            const uint32_t bB = sKVB + (pass == 1 ? PL_KV : 0) + (wn * 16) * (APAD * 2) + bLM;
            #pragma unroll
            for (int ks = 0; ks < 4; ks++) {
                uint32_t af[4], bf2[4];
                ldsm4(af, aB + ks * 32);
                ldsm4(bf2, bB + ks * 32);
                mma16816(acc[0], af[0], af[1], af[2], af[3], bf2[0], bf2[1]);
                mma16816(acc[1], af[0], af[1], af[2], af[3], bf2[2], bf2[3]);
            }
        }
        #pragma unroll
        for (int nf = 0; nf < 2; nf++) {
            int col = k0 + wn * 16 + nf * 8 + lr * 2;
            *(float2*)(sS + (wm * 16 + lq) * SST + col) = make_float2(acc[nf][0], acc[nf][1]);
            *(float2*)(sS + (wm * 16 + lq + 8) * SST + col) = make_float2(acc[nf][2], acc[nf][3]);
        }
    }
    __syncthreads();

    // ---- softmax + gate, P (f16 pairs) written in place ----
    const float L2E = 1.44269504f;
    const int CP = SP * 64;
    #pragma unroll
    for (int rr = 0; rr < 4; rr++) {
        int r = wid * 4 + rr;
        int qg = q0 + r;
        float* rowp = sS + r * SST;
        float m = -1e30f;
        for (int c = lane; c < S; c += 32) m = fmaxf(m, rowp[c]);
        #pragma unroll
        for (int o = 16; o; o >>= 1) m = fmaxf(m, __shfl_xor_sync(0xffffffffu, m, o));
        float mL = m * L2E;

        const bool isQ = (qg == NK);
        int qdv = qg / Kc;
        int lo = isQ ? -1 : qdv * Kc;
        int hi = isQ ? -1 : lo + Kc;
        float gOut  = isQ ? tw[4] : tw[2];
        float gIn   = isQ ? tw[4] : tw[1];
        float gDiag = isQ ? tw[5] : tw[0];
        float gLast = isQ ? tw[5] : tw[3];

        float sum = 0.f;
        for (int c2 = lane * 2; c2 < CP; c2 += 64) {
            float2 s2 = *(float2*)(rowp + c2);
            int c0 = c2, c1 = c2 + 1;
            float t0v = fmaf(s2.x, L2E, -mL);
            float t1v = fmaf(s2.y, L2E, -mL);
            if (c0 >= S) t0v = -100.f;
            if (c1 >= S) t1v = -100.f;
            __half2 e2 = h2exp2(__floats2half2_rn(t0v, t1v));
            float2 ef = __half22float2(e2);
            sum += ef.x + ef.y;
            float g0 = (c0 >= lo && c0 < hi) ? gIn : gOut;
            float g1 = (c1 >= lo && c1 < hi) ? gIn : gOut;
            if (c0 == qg) g0 = gDiag;
            if (c1 == qg) g1 = gDiag;
            if (c0 == NK) g0 = gLast;
            if (c1 == NK) g1 = gLast;
            __half2 p2 = __hmul2(e2, __floats2half2_rn(g0, g1));
            ((uint32_t*)rowp)[c2 >> 1] = *(uint32_t*)&p2;
        }
        #pragma unroll
        for (int o = 16; o; o >>= 1) sum += __shfl_xor_sync(0xffffffffu, sum, o);
        if (lane == 0) s_inv[r] = 1.f / sum;
    }
    __syncthreads();

    // ---- phase 2: O = (P V) * inv ----
    float oacc[2][4] = {};
    for (int t = 0; t < SP; t++) {
        int k0 = t * 64;
        if (t) __syncthreads();
        // V chunk row-major [key][d], f16, 2 planes
        #pragma unroll
        for (int p = 0; p < 2; p++) {
            const __half* src = Vsp + p * plane;
            __half* dst = (__half*)sKV + p * 64 * APAD;
            for (int it = tid; it < 1024; it += 256) {
                int r = it >> 4, c4 = (it & 15) * 4;
                uint2 v = make_uint2(0, 0);
                if (k0 + r < S)
                    v = *(const uint2*)(src + (rowB + k0 + r) * 256 + col0 + c4);
                *(uint2*)(dst + r * APAD + c4) = v;
            }
        }
        __syncthreads();

        #pragma unroll
        for (int pass = 0; pass < 2; pass++) {
            const uint32_t bB = sKVB + (pass ? PL_KV : 0) + (wn * 16) * 2 + vLM;
            const uint32_t aB = sSB + (wm * 16) * (SST * 4) + k0 * 2 + pLM;
            #pragma unroll
            for (int ks = 0; ks < 4; ks++) {
                uint32_t af[4], bf2[4];
                ldsm4(af, aB + ks * 32);
                ldsm4t(bf2, bB + ks * 16 * (APAD * 2));
                mma16816h(oacc[0], af[0], af[1], af[2], af[3], bf2[0], bf2[1]);
                mma16816h(oacc[1], af[0], af[1], af[2], af[3], bf2[2], bf2[3]);
            }
        }
    }

    const float inv0 = s_inv[wm * 16 + lq];
    const float inv1 = s_inv[wm * 16 + lq + 8];
    #pragma unroll
    for (int nf = 0; nf < 2; nf++) {
        int col = col0 + wn * 16 + nf * 8 + lr * 2;
        int r0a = q0 + wm * 16 + lq;
        if (r0a < S)
            *(float2*)(O + (rowB + r0a) * 256 + col) =
                make_float2(oacc[nf][0] * inv0, oacc[nf][1] * inv0);
        if (r0a + 8 < S)
            *(float2*)(O + (rowB + r0a + 8) * 256 + col) =
                make_float2(oacc[nf][2] * inv1, oacc[nf][3] * inv1);
    }
}

// ---------------------------------------------------------------------------
extern "C" void kernel_launch(void* const* d_in, const int* in_sizes, int n_in,
                              void* d_out, int out_size) {
    const float* samples  = (const float*)d_in[0];
    const float* Wq       = (const float*)d_in[1];
    const float* Wk       = (const float*)d_in[2];
    const float* Wv       = (const float*)d_in[3];
    const float* attn_w   = (const float*)d_in[4];
    const float* mha_fc_w = (const float*)d_in[5];
    const float* mha_fc_b = (const float*)d_in[6];
    const float* mha_ln_g = (const float*)d_in[7];
    const float* mha_ln_b = (const float*)d_in[8];
    const float* d_fc1_w  = (const float*)d_in[9];
    const float* d_fc1_b  = (const float*)d_in[10];
    const float* d_fc2_w  = (const float*)d_in[11];
    const float* d_fc2_b  = (const float*)d_in[12];
    const float* d_ln_g   = (const float*)d_in[13];
    const float* d_ln_b   = (const float*)d_in[14];
    const float* out_fc_w = (const float*)d_in[15];
    const float* out_fc_b = (const float*)d_in[16];
    const float* out_ln_g = (const float*)d_in[17];
    const float* out_ln_b = (const float*)d_in[18];
    const int*   Kptr     = (const int*)d_in[20];

    const int S = in_sizes[0] / (BATCH * DMODEL);

    float* base = nullptr;
    cudaGetSymbolAddress((void**)&base, g_scratch);
    float* x  = base + 0 * CHUNK;
    float* qb = base + 1 * CHUNK;
    float* kb = base + 2 * CHUNK;
    float* vb = base + 3 * CHUNK;
    float* ao = base + 4 * CHUNK;

    __nv_bfloat16* qsp = (__nv_bfloat16*)qb;
    __nv_bfloat16* ksp = (__nv_bfloat16*)kb;
    __half*        vsp = (__half*)vb;
    const size_t plane = (size_t)(BATCH * S) * 256;

    __nv_bfloat16* wsp = nullptr;
    cudaGetSymbolAddress((void**)&wsp, g_wsplit);

    cudaFuncSetAttribute(attn_tc, cudaFuncAttributeMaxDynamicSharedMemorySize, ATTN_DYN);
    cudaFuncSetAttribute(gemm_tc, cudaFuncAttributeMaxDynamicSharedMemorySize, GEMM_DYN);
    cudaFuncSetAttribute(qkv_tc, cudaFuncAttributeMaxDynamicSharedMemorySize, GEMM_DYN);

    WP wp;
    wp.p[0] = Wq;        wp.p[1] = Wq + 65536;
    wp.p[2] = Wk;        wp.p[3] = Wk + 65536;
    wp.p[4] = Wv;        wp.p[5] = Wv + 65536;
    wp.p[6] = mha_fc_w;  wp.p[7] = mha_fc_w + 65536;
    wp.p[8] = d_fc1_w;   wp.p[9] = d_fc1_w + 65536;
    wp.p[10] = d_fc2_w;  wp.p[11] = d_fc2_w + 65536;
    wp.p[12] = out_fc_w;
    prep_w<<<dim3(64, 13), 256>>>(wp, wsp);

    dim3 ga((S + 31) / 32, NHEAD, BATCH);
    const int GR = S;

    for (int l = 0; l < 2; l++) {
        const float* xin = (l == 0) ? samples : x;
        qkv_tc<<<GR, 256, GEMM_DYN>>>(xin,
                                      wsp + (size_t)(0 + l) * 131072,
                                      wsp + (size_t)(2 + l) * 131072,
                                      wsp + (size_t)(4 + l) * 131072,
                                      qsp, ksp, vsp, plane);
        attn_tc<<<ga, 256, ATTN_DYN>>>(qsp, ksp, vsp, plane,
                                       attn_w + l * 24, Kptr, ao, S);
        gemm_tc<<<GR, 256, GEMM_DYN>>>(ao, wsp + (size_t)(6 + l) * 131072,
                                       mha_fc_b + l * 256, xin,
                                       mha_ln_g + l * 256, mha_ln_b + l * 256, x, 0);
        gemm_tc<<<GR, 256, GEMM_DYN>>>(x, wsp + (size_t)(8 + l) * 131072,
                                       d_fc1_b + l * 256, nullptr, nullptr, nullptr, qb, 1);
        gemm_tc<<<GR, 256, GEMM_DYN>>>(qb, wsp + (size_t)(10 + l) * 131072,
                                       d_fc2_b + l * 256, x,
                                       d_ln_g + l * 256, d_ln_b + l * 256, x, 0);
    }
    gemm_tc<<<GR, 256, GEMM_DYN>>>(x, wsp + (size_t)12 * 131072,
                                   out_fc_b, samples, out_ln_g, out_ln_b,
                                   (float*)d_out, 0);
}

// round 11
// speedup vs baseline: 2.4069x; 2.1928x over previous
#include <cuda_runtime.h>
#include <cuda_bf16.h>
#include <cuda_fp16.h>
#include <math.h>
#include <stdint.h>

#define DMODEL 256
#define BATCH  128
#define NHEAD  4
#define DK     64

#define CHUNK (128ull * 512ull * 256ull)
__device__ float g_scratch[5ull * CHUNK];
__device__ __nv_bfloat16 g_wsplit[13ull * 131072ull];

// ---------------------------------------------------------------------------
__device__ __forceinline__ uint32_t smem_u32(const void* p) {
    uint32_t a;
    asm("{ .reg .u64 t; cvta.to.shared.u64 t, %1; cvt.u32.u64 %0, t; }" : "=r"(a) : "l"(p));
    return a;
}
__device__ __forceinline__ void mma16816(float* c,
                                         uint32_t a0, uint32_t a1, uint32_t a2, uint32_t a3,
                                         uint32_t b0, uint32_t b1) {
    asm volatile(
        "mma.sync.aligned.m16n8k16.row.col.f32.bf16.bf16.f32 "
        "{%0,%1,%2,%3},{%4,%5,%6,%7},{%8,%9},{%0,%1,%2,%3};"
        : "+f"(c[0]), "+f"(c[1]), "+f"(c[2]), "+f"(c[3])
        : "r"(a0), "r"(a1), "r"(a2), "r"(a3), "r"(b0), "r"(b1));
}
__device__ __forceinline__ void mma16816h(float* c,
                                          uint32_t a0, uint32_t a1, uint32_t a2, uint32_t a3,
                                          uint32_t b0, uint32_t b1) {
    asm volatile(
        "mma.sync.aligned.m16n8k16.row.col.f32.f16.f16.f32 "
        "{%0,%1,%2,%3},{%4,%5,%6,%7},{%8,%9},{%0,%1,%2,%3};"
        : "+f"(c[0]), "+f"(c[1]), "+f"(c[2]), "+f"(c[3])
        : "r"(a0), "r"(a1), "r"(a2), "r"(a3), "r"(b0), "r"(b1));
}
__device__ __forceinline__ void ldsm4(uint32_t* r, uint32_t a) {
    asm volatile("ldmatrix.sync.aligned.m8n8.x4.shared.b16 {%0,%1,%2,%3}, [%4];"
        : "=r"(r[0]), "=r"(r[1]), "=r"(r[2]), "=r"(r[3]) : "r"(a));
}
__device__ __forceinline__ void ldsm4t(uint32_t* r, uint32_t a) {
    asm volatile("ldmatrix.sync.aligned.m8n8.x4.trans.shared.b16 {%0,%1,%2,%3}, [%4];"
        : "=r"(r[0]), "=r"(r[1]), "=r"(r[2]), "=r"(r[3]) : "r"(a));
}
__device__ __forceinline__ void cp16(uint32_t saddr, const void* g) {
    asm volatile("cp.async.cg.shared.global [%0], [%1], 16;" :: "r"(saddr), "l"(g));
}
__device__ __forceinline__ void sts16z(uint32_t a) {
    asm volatile("st.shared.v4.u32 [%0], {%1,%1,%1,%1};" :: "r"(a), "r"(0u));
}
#define CP_COMMIT() asm volatile("cp.async.commit_group;" ::: "memory")
#define CP_WAIT1()  asm volatile("cp.async.wait_group 1;" ::: "memory")
#define CP_WAIT0()  asm volatile("cp.async.wait_group 0;" ::: "memory")

// ---------------------------------------------------------------------------
struct WP { const float* p[13]; };

__global__ void prep_w(WP wp, __nv_bfloat16* dst) {
    const int mid = blockIdx.y;
    const float* W = wp.p[mid];
    __nv_bfloat16* hi = dst + (size_t)mid * 131072;
    __nv_bfloat16* lo = hi + 65536;
    int idx0 = blockIdx.x * 1024 + threadIdx.x;
    #pragma unroll
    for (int i = 0; i < 4; i++) {
        int idx = idx0 + i * 256;
        int k = idx >> 8, n = idx & 255;
        float x = W[idx];
        __nv_bfloat16 h = __float2bfloat16(x);
        hi[n * 256 + k] = h;
        lo[n * 256 + k] = __float2bfloat16(x - __bfloat162float(h));
    }
}

// ---------------------------------------------------------------------------
// GEMM: CTA tile 64(M) x 256(N), double-buffered B via cp.async.
// smem: A[2][64][AST] + B[2 stages][2 planes][256][BST]
// ---------------------------------------------------------------------------
#define AST 264
#define BST 72
#define APL (64 * AST * 2)          // A plane bytes
#define BPL (256 * BST * 2)         // B plane bytes (36864)
#define BSTG (2 * BPL)              // B stage bytes (73728)
#define GEMM_DYN (2 * APL + 2 * BSTG)   // 215040

__device__ __forceinline__ void issue_B(const __nv_bfloat16* Whi, uint32_t bSt,
                                        int kc, int tid) {
    const __nv_bfloat16* Wlo = Whi + 65536;
    #pragma unroll
    for (int i = 0; i < 8; i++) {
        int it = tid + i * 256;
        int n = it >> 3, k8 = (it & 7) << 3;
        uint32_t d = bSt + (uint32_t)(n * BST + k8) * 2;
        cp16(d, Whi + n * 256 + kc * 64 + k8);
        cp16(d + BPL, Wlo + n * 256 + kc * 64 + k8);
    }
}

__device__ __forceinline__ void load_split_A64(
    const float* __restrict__ A, int bm, int tid,
    __nv_bfloat16* sAhi, __nv_bfloat16* sAlo)
{
    #pragma unroll
    for (int i = 0; i < 16; i++) {
        int it = tid + i * 256;
        int m = it >> 6, k4 = (it & 63) << 2;
        float4 a = *(const float4*)(A + (size_t)(bm + m) * 256 + k4);
        float h0 = __bfloat162float(__float2bfloat16(a.x));
        float h1 = __bfloat162float(__float2bfloat16(a.y));
        float h2 = __bfloat162float(__float2bfloat16(a.z));
        float h3 = __bfloat162float(__float2bfloat16(a.w));
        __nv_bfloat162 hA = __floats2bfloat162_rn(a.x, a.y);
        __nv_bfloat162 hB = __floats2bfloat162_rn(a.z, a.w);
        __nv_bfloat162 lA = __floats2bfloat162_rn(a.x - h0, a.y - h1);
        __nv_bfloat162 lB = __floats2bfloat162_rn(a.z - h2, a.w - h3);
        uint2 hv = make_uint2(*(uint32_t*)&hA, *(uint32_t*)&hB);
        uint2 lv = make_uint2(*(uint32_t*)&lA, *(uint32_t*)&lB);
        *(uint2*)(sAhi + m * AST + k4) = hv;
        *(uint2*)(sAlo + m * AST + k4) = lv;
    }
}

__device__ __forceinline__ void mma_chunk64(
    uint32_t aHiB, uint32_t aLoB, uint32_t bSt, int kcGlob,
    uint32_t aLM, uint32_t bLM, int wid, float acc[4][4][4])
{
    #pragma unroll
    for (int ks = 0; ks < 4; ks++) {
        const int ka = kcGlob * 64 + ks * 16;
        #pragma unroll
        for (int pass = 0; pass < 3; pass++) {
            const uint32_t aB = ((pass == 2) ? aLoB : aHiB) + ka * 2 + aLM;
            const uint32_t bB = bSt + ((pass == 1) ? BPL : 0) + ks * 16 * 2 + bLM;
            uint32_t af[4][4];
            #pragma unroll
            for (int mf = 0; mf < 4; mf++)
                ldsm4(af[mf], aB + (mf * 16) * (AST * 2));
            uint32_t bfr[4][2];
            #pragma unroll
            for (int nb = 0; nb < 2; nb++) {
                uint32_t t[4];
                ldsm4(t, bB + (wid * 32 + nb * 16) * (BST * 2));
                bfr[2 * nb][0] = t[0]; bfr[2 * nb][1] = t[1];
                bfr[2 * nb + 1][0] = t[2]; bfr[2 * nb + 1][1] = t[3];
            }
            #pragma unroll
            for (int mf = 0; mf < 4; mf++)
                #pragma unroll
                for (int nf = 0; nf < 4; nf++)
                    mma16816(acc[mf][nf], af[mf][0], af[mf][1], af[mf][2], af[mf][3],
                             bfr[nf][0], bfr[nf][1]);
        }
    }
}

__global__ __launch_bounds__(256) void gemm_tc(
    const float* __restrict__ A, const __nv_bfloat16* __restrict__ Wsp,
    const float* __restrict__ bias, const float* __restrict__ resid,
    const float* __restrict__ lng, const float* __restrict__ lnb,
    float* __restrict__ C, int relu)
{
    extern __shared__ __nv_bfloat16 dsm[];
    __nv_bfloat16* sAhi = dsm;
    __nv_bfloat16* sAlo = sAhi + 64 * AST;

    __shared__ float s_bias[256], s_g[256], s_b[256];
    __shared__ float s_sum[64], s_ssq[64];

    const int tid = threadIdx.x;
    const int wid = tid >> 5, lane = tid & 31;
    const int lq = lane >> 2, lr = lane & 3;
    const int bm = blockIdx.x * 64;

    const uint32_t aHiB = smem_u32(sAhi);
    const uint32_t aLoB = aHiB + APL;
    const uint32_t bBase = aLoB + APL;
    const uint32_t aLM = ((uint32_t)((lane & 15) * AST) + ((lane >> 4) << 3)) * 2;
    const uint32_t bLM = ((uint32_t)((((lane >> 4) << 3) + (lane & 7)) * BST) + (((lane >> 3) & 1) << 3)) * 2;

    issue_B(Wsp, bBase, 0, tid); CP_COMMIT();

    s_bias[tid] = bias ? bias[tid] : 0.f;
    if (resid) { s_g[tid] = lng[tid]; s_b[tid] = lnb[tid]; }
    if (tid < 64) { s_sum[tid] = 0.f; s_ssq[tid] = 0.f; }

    load_split_A64(A, bm, tid, sAhi, sAlo);

    float acc[4][4][4];
    #pragma unroll
    for (int mf = 0; mf < 4; mf++)
        #pragma unroll
        for (int nf = 0; nf < 4; nf++)
            #pragma unroll
            for (int j = 0; j < 4; j++) acc[mf][nf][j] = 0.f;

    for (int kc = 0; kc < 4; kc++) {
        if (kc < 3) { issue_B(Wsp, bBase + ((kc + 1) & 1) * BSTG, kc + 1, tid); CP_COMMIT(); }
        if (kc < 3) CP_WAIT1(); else CP_WAIT0();
        __syncthreads();
        mma_chunk64(aHiB, aLoB, bBase + (kc & 1) * BSTG, kc, aLM, bLM, wid, acc);
        __syncthreads();
    }

    if (resid) {
        #pragma unroll
        for (int mf = 0; mf < 4; mf++) {
            #pragma unroll
            for (int h = 0; h < 2; h++) {
                int r = mf * 16 + lq + h * 8;
                const float* Rr = resid + (size_t)(bm + r) * 256;
                float ps = 0.f, pq = 0.f;
                #pragma unroll
                for (int nf = 0; nf < 4; nf++) {
                    int c = wid * 32 + nf * 8 + lr * 2;
                    float2 rv = *(const float2*)(Rr + c);
                    float v0 = acc[mf][nf][h * 2 + 0] + s_bias[c] + rv.x;
                    float v1 = acc[mf][nf][h * 2 + 1] + s_bias[c + 1] + rv.y;
                    acc[mf][nf][h * 2 + 0] = v0;
                    acc[mf][nf][h * 2 + 1] = v1;
                    ps += v0 + v1;
                    pq += v0 * v0 + v1 * v1;
                }
                ps += __shfl_xor_sync(0xffffffffu, ps, 1);
                ps += __shfl_xor_sync(0xffffffffu, ps, 2);
                pq += __shfl_xor_sync(0xffffffffu, pq, 1);
                pq += __shfl_xor_sync(0xffffffffu, pq, 2);
                if (lr == 0) {
                    atomicAdd(&s_sum[r], ps);
                    atomicAdd(&s_ssq[r], pq);
                }
            }
        }
        __syncthreads();
        if (tid < 64) {
            float mu = s_sum[tid] * (1.f / 256.f);
            float var = s_ssq[tid] * (1.f / 256.f) - mu * mu;
            s_sum[tid] = mu;
            s_ssq[tid] = rsqrtf(var + 1e-5f);
        }
        __syncthreads();
        #pragma unroll
        for (int mf = 0; mf < 4; mf++) {
            #pragma unroll
            for (int h = 0; h < 2; h++) {
                int r = mf * 16 + lq + h * 8;
                float mu = s_sum[r], rs = s_ssq[r];
                float* Cr = C + (size_t)(bm + r) * 256;
                #pragma unroll
                for (int nf = 0; nf < 4; nf++) {
                    int c = wid * 32 + nf * 8 + lr * 2;
                    float2 o;
                    o.x = (acc[mf][nf][h * 2 + 0] - mu) * rs * s_g[c] + s_b[c];
                    o.y = (acc[mf][nf][h * 2 + 1] - mu) * rs * s_g[c + 1] + s_b[c + 1];
                    *(float2*)(Cr + c) = o;
                }
            }
        }
    } else {
        #pragma unroll
        for (int mf = 0; mf < 4; mf++) {
            #pragma unroll
            for (int h = 0; h < 2; h++) {
                int r = mf * 16 + lq + h * 8;
                float* Cr = C + (size_t)(bm + r) * 256;
                #pragma unroll
                for (int nf = 0; nf < 4; nf++) {
                    int c = wid * 32 + nf * 8 + lr * 2;
                    float2 o;
                    o.x = acc[mf][nf][h * 2 + 0] + s_bias[c];
                    o.y = acc[mf][nf][h * 2 + 1] + s_bias[c + 1];
                    if (relu) { o.x = fmaxf(o.x, 0.f); o.y = fmaxf(o.y, 0.f); }
                    *(float2*)(Cr + c) = o;
                }
            }
        }
    }
}

// ---------------------------------------------------------------------------
// Fused QKV (M=64 tile, 12 pipelined chunks across 3 weights).
// ---------------------------------------------------------------------------
__global__ __launch_bounds__(256) void qkv_tc(
    const float* __restrict__ A,
    const __nv_bfloat16* __restrict__ Wq_, const __nv_bfloat16* __restrict__ Wk_,
    const __nv_bfloat16* __restrict__ Wv_,
    __nv_bfloat16* __restrict__ Qs, __nv_bfloat16* __restrict__ Ks,
    __half* __restrict__ Vs, size_t plane)
{
    extern __shared__ __nv_bfloat16 dsm[];
    __nv_bfloat16* sAhi = dsm;
    __nv_bfloat16* sAlo = sAhi + 64 * AST;

    const int tid = threadIdx.x;
    const int wid = tid >> 5, lane = tid & 31;
    const int lq = lane >> 2, lr = lane & 3;
    const int bm = blockIdx.x * 64;

    const uint32_t aHiB = smem_u32(sAhi);
    const uint32_t aLoB = aHiB + APL;
    const uint32_t bBase = aLoB + APL;
    const uint32_t aLM = ((uint32_t)((lane & 15) * AST) + ((lane >> 4) << 3)) * 2;
    const uint32_t bLM = ((uint32_t)((((lane >> 4) << 3) + (lane & 7)) * BST) + (((lane >> 3) & 1) << 3)) * 2;

    const __nv_bfloat16* Ws[3] = {Wq_, Wk_, Wv_};

    issue_B(Ws[0], bBase, 0, tid); CP_COMMIT();
    load_split_A64(A, bm, tid, sAhi, sAlo);

    float acc[4][4][4];

    for (int c = 0; c < 12; c++) {
        if (c + 1 < 12) {
            issue_B(Ws[(c + 1) >> 2], bBase + ((c + 1) & 1) * BSTG, (c + 1) & 3, tid);
            CP_COMMIT();
        }
        if (c + 1 < 12) CP_WAIT1(); else CP_WAIT0();
        __syncthreads();
        if ((c & 3) == 0) {
            #pragma unroll
            for (int mf = 0; mf < 4; mf++)
                #pragma unroll
                for (int nf = 0; nf < 4; nf++)
                    #pragma unroll
                    for (int j = 0; j < 4; j++) acc[mf][nf][j] = 0.f;
        }
        mma_chunk64(aHiB, aLoB, bBase + (c & 1) * BSTG, c & 3, aLM, bLM, wid, acc);
        __syncthreads();

        if ((c & 3) == 3) {
            int m = c >> 2;
            if (m < 2) {
                float scale = (m == 0) ? 0.125f : 1.0f;
                __nv_bfloat16* Out = (m == 0) ? Qs : Ks;
                #pragma unroll
                for (int mf = 0; mf < 4; mf++) {
                    #pragma unroll
                    for (int h = 0; h < 2; h++) {
                        int r = mf * 16 + lq + h * 8;
                        __nv_bfloat16* Cr = Out + (size_t)(bm + r) * 256;
                        #pragma unroll
                        for (int nf = 0; nf < 4; nf++) {
                            int cc = wid * 32 + nf * 8 + lr * 2;
                            float v0 = acc[mf][nf][h * 2 + 0] * scale;
                            float v1 = acc[mf][nf][h * 2 + 1] * scale;
                            __nv_bfloat162 hp = __floats2bfloat162_rn(v0, v1);
                            float r0 = v0 - __bfloat162float(__low2bfloat16(hp));
                            float r1 = v1 - __bfloat162float(__high2bfloat16(hp));
                            __nv_bfloat162 lp = __floats2bfloat162_rn(r0, r1);
                            *(__nv_bfloat162*)(Cr + cc) = hp;
                            *(__nv_bfloat162*)(Cr + plane + cc) = lp;
                        }
                    }
                }
            } else {
                #pragma unroll
                for (int mf = 0; mf < 4; mf++) {
                    #pragma unroll
                    for (int h = 0; h < 2; h++) {
                        int r = mf * 16 + lq + h * 8;
                        __half* Cr = Vs + (size_t)(bm + r) * 256;
                        #pragma unroll
                        for (int nf = 0; nf < 4; nf++) {
                            int cc = wid * 32 + nf * 8 + lr * 2;
                            float v0 = acc[mf][nf][h * 2 + 0];
                            float v1 = acc[mf][nf][h * 2 + 1];
                            __half2 hp = __floats2half2_rn(v0, v1);
                            float r0 = v0 - __half2float(__low2half(hp));
                            float r1 = v1 - __half2float(__high2half(hp));
                            __half2 lp = __floats2half2_rn(r0, r1);
                            *(__half2*)(Cr + cc) = hp;
                            *(__half2*)(Cr + plane + cc) = lp;
                        }
                    }
                }
            }
        }
    }
}

// ---------------------------------------------------------------------------
// Attention: q-tile 64, cp.async double-buffered K/V, f16 exp, in-place P.
// ---------------------------------------------------------------------------
#define APAD 72
#define SST  516
#define SST4 (SST * 4)
#define QPL  (64 * APAD * 2)
#define KVPL (64 * APAD * 2)
#define KVSTG (2 * KVPL)
#define ATTN_DYN (2 * QPL + 2 * KVSTG + 64 * SST4)   // 187392

__device__ __forceinline__ void issue_kv(const void* base16, size_t plane_el,
                                         size_t rowB, int k0, int col0, int S,
                                         uint32_t dstStage, int tid) {
    // base16: array of 2-byte elements (bf16 or f16), 2 planes of plane_el
    const __nv_bfloat16* src = (const __nv_bfloat16*)base16;
    #pragma unroll
    for (int i = 0; i < 4; i++) {
        int it = tid + i * 256;
        int p = it >> 9, r = (it >> 3) & 63, c8 = (it & 7) << 3;
        uint32_t d = dstStage + p * KVPL + (uint32_t)(r * APAD + c8) * 2;
        if (k0 + r < S)
            cp16(d, src + p * plane_el + (rowB + k0 + r) * 256 + col0 + c8);
        else
            sts16z(d);
    }
}

__global__ __launch_bounds__(256) void attn_tc(
    const __nv_bfloat16* __restrict__ Qsp, const __nv_bfloat16* __restrict__ Ksp,
    const __half* __restrict__ Vsp, size_t plane,
    const float* __restrict__ AW, const int* __restrict__ Kcls,
    float* __restrict__ O, int S)
{
    extern __shared__ char smraw[];
    __nv_bfloat16* sQ  = (__nv_bfloat16*)smraw;               // [2][64][APAD]
    char* sKVc = smraw + 2 * QPL;                             // 2 stages
    float* sS = (float*)(sKVc + 2 * KVSTG);                   // [64][SST]
    __shared__ float tw[6];
    __shared__ float s_inv[64];

    const int b = blockIdx.z, h = blockIdx.y, q0 = blockIdx.x * 64;
    const int tid = threadIdx.x, wid = tid >> 5, lane = tid & 31;
    const int lq = lane >> 2, lr = lane & 3;
    const int wm = wid >> 1, wn = wid & 1;
    const int Kc = *Kcls;
    const int NK = S - 1;
    const size_t rowB = (size_t)b * S;
    const int col0 = h * 64;

    const uint32_t sQB  = smem_u32(sQ);
    const uint32_t sKVB = sQB + 2 * QPL;
    const uint32_t sSB  = sKVB + 2 * KVSTG;
    const uint32_t aLM = ((uint32_t)((lane & 15) * APAD) + ((lane >> 4) << 3)) * 2;
    const uint32_t bLM = ((uint32_t)((((lane >> 4) << 3) + (lane & 7)) * APAD) + (((lane >> 3) & 1) << 3)) * 2;
    const uint32_t vLM = ((uint32_t)(((((lane >> 3) & 1) << 3) + (lane & 7)) * APAD) + (((lane >> 4) & 1) << 3)) * 2;
    const uint32_t pLM = (uint32_t)(lane & 15) * SST4 + ((lane >> 4) << 4);

    const int SP = (S + 63) >> 6;

    // prefetch Q + K0 (group), then K1
    issue_kv(Qsp, plane, rowB, q0, col0, S, sQB, tid);   // Q into sQ (2 planes, 64 rows)
    issue_kv(Ksp, plane, rowB, 0, col0, S, sKVB, tid);
    CP_COMMIT();
    if (tid < 6) tw[tid] = tanhf(AW[h * 6 + tid]);

    // ---- phase 1: scores ----
    for (int t = 0; t < SP; t++) {
        int k0 = t * 64;
        if (t + 1 < SP) {
            issue_kv(Ksp, plane, rowB, (t + 1) * 64, col0, S,
                     sKVB + ((t + 1) & 1) * KVSTG, tid);
            CP_COMMIT();
        }
        if (t + 1 < SP) CP_WAIT1(); else CP_WAIT0();
        __syncthreads();

        const uint32_t kvSt = sKVB + (t & 1) * KVSTG;
        float acc[4][4] = {};
        #pragma unroll
        for (int pass = 0; pass < 3; pass++) {
            const uint32_t aB = sQB + (pass == 2 ? QPL : 0) + (wm * 16) * (APAD * 2) + aLM;
            const uint32_t bB = kvSt + (pass == 1 ? KVPL : 0) + bLM;
            #pragma unroll
            for (int ks = 0; ks < 4; ks++) {
                uint32_t af[4];
                ldsm4(af, aB + ks * 32);
                #pragma unroll
                for (int nb = 0; nb < 2; nb++) {
                    uint32_t bf4[4];
                    ldsm4(bf4, bB + (wn * 32 + nb * 16) * (APAD * 2) + ks * 32);
                    mma16816(acc[nb * 2], af[0], af[1], af[2], af[3], bf4[0], bf4[1]);
                    mma16816(acc[nb * 2 + 1], af[0], af[1], af[2], af[3], bf4[2], bf4[3]);
                }
            }
        }
        #pragma unroll
        for (int nf = 0; nf < 4; nf++) {
            int col = k0 + wn * 32 + nf * 8 + lr * 2;
            *(float2*)(sS + (wm * 16 + lq) * SST + col) = make_float2(acc[nf][0], acc[nf][1]);
            *(float2*)(sS + (wm * 16 + lq + 8) * SST + col) = make_float2(acc[nf][2], acc[nf][3]);
        }
        __syncthreads();
    }

    // prefetch V0 before softmax
    issue_kv(Vsp, plane, rowB, 0, col0, S, sKVB, tid);
    CP_COMMIT();

    // ---- softmax + gate, P f16 in place ----
    const float L2E = 1.44269504f;
    const int CP = SP * 64;
    #pragma unroll
    for (int rr = 0; rr < 8; rr++) {
        int r = wid * 8 + rr;
        int qg = q0 + r;
        float* rowp = sS + r * SST;
        float m = -1e30f;
        for (int c = lane; c < S; c += 32) m = fmaxf(m, rowp[c]);
        #pragma unroll
        for (int o = 16; o; o >>= 1) m = fmaxf(m, __shfl_xor_sync(0xffffffffu, m, o));
        float mL = m * L2E;

        const bool isQ = (qg == NK);
        int qdv = qg / Kc;
        int lo = isQ ? -1 : qdv * Kc;
        int hi = isQ ? -1 : lo + Kc;
        float gOut  = isQ ? tw[4] : tw[2];
        float gIn   = isQ ? tw[4] : tw[1];
        float gDiag = isQ ? tw[5] : tw[0];
        float gLast = isQ ? tw[5] : tw[3];

        float sum = 0.f;
        for (int c2 = lane * 2; c2 < CP; c2 += 64) {
            float2 s2 = *(float2*)(rowp + c2);
            int c0 = c2, c1 = c2 + 1;
            float t0v = fmaf(s2.x, L2E, -mL);
            float t1v = fmaf(s2.y, L2E, -mL);
            if (c0 >= S) t0v = -100.f;
            if (c1 >= S) t1v = -100.f;
            __half2 e2 = h2exp2(__floats2half2_rn(t0v, t1v));
            float2 ef = __half22float2(e2);
            sum += ef.x + ef.y;
            float g0 = (c0 >= lo && c0 < hi) ? gIn : gOut;
            float g1 = (c1 >= lo && c1 < hi) ? gIn : gOut;
            if (c0 == qg) g0 = gDiag;
            if (c1 == qg) g1 = gDiag;
            if (c0 == NK) g0 = gLast;
            if (c1 == NK) g1 = gLast;
            __half2 p2 = __hmul2(e2, __floats2half2_rn(g0, g1));
            ((uint32_t*)rowp)[c2 >> 1] = *(uint32_t*)&p2;
        }
        #pragma unroll
        for (int o = 16; o; o >>= 1) sum += __shfl_xor_sync(0xffffffffu, sum, o);
        if (lane == 0) s_inv[r] = 1.f / sum;
    }
    __syncthreads();

    // ---- phase 2: O = (P V) * inv ----
    float oacc[4][4] = {};
    for (int t = 0; t < SP; t++) {
        int k0 = t * 64;
        if (t + 1 < SP) {
            issue_kv(Vsp, plane, rowB, (t + 1) * 64, col0, S,
                     sKVB + ((t + 1) & 1) * KVSTG, tid);
            CP_COMMIT();
        }
        if (t + 1 < SP) CP_WAIT1(); else CP_WAIT0();
        __syncthreads();

        const uint32_t kvSt = sKVB + (t & 1) * KVSTG;
        const uint32_t aBase = sSB + (wm * 16) * SST4 + k0 * 2 + pLM;
        #pragma unroll
        for (int pass = 0; pass < 2; pass++) {
            const uint32_t bB = kvSt + (pass ? KVPL : 0) + vLM;
            #pragma unroll
            for (int ks = 0; ks < 4; ks++) {
                uint32_t af[4];
                ldsm4(af, aBase + ks * 32);
                #pragma unroll
                for (int nb = 0; nb < 2; nb++) {
                    uint32_t bf4[4];
                    ldsm4t(bf4, bB + (wn * 32 + nb * 16) * 2 + ks * 16 * (APAD * 2));
                    mma16816h(oacc[nb * 2], af[0], af[1], af[2], af[3], bf4[0], bf4[1]);
                    mma16816h(oacc[nb * 2 + 1], af[0], af[1], af[2], af[3], bf4[2], bf4[3]);
                }
            }
        }
        __syncthreads();
    }

    const float inv0 = s_inv[wm * 16 + lq];
    const float inv1 = s_inv[wm * 16 + lq + 8];
    #pragma unroll
    for (int nf = 0; nf < 4; nf++) {
        int col = col0 + wn * 32 + nf * 8 + lr * 2;
        int r0a = q0 + wm * 16 + lq;
        if (r0a < S)
            *(float2*)(O + (rowB + r0a) * 256 + col) =
                make_float2(oacc[nf][0] * inv0, oacc[nf][1] * inv0);
        if (r0a + 8 < S)
            *(float2*)(O + (rowB + r0a + 8) * 256 + col) =
                make_float2(oacc[nf][2] * inv1, oacc[nf][3] * inv1);
    }
}

// ---------------------------------------------------------------------------
extern "C" void kernel_launch(void* const* d_in, const int* in_sizes, int n_in,
                              void* d_out, int out_size) {
    const float* samples  = (const float*)d_in[0];
    const float* Wq       = (const float*)d_in[1];
    const float* Wk       = (const float*)d_in[2];
    const float* Wv       = (const float*)d_in[3];
    const float* attn_w   = (const float*)d_in[4];
    const float* mha_fc_w = (const float*)d_in[5];
    const float* mha_fc_b = (const float*)d_in[6];
    const float* mha_ln_g = (const float*)d_in[7];
    const float* mha_ln_b = (const float*)d_in[8];
    const float* d_fc1_w  = (const float*)d_in[9];
    const float* d_fc1_b  = (const float*)d_in[10];
    const float* d_fc2_w  = (const float*)d_in[11];
    const float* d_fc2_b  = (const float*)d_in[12];
    const float* d_ln_g   = (const float*)d_in[13];
    const float* d_ln_b   = (const float*)d_in[14];
    const float* out_fc_w = (const float*)d_in[15];
    const float* out_fc_b = (const float*)d_in[16];
    const float* out_ln_g = (const float*)d_in[17];
    const float* out_ln_b = (const float*)d_in[18];
    const int*   Kptr     = (const int*)d_in[20];

    const int S = in_sizes[0] / (BATCH * DMODEL);

    float* base = nullptr;
    cudaGetSymbolAddress((void**)&base, g_scratch);
    float* x  = base + 0 * CHUNK;
    float* qb = base + 1 * CHUNK;
    float* kb = base + 2 * CHUNK;
    float* vb = base + 3 * CHUNK;
    float* ao = base + 4 * CHUNK;

    __nv_bfloat16* qsp = (__nv_bfloat16*)qb;
    __nv_bfloat16* ksp = (__nv_bfloat16*)kb;
    __half*        vsp = (__half*)vb;
    const size_t plane = (size_t)(BATCH * S) * 256;

    __nv_bfloat16* wsp = nullptr;
    cudaGetSymbolAddress((void**)&wsp, g_wsplit);

    cudaFuncSetAttribute(attn_tc, cudaFuncAttributeMaxDynamicSharedMemorySize, ATTN_DYN);
    cudaFuncSetAttribute(gemm_tc, cudaFuncAttributeMaxDynamicSharedMemorySize, GEMM_DYN);
    cudaFuncSetAttribute(qkv_tc, cudaFuncAttributeMaxDynamicSharedMemorySize, GEMM_DYN);

    WP wp;
    wp.p[0] = Wq;        wp.p[1] = Wq + 65536;
    wp.p[2] = Wk;        wp.p[3] = Wk + 65536;
    wp.p[4] = Wv;        wp.p[5] = Wv + 65536;
    wp.p[6] = mha_fc_w;  wp.p[7] = mha_fc_w + 65536;
    wp.p[8] = d_fc1_w;   wp.p[9] = d_fc1_w + 65536;
    wp.p[10] = d_fc2_w;  wp.p[11] = d_fc2_w + 65536;
    wp.p[12] = out_fc_w;
    prep_w<<<dim3(64, 13), 256>>>(wp, wsp);

    dim3 ga((S + 63) / 64, NHEAD, BATCH);
    const int GR = (BATCH * S + 63) / 64;

    for (int l = 0; l < 2; l++) {
        const float* xin = (l == 0) ? samples : x;
        qkv_tc<<<GR, 256, GEMM_DYN>>>(xin,
                                      wsp + (size_t)(0 + l) * 131072,
                                      wsp + (size_t)(2 + l) * 131072,
                                      wsp + (size_t)(4 + l) * 131072,
                                      qsp, ksp, vsp, plane);
        attn_tc<<<ga, 256, ATTN_DYN>>>(qsp, ksp, vsp, plane,
                                       attn_w + l * 24, Kptr, ao, S);
        gemm_tc<<<GR, 256, GEMM_DYN>>>(ao, wsp + (size_t)(6 + l) * 131072,
                                       mha_fc_b + l * 256, xin,
                                       mha_ln_g + l * 256, mha_ln_b + l * 256, x, 0);
        gemm_tc<<<GR, 256, GEMM_DYN>>>(x, wsp + (size_t)(8 + l) * 131072,
                                       d_fc1_b + l * 256, nullptr, nullptr, nullptr, qb, 1);
        gemm_tc<<<GR, 256, GEMM_DYN>>>(qb, wsp + (size_t)(10 + l) * 131072,
                                       d_fc2_b + l * 256, x,
                                       d_ln_g + l * 256, d_ln_b + l * 256, x, 0);
    }
    gemm_tc<<<GR, 256, GEMM_DYN>>>(x, wsp + (size_t)12 * 131072,
                                   out_fc_b, samples, out_ln_g, out_ln_b,
                                   (float*)d_out, 0);
}

// round 12
// speedup vs baseline: 2.5447x; 1.0573x over previous
#include <cuda_runtime.h>
#include <cuda_bf16.h>
#include <cuda_fp16.h>
#include <math.h>
#include <stdint.h>

#define DMODEL 256
#define BATCH  128
#define NHEAD  4
#define DK     64

#define CHUNK (128ull * 512ull * 256ull)
__device__ float g_scratch[5ull * CHUNK];
__device__ __nv_bfloat16 g_wsplit[13ull * 131072ull];

// ---------------------------------------------------------------------------
__device__ __forceinline__ uint32_t smem_u32(const void* p) {
    uint32_t a;
    asm("{ .reg .u64 t; cvta.to.shared.u64 t, %1; cvt.u32.u64 %0, t; }" : "=r"(a) : "l"(p));
    return a;
}
__device__ __forceinline__ void mma16816(float* c,
                                         uint32_t a0, uint32_t a1, uint32_t a2, uint32_t a3,
                                         uint32_t b0, uint32_t b1) {
    asm volatile(
        "mma.sync.aligned.m16n8k16.row.col.f32.bf16.bf16.f32 "
        "{%0,%1,%2,%3},{%4,%5,%6,%7},{%8,%9},{%0,%1,%2,%3};"
        : "+f"(c[0]), "+f"(c[1]), "+f"(c[2]), "+f"(c[3])
        : "r"(a0), "r"(a1), "r"(a2), "r"(a3), "r"(b0), "r"(b1));
}
__device__ __forceinline__ void mma16816h(float* c,
                                          uint32_t a0, uint32_t a1, uint32_t a2, uint32_t a3,
                                          uint32_t b0, uint32_t b1) {
    asm volatile(
        "mma.sync.aligned.m16n8k16.row.col.f32.f16.f16.f32 "
        "{%0,%1,%2,%3},{%4,%5,%6,%7},{%8,%9},{%0,%1,%2,%3};"
        : "+f"(c[0]), "+f"(c[1]), "+f"(c[2]), "+f"(c[3])
        : "r"(a0), "r"(a1), "r"(a2), "r"(a3), "r"(b0), "r"(b1));
}
__device__ __forceinline__ void ldsm4(uint32_t* r, uint32_t a) {
    asm volatile("ldmatrix.sync.aligned.m8n8.x4.shared.b16 {%0,%1,%2,%3}, [%4];"
        : "=r"(r[0]), "=r"(r[1]), "=r"(r[2]), "=r"(r[3]) : "r"(a));
}
__device__ __forceinline__ void ldsm4t(uint32_t* r, uint32_t a) {
    asm volatile("ldmatrix.sync.aligned.m8n8.x4.trans.shared.b16 {%0,%1,%2,%3}, [%4];"
        : "=r"(r[0]), "=r"(r[1]), "=r"(r[2]), "=r"(r[3]) : "r"(a));
}
__device__ __forceinline__ void cp16(uint32_t saddr, const void* g) {
    asm volatile("cp.async.cg.shared.global [%0], [%1], 16;" :: "r"(saddr), "l"(g));
}
__device__ __forceinline__ void sts16z(uint32_t a) {
    asm volatile("st.shared.v4.u32 [%0], {%1,%1,%1,%1};" :: "r"(a), "r"(0u));
}
#define CP_COMMIT() asm volatile("cp.async.commit_group;" ::: "memory")
#define CP_WAIT1()  asm volatile("cp.async.wait_group 1;" ::: "memory")
#define CP_WAIT0()  asm volatile("cp.async.wait_group 0;" ::: "memory")

// ---------------------------------------------------------------------------
struct WP { const float* p[13]; };

__global__ void prep_w(WP wp, __nv_bfloat16* dst) {
    const int mid = blockIdx.y;
    const float* W = wp.p[mid];
    __nv_bfloat16* hi = dst + (size_t)mid * 131072;
    __nv_bfloat16* lo = hi + 65536;
    int idx0 = blockIdx.x * 1024 + threadIdx.x;
    #pragma unroll
    for (int i = 0; i < 4; i++) {
        int idx = idx0 + i * 256;
        int k = idx >> 8, n = idx & 255;
        float x = W[idx];
        __nv_bfloat16 h = __float2bfloat16(x);
        hi[n * 256 + k] = h;
        lo[n * 256 + k] = __float2bfloat16(x - __bfloat162float(h));
    }
}

// fp32 -> split bf16 planes
__global__ void conv_split(const float* __restrict__ X, __nv_bfloat16* __restrict__ Osp,
                           size_t planeEl) {
    int i = (blockIdx.x * 256 + threadIdx.x) * 4;
    float4 a = *(const float4*)(X + i);
    __nv_bfloat162 h0 = __floats2bfloat162_rn(a.x, a.y);
    __nv_bfloat162 h1 = __floats2bfloat162_rn(a.z, a.w);
    float r0 = a.x - __bfloat162float(__low2bfloat16(h0));
    float r1 = a.y - __bfloat162float(__high2bfloat16(h0));
    float r2 = a.z - __bfloat162float(__low2bfloat16(h1));
    float r3 = a.w - __bfloat162float(__high2bfloat16(h1));
    __nv_bfloat162 l0 = __floats2bfloat162_rn(r0, r1);
    __nv_bfloat162 l1 = __floats2bfloat162_rn(r2, r3);
    *(__nv_bfloat162*)(Osp + i) = h0;
    *(__nv_bfloat162*)(Osp + i + 2) = h1;
    *(__nv_bfloat162*)(Osp + planeEl + i) = l0;
    *(__nv_bfloat162*)(Osp + planeEl + i + 2) = l1;
}

// ---------------------------------------------------------------------------
// GEMM: 64(M) x 256(N) tile, k-chunks of 32, A+B streamed via cp.async,
// double-buffered, 2 CTAs/SM.
// ---------------------------------------------------------------------------
#define KC   32
#define ST2  40
#define APL2 (64 * ST2 * 2)     // 5120 B per A plane
#define BPL2 (256 * ST2 * 2)    // 20480 B per B plane
#define STG2 (2 * APL2 + 2 * BPL2)  // 51200
#define GEMM_DYN (2 * STG2)         // 102400

__device__ __forceinline__ void issue_chunkA(const __nv_bfloat16* __restrict__ Asp,
                                             size_t planeEl, int bm, int kc,
                                             uint32_t aSt, int tid) {
    #pragma unroll
    for (int i = 0; i < 2; i++) {
        int it = tid + i * 256;
        int p = it >> 8, rem = it & 255, r = rem >> 2, k8 = (rem & 3) << 3;
        uint32_t d = aSt + p * APL2 + (uint32_t)(r * ST2 + k8) * 2;
        cp16(d, Asp + p * planeEl + (size_t)(bm + r) * 256 + kc * KC + k8);
    }
}
__device__ __forceinline__ void issue_chunkB(const __nv_bfloat16* __restrict__ Whi,
                                             int kc, uint32_t bSt, int tid) {
    const __nv_bfloat16* Wlo = Whi + 65536;
    #pragma unroll
    for (int i = 0; i < 8; i++) {
        int it = tid + i * 256;
        int p = it >> 10, rem = it & 1023, n = rem >> 2, k8 = (rem & 3) << 3;
        uint32_t d = bSt + p * BPL2 + (uint32_t)(n * ST2 + k8) * 2;
        cp16(d, (p ? Wlo : Whi) + n * 256 + kc * KC + k8);
    }
}

__device__ __forceinline__ void mma_chunk32(
    uint32_t aSt, uint32_t bSt, uint32_t aLM, uint32_t bLM, int wid, float acc[4][4][4])
{
    #pragma unroll
    for (int ks = 0; ks < 2; ks++) {
        #pragma unroll
        for (int pass = 0; pass < 3; pass++) {
            const uint32_t aB = aSt + ((pass == 2) ? APL2 : 0) + ks * 32 + aLM;
            const uint32_t bB = bSt + ((pass == 1) ? BPL2 : 0) + ks * 32 + bLM;
            uint32_t af[4][4];
            #pragma unroll
            for (int mf = 0; mf < 4; mf++)
                ldsm4(af[mf], aB + (mf * 16) * (ST2 * 2));
            uint32_t bfr[4][2];
            #pragma unroll
            for (int nb = 0; nb < 2; nb++) {
                uint32_t t[4];
                ldsm4(t, bB + (wid * 32 + nb * 16) * (ST2 * 2));
                bfr[2 * nb][0] = t[0]; bfr[2 * nb][1] = t[1];
                bfr[2 * nb + 1][0] = t[2]; bfr[2 * nb + 1][1] = t[3];
            }
            #pragma unroll
            for (int mf = 0; mf < 4; mf++)
                #pragma unroll
                for (int nf = 0; nf < 4; nf++)
                    mma16816(acc[mf][nf], af[mf][0], af[mf][1], af[mf][2], af[mf][3],
                             bfr[nf][0], bfr[nf][1]);
        }
    }
}

__device__ __forceinline__ void split_store(__nv_bfloat16* Cr, size_t planeEl,
                                            int c, float v0, float v1) {
    __nv_bfloat162 hp = __floats2bfloat162_rn(v0, v1);
    float r0 = v0 - __bfloat162float(__low2bfloat16(hp));
    float r1 = v1 - __bfloat162float(__high2bfloat16(hp));
    __nv_bfloat162 lp = __floats2bfloat162_rn(r0, r1);
    *(__nv_bfloat162*)(Cr + c) = hp;
    *(__nv_bfloat162*)(Cr + planeEl + c) = lp;
}

__global__ __launch_bounds__(256, 2) void gemm_tc(
    const __nv_bfloat16* __restrict__ Asp, const __nv_bfloat16* __restrict__ Wsp,
    const float* __restrict__ bias,
    const __nv_bfloat16* __restrict__ residSp, const float* __restrict__ residF,
    const float* __restrict__ lng, const float* __restrict__ lnb,
    __nv_bfloat16* __restrict__ OutSp, float* __restrict__ OutF,
    size_t planeEl, int relu)
{
    extern __shared__ char dsm[];
    __shared__ float s_bias[256], s_g[256], s_b[256];
    __shared__ float s_sum[64], s_ssq[64];

    const int tid = threadIdx.x;
    const int wid = tid >> 5, lane = tid & 31;
    const int lq = lane >> 2, lr = lane & 3;
    const int bm = blockIdx.x * 64;

    const uint32_t base = smem_u32(dsm);
    const uint32_t aLM = ((uint32_t)((lane & 15) * ST2) + ((lane >> 4) << 3)) * 2;
    const uint32_t bLM = ((uint32_t)((((lane >> 4) << 3) + (lane & 7)) * ST2) + (((lane >> 3) & 1) << 3)) * 2;

    issue_chunkA(Asp, planeEl, bm, 0, base, tid);
    issue_chunkB(Wsp, 0, base + 2 * APL2, tid);
    CP_COMMIT();

    s_bias[tid] = bias ? bias[tid] : 0.f;
    if (lng) { s_g[tid] = lng[tid]; s_b[tid] = lnb[tid]; }
    if (tid < 64) { s_sum[tid] = 0.f; s_ssq[tid] = 0.f; }

    float acc[4][4][4];
    #pragma unroll
    for (int mf = 0; mf < 4; mf++)
        #pragma unroll
        for (int nf = 0; nf < 4; nf++)
            #pragma unroll
            for (int j = 0; j < 4; j++) acc[mf][nf][j] = 0.f;

    for (int c = 0; c < 8; c++) {
        if (c < 7) {
            uint32_t st = base + ((c + 1) & 1) * STG2;
            issue_chunkA(Asp, planeEl, bm, c + 1, st, tid);
            issue_chunkB(Wsp, c + 1, st + 2 * APL2, tid);
            CP_COMMIT();
        }
        if (c < 7) CP_WAIT1(); else CP_WAIT0();
        __syncthreads();
        uint32_t st = base + (c & 1) * STG2;
        mma_chunk32(st, st + 2 * APL2, aLM, bLM, wid, acc);
        __syncthreads();
    }

    if (lng) {
        // bias + residual + LN
        float rv[4][2][2];
        #pragma unroll
        for (int mf = 0; mf < 4; mf++) {
            #pragma unroll
            for (int h = 0; h < 2; h++) {
                int r = mf * 16 + lq + h * 8;
                float ps = 0.f, pq = 0.f;
                #pragma unroll
                for (int nf = 0; nf < 4; nf++) {
                    int c = wid * 32 + nf * 8 + lr * 2;
                    float rv0, rv1;
                    if (residF) {
                        float2 t = *(const float2*)(residF + (size_t)(bm + r) * 256 + c);
                        rv0 = t.x; rv1 = t.y;
                    } else {
                        __nv_bfloat162 h2 = *(const __nv_bfloat162*)(residSp + (size_t)(bm + r) * 256 + c);
                        __nv_bfloat162 l2 = *(const __nv_bfloat162*)(residSp + planeEl + (size_t)(bm + r) * 256 + c);
                        rv0 = __bfloat162float(__low2bfloat16(h2)) + __bfloat162float(__low2bfloat16(l2));
                        rv1 = __bfloat162float(__high2bfloat16(h2)) + __bfloat162float(__high2bfloat16(l2));
                    }
                    float v0 = acc[mf][nf][h * 2 + 0] + s_bias[c] + rv0;
                    float v1 = acc[mf][nf][h * 2 + 1] + s_bias[c + 1] + rv1;
                    acc[mf][nf][h * 2 + 0] = v0;
                    acc[mf][nf][h * 2 + 1] = v1;
                    ps += v0 + v1;
                    pq += v0 * v0 + v1 * v1;
                }
                ps += __shfl_xor_sync(0xffffffffu, ps, 1);
                ps += __shfl_xor_sync(0xffffffffu, ps, 2);
                pq += __shfl_xor_sync(0xffffffffu, pq, 1);
                pq += __shfl_xor_sync(0xffffffffu, pq, 2);
                if (lr == 0) {
                    atomicAdd(&s_sum[r], ps);
                    atomicAdd(&s_ssq[r], pq);
                }
                (void)rv;
            }
        }
        __syncthreads();
        if (tid < 64) {
            float mu = s_sum[tid] * (1.f / 256.f);
            float var = s_ssq[tid] * (1.f / 256.f) - mu * mu;
            s_sum[tid] = mu;
            s_ssq[tid] = rsqrtf(var + 1e-5f);
        }
        __syncthreads();
        #pragma unroll
        for (int mf = 0; mf < 4; mf++) {
            #pragma unroll
            for (int h = 0; h < 2; h++) {
                int r = mf * 16 + lq + h * 8;
                float mu = s_sum[r], rs = s_ssq[r];
                #pragma unroll
                for (int nf = 0; nf < 4; nf++) {
                    int c = wid * 32 + nf * 8 + lr * 2;
                    float v0 = (acc[mf][nf][h * 2 + 0] - mu) * rs * s_g[c] + s_b[c];
                    float v1 = (acc[mf][nf][h * 2 + 1] - mu) * rs * s_g[c + 1] + s_b[c + 1];
                    if (OutF)
                        *(float2*)(OutF + (size_t)(bm + r) * 256 + c) = make_float2(v0, v1);
                    else
                        split_store(OutSp + (size_t)(bm + r) * 256, planeEl, c, v0, v1);
                }
            }
        }
    } else {
        #pragma unroll
        for (int mf = 0; mf < 4; mf++) {
            #pragma unroll
            for (int h = 0; h < 2; h++) {
                int r = mf * 16 + lq + h * 8;
                #pragma unroll
                for (int nf = 0; nf < 4; nf++) {
                    int c = wid * 32 + nf * 8 + lr * 2;
                    float v0 = acc[mf][nf][h * 2 + 0] + s_bias[c];
                    float v1 = acc[mf][nf][h * 2 + 1] + s_bias[c + 1];
                    if (relu) { v0 = fmaxf(v0, 0.f); v1 = fmaxf(v1, 0.f); }
                    split_store(OutSp + (size_t)(bm + r) * 256, planeEl, c, v0, v1);
                }
            }
        }
    }
}

// ---------------------------------------------------------------------------
// Fused QKV: 24 streamed chunks (3 weights x 8), A re-streamed per weight.
// ---------------------------------------------------------------------------
__global__ __launch_bounds__(256, 2) void qkv_tc(
    const __nv_bfloat16* __restrict__ Asp,
    const __nv_bfloat16* __restrict__ Wq_, const __nv_bfloat16* __restrict__ Wk_,
    const __nv_bfloat16* __restrict__ Wv_,
    __nv_bfloat16* __restrict__ Qs, __nv_bfloat16* __restrict__ Ks,
    __half* __restrict__ Vs, size_t planeEl)
{
    extern __shared__ char dsm[];
    const int tid = threadIdx.x;
    const int wid = tid >> 5, lane = tid & 31;
    const int lq = lane >> 2, lr = lane & 3;
    const int bm = blockIdx.x * 64;

    const uint32_t base = smem_u32(dsm);
    const uint32_t aLM = ((uint32_t)((lane & 15) * ST2) + ((lane >> 4) << 3)) * 2;
    const uint32_t bLM = ((uint32_t)((((lane >> 4) << 3) + (lane & 7)) * ST2) + (((lane >> 3) & 1) << 3)) * 2;

    const __nv_bfloat16* Ws[3] = {Wq_, Wk_, Wv_};

    issue_chunkA(Asp, planeEl, bm, 0, base, tid);
    issue_chunkB(Ws[0], 0, base + 2 * APL2, tid);
    CP_COMMIT();

    float acc[4][4][4];

    for (int c = 0; c < 24; c++) {
        if (c + 1 < 24) {
            uint32_t st = base + ((c + 1) & 1) * STG2;
            issue_chunkA(Asp, planeEl, bm, (c + 1) & 7, st, tid);
            issue_chunkB(Ws[(c + 1) >> 3], (c + 1) & 7, st + 2 * APL2, tid);
            CP_COMMIT();
        }
        if (c + 1 < 24) CP_WAIT1(); else CP_WAIT0();
        __syncthreads();
        if ((c & 7) == 0) {
            #pragma unroll
            for (int mf = 0; mf < 4; mf++)
                #pragma unroll
                for (int nf = 0; nf < 4; nf++)
                    #pragma unroll
                    for (int j = 0; j < 4; j++) acc[mf][nf][j] = 0.f;
        }
        uint32_t st = base + (c & 1) * STG2;
        mma_chunk32(st, st + 2 * APL2, aLM, bLM, wid, acc);
        __syncthreads();

        if ((c & 7) == 7) {
            int m = c >> 3;
            if (m < 2) {
                float scale = (m == 0) ? 0.125f : 1.0f;
                __nv_bfloat16* Out = (m == 0) ? Qs : Ks;
                #pragma unroll
                for (int mf = 0; mf < 4; mf++)
                    #pragma unroll
                    for (int h = 0; h < 2; h++) {
                        int r = mf * 16 + lq + h * 8;
                        #pragma unroll
                        for (int nf = 0; nf < 4; nf++) {
                            int cc = wid * 32 + nf * 8 + lr * 2;
                            split_store(Out + (size_t)(bm + r) * 256, planeEl, cc,
                                        acc[mf][nf][h * 2 + 0] * scale,
                                        acc[mf][nf][h * 2 + 1] * scale);
                        }
                    }
            } else {
                #pragma unroll
                for (int mf = 0; mf < 4; mf++)
                    #pragma unroll
                    for (int h = 0; h < 2; h++) {
                        int r = mf * 16 + lq + h * 8;
                        __half* Cr = Vs + (size_t)(bm + r) * 256;
                        #pragma unroll
                        for (int nf = 0; nf < 4; nf++) {
                            int cc = wid * 32 + nf * 8 + lr * 2;
                            float v0 = acc[mf][nf][h * 2 + 0];
                            float v1 = acc[mf][nf][h * 2 + 1];
                            __half2 hp = __floats2half2_rn(v0, v1);
                            float r0 = v0 - __half2float(__low2half(hp));
                            float r1 = v1 - __half2float(__high2half(hp));
                            __half2 lp = __floats2half2_rn(r0, r1);
                            *(__half2*)(Cr + cc) = hp;
                            *(__half2*)(Cr + planeEl + cc) = lp;
                        }
                    }
            }
        }
    }
}

// ---------------------------------------------------------------------------
// Attention (as R11) with split-bf16 output.
// ---------------------------------------------------------------------------
#define APAD 72
#define SST  516
#define SST4 (SST * 4)
#define QPL  (64 * APAD * 2)
#define KVPL (64 * APAD * 2)
#define KVSTG (2 * KVPL)
#define ATTN_DYN (2 * QPL + 2 * KVSTG + 64 * SST4)

__device__ __forceinline__ void issue_kv(const void* base16, size_t plane_el,
                                         size_t rowB, int k0, int col0, int S,
                                         uint32_t dstStage, int tid) {
    const __nv_bfloat16* src = (const __nv_bfloat16*)base16;
    #pragma unroll
    for (int i = 0; i < 4; i++) {
        int it = tid + i * 256;
        int p = it >> 9, r = (it >> 3) & 63, c8 = (it & 7) << 3;
        uint32_t d = dstStage + p * KVPL + (uint32_t)(r * APAD + c8) * 2;
        if (k0 + r < S)
            cp16(d, src + p * plane_el + (rowB + k0 + r) * 256 + col0 + c8);
        else
            sts16z(d);
    }
}

__global__ __launch_bounds__(256) void attn_tc(
    const __nv_bfloat16* __restrict__ Qsp, const __nv_bfloat16* __restrict__ Ksp,
    const __half* __restrict__ Vsp, size_t plane,
    const float* __restrict__ AW, const int* __restrict__ Kcls,
    __nv_bfloat16* __restrict__ Osp, int S)
{
    extern __shared__ char smraw[];
    float* sS = (float*)(smraw + 2 * QPL + 2 * KVSTG);
    __shared__ float tw[6];
    __shared__ float s_inv[64];

    const int b = blockIdx.z, h = blockIdx.y, q0 = blockIdx.x * 64;
    const int tid = threadIdx.x, wid = tid >> 5, lane = tid & 31;
    const int lq = lane >> 2, lr = lane & 3;
    const int wm = wid >> 1, wn = wid & 1;
    const int Kc = *Kcls;
    const int NK = S - 1;
    const size_t rowB = (size_t)b * S;
    const int col0 = h * 64;

    const uint32_t sQB  = smem_u32(smraw);
    const uint32_t sKVB = sQB + 2 * QPL;
    const uint32_t sSB  = sKVB + 2 * KVSTG;
    const uint32_t aLM = ((uint32_t)((lane & 15) * APAD) + ((lane >> 4) << 3)) * 2;
    const uint32_t bLM = ((uint32_t)((((lane >> 4) << 3) + (lane & 7)) * APAD) + (((lane >> 3) & 1) << 3)) * 2;
    const uint32_t vLM = ((uint32_t)(((((lane >> 3) & 1) << 3) + (lane & 7)) * APAD) + (((lane >> 4) & 1) << 3)) * 2;
    const uint32_t pLM = (uint32_t)(lane & 15) * SST4 + ((lane >> 4) << 4);

    const int SP = (S + 63) >> 6;

    issue_kv(Qsp, plane, rowB, q0, col0, S, sQB, tid);
    issue_kv(Ksp, plane, rowB, 0, col0, S, sKVB, tid);
    CP_COMMIT();
    if (tid < 6) tw[tid] = tanhf(AW[h * 6 + tid]);

    for (int t = 0; t < SP; t++) {
        int k0 = t * 64;
        if (t + 1 < SP) {
            issue_kv(Ksp, plane, rowB, (t + 1) * 64, col0, S,
                     sKVB + ((t + 1) & 1) * KVSTG, tid);
            CP_COMMIT();
        }
        if (t + 1 < SP) CP_WAIT1(); else CP_WAIT0();
        __syncthreads();

        const uint32_t kvSt = sKVB + (t & 1) * KVSTG;
        float acc[4][4] = {};
        #pragma unroll
        for (int pass = 0; pass < 3; pass++) {
            const uint32_t aB = sQB + (pass == 2 ? QPL : 0) + (wm * 16) * (APAD * 2) + aLM;
            const uint32_t bB = kvSt + (pass == 1 ? KVPL : 0) + bLM;
            #pragma unroll
            for (int ks = 0; ks < 4; ks++) {
                uint32_t af[4];
                ldsm4(af, aB + ks * 32);
                #pragma unroll
                for (int nb = 0; nb < 2; nb++) {
                    uint32_t bf4[4];
                    ldsm4(bf4, bB + (wn * 32 + nb * 16) * (APAD * 2) + ks * 32);
                    mma16816(acc[nb * 2], af[0], af[1], af[2], af[3], bf4[0], bf4[1]);
                    mma16816(acc[nb * 2 + 1], af[0], af[1], af[2], af[3], bf4[2], bf4[3]);
                }
            }
        }
        #pragma unroll
        for (int nf = 0; nf < 4; nf++) {
            int col = k0 + wn * 32 + nf * 8 + lr * 2;
            *(float2*)(sS + (wm * 16 + lq) * SST + col) = make_float2(acc[nf][0], acc[nf][1]);
            *(float2*)(sS + (wm * 16 + lq + 8) * SST + col) = make_float2(acc[nf][2], acc[nf][3]);
        }
        __syncthreads();
    }

    issue_kv(Vsp, plane, rowB, 0, col0, S, sKVB, tid);
    CP_COMMIT();

    const float L2E = 1.44269504f;
    const int CP = SP * 64;
    #pragma unroll
    for (int rr = 0; rr < 8; rr++) {
        int r = wid * 8 + rr;
        int qg = q0 + r;
        float* rowp = sS + r * SST;
        float m = -1e30f;
        for (int c = lane; c < S; c += 32) m = fmaxf(m, rowp[c]);
        #pragma unroll
        for (int o = 16; o; o >>= 1) m = fmaxf(m, __shfl_xor_sync(0xffffffffu, m, o));
        float mL = m * L2E;

        const bool isQ = (qg == NK);
        int qdv = qg / Kc;
        int lo = isQ ? -1 : qdv * Kc;
        int hi = isQ ? -1 : lo + Kc;
        float gOut  = isQ ? tw[4] : tw[2];
        float gIn   = isQ ? tw[4] : tw[1];
        float gDiag = isQ ? tw[5] : tw[0];
        float gLast = isQ ? tw[5] : tw[3];

        float sum = 0.f;
        for (int c2 = lane * 2; c2 < CP; c2 += 64) {
            float2 s2 = *(float2*)(rowp + c2);
            int c0 = c2, c1 = c2 + 1;
            float t0v = fmaf(s2.x, L2E, -mL);
            float t1v = fmaf(s2.y, L2E, -mL);
            if (c0 >= S) t0v = -100.f;
            if (c1 >= S) t1v = -100.f;
            __half2 e2 = h2exp2(__floats2half2_rn(t0v, t1v));
            float2 ef = __half22float2(e2);
            sum += ef.x + ef.y;
            float g0 = (c0 >= lo && c0 < hi) ? gIn : gOut;
            float g1 = (c1 >= lo && c1 < hi) ? gIn : gOut;
            if (c0 == qg) g0 = gDiag;
            if (c1 == qg) g1 = gDiag;
            if (c0 == NK) g0 = gLast;
            if (c1 == NK) g1 = gLast;
            __half2 p2 = __hmul2(e2, __floats2half2_rn(g0, g1));
            ((uint32_t*)rowp)[c2 >> 1] = *(uint32_t*)&p2;
        }
        #pragma unroll
        for (int o = 16; o; o >>= 1) sum += __shfl_xor_sync(0xffffffffu, sum, o);
        if (lane == 0) s_inv[r] = 1.f / sum;
    }
    __syncthreads();

    float oacc[4][4] = {};
    for (int t = 0; t < SP; t++) {
        int k0 = t * 64;
        if (t + 1 < SP) {
            issue_kv(Vsp, plane, rowB, (t + 1) * 64, col0, S,
                     sKVB + ((t + 1) & 1) * KVSTG, tid);
            CP_COMMIT();
        }
        if (t + 1 < SP) CP_WAIT1(); else CP_WAIT0();
        __syncthreads();

        const uint32_t kvSt = sKVB + (t & 1) * KVSTG;
        const uint32_t aBase = sSB + (wm * 16) * SST4 + k0 * 2 + pLM;
        #pragma unroll
        for (int pass = 0; pass < 2; pass++) {
            const uint32_t bB = kvSt + (pass ? KVPL : 0) + vLM;
            #pragma unroll
            for (int ks = 0; ks < 4; ks++) {
                uint32_t af[4];
                ldsm4(af, aBase + ks * 32);
                #pragma unroll
                for (int nb = 0; nb < 2; nb++) {
                    uint32_t bf4[4];
                    ldsm4t(bf4, bB + (wn * 32 + nb * 16) * 2 + ks * 16 * (APAD * 2));
                    mma16816h(oacc[nb * 2], af[0], af[1], af[2], af[3], bf4[0], bf4[1]);
                    mma16816h(oacc[nb * 2 + 1], af[0], af[1], af[2], af[3], bf4[2], bf4[3]);
                }
            }
        }
        __syncthreads();
    }

    const float inv0 = s_inv[wm * 16 + lq];
    const float inv1 = s_inv[wm * 16 + lq + 8];
    #pragma unroll
    for (int nf = 0; nf < 4; nf++) {
        int col = col0 + wn * 32 + nf * 8 + lr * 2;
        int r0a = q0 + wm * 16 + lq;
        if (r0a < S)
            split_store(Osp + (rowB + r0a) * 256, plane, col,
                        oacc[nf][0] * inv0, oacc[nf][1] * inv0);
        if (r0a + 8 < S)
            split_store(Osp + (rowB + r0a + 8) * 256, plane, col,
                        oacc[nf][2] * inv1, oacc[nf][3] * inv1);
    }
}

// ---------------------------------------------------------------------------
extern "C" void kernel_launch(void* const* d_in, const int* in_sizes, int n_in,
                              void* d_out, int out_size) {
    const float* samples  = (const float*)d_in[0];
    const float* Wq       = (const float*)d_in[1];
    const float* Wk       = (const float*)d_in[2];
    const float* Wv       = (const float*)d_in[3];
    const float* attn_w   = (const float*)d_in[4];
    const float* mha_fc_w = (const float*)d_in[5];
    const float* mha_fc_b = (const float*)d_in[6];
    const float* mha_ln_g = (const float*)d_in[7];
    const float* mha_ln_b = (const float*)d_in[8];
    const float* d_fc1_w  = (const float*)d_in[9];
    const float* d_fc1_b  = (const float*)d_in[10];
    const float* d_fc2_w  = (const float*)d_in[11];
    const float* d_fc2_b  = (const float*)d_in[12];
    const float* d_ln_g   = (const float*)d_in[13];
    const float* d_ln_b   = (const float*)d_in[14];
    const float* out_fc_w = (const float*)d_in[15];
    const float* out_fc_b = (const float*)d_in[16];
    const float* out_ln_g = (const float*)d_in[17];
    const float* out_ln_b = (const float*)d_in[18];
    const int*   Kptr     = (const int*)d_in[20];

    const int S = in_sizes[0] / (BATCH * DMODEL);
    const int M = BATCH * S;
    const size_t plane = (size_t)M * 256;

    float* base = nullptr;
    cudaGetSymbolAddress((void**)&base, g_scratch);
    __nv_bfloat16* xsp = (__nv_bfloat16*)(base + 0 * CHUNK);
    __nv_bfloat16* qsp = (__nv_bfloat16*)(base + 1 * CHUNK);   // also FFN hidden
    __nv_bfloat16* ksp = (__nv_bfloat16*)(base + 2 * CHUNK);
    __half*        vsp = (__half*)(base + 3 * CHUNK);
    __nv_bfloat16* aosp = (__nv_bfloat16*)(base + 4 * CHUNK);

    __nv_bfloat16* wsp = nullptr;
    cudaGetSymbolAddress((void**)&wsp, g_wsplit);

    cudaFuncSetAttribute(attn_tc, cudaFuncAttributeMaxDynamicSharedMemorySize, ATTN_DYN);
    cudaFuncSetAttribute(gemm_tc, cudaFuncAttributeMaxDynamicSharedMemorySize, GEMM_DYN);
    cudaFuncSetAttribute(qkv_tc, cudaFuncAttributeMaxDynamicSharedMemorySize, GEMM_DYN);

    WP wp;
    wp.p[0] = Wq;        wp.p[1] = Wq + 65536;
    wp.p[2] = Wk;        wp.p[3] = Wk + 65536;
    wp.p[4] = Wv;        wp.p[5] = Wv + 65536;
    wp.p[6] = mha_fc_w;  wp.p[7] = mha_fc_w + 65536;
    wp.p[8] = d_fc1_w;   wp.p[9] = d_fc1_w + 65536;
    wp.p[10] = d_fc2_w;  wp.p[11] = d_fc2_w + 65536;
    wp.p[12] = out_fc_w;
    prep_w<<<dim3(64, 13), 256>>>(wp, wsp);
    conv_split<<<M / 4, 256>>>(samples, xsp, plane);

    dim3 ga((S + 63) / 64, NHEAD, BATCH);
    const int GR = (M + 63) / 64;

    for (int l = 0; l < 2; l++) {
        qkv_tc<<<GR, 256, GEMM_DYN>>>(xsp,
                                      wsp + (size_t)(0 + l) * 131072,
                                      wsp + (size_t)(2 + l) * 131072,
                                      wsp + (size_t)(4 + l) * 131072,
                                      qsp, ksp, vsp, plane);
        attn_tc<<<ga, 256, ATTN_DYN>>>(qsp, ksp, vsp, plane,
                                       attn_w + l * 24, Kptr, aosp, S);
        // mha_fc + LN (resid = xsp), out -> xsp (in-place rows)
        gemm_tc<<<GR, 256, GEMM_DYN>>>(aosp, wsp + (size_t)(6 + l) * 131072,
                                       mha_fc_b + l * 256, xsp, nullptr,
                                       mha_ln_g + l * 256, mha_ln_b + l * 256,
                                       xsp, nullptr, plane, 0);
        // fc1 + relu -> qsp
        gemm_tc<<<GR, 256, GEMM_DYN>>>(xsp, wsp + (size_t)(8 + l) * 131072,
                                       d_fc1_b + l * 256, nullptr, nullptr,
                                       nullptr, nullptr, qsp, nullptr, plane, 1);
        // fc2 + LN (resid = xsp) -> xsp
        gemm_tc<<<GR, 256, GEMM_DYN>>>(qsp, wsp + (size_t)(10 + l) * 131072,
                                       d_fc2_b + l * 256, xsp, nullptr,
                                       d_ln_g + l * 256, d_ln_b + l * 256,
                                       xsp, nullptr, plane, 0);
    }
    // final: out_fc + LN (resid = samples fp32) -> d_out fp32
    gemm_tc<<<GR, 256, GEMM_DYN>>>(xsp, wsp + (size_t)12 * 131072,
                                   out_fc_b, nullptr, samples,
                                   out_ln_g, out_ln_b,
                                   nullptr, (float*)d_out, plane, 0);
}

// round 13
// speedup vs baseline: 3.2234x; 1.2667x over previous
#include <cuda_runtime.h>
#include <cuda_bf16.h>
#include <cuda_fp16.h>
#include <math.h>
#include <stdint.h>

#define DMODEL 256
#define BATCH  128
#define NHEAD  4
#define DK     64

#define CHUNK (128ull * 512ull * 256ull)
__device__ float g_scratch[5ull * CHUNK];
__device__ __nv_bfloat16 g_wsplit[13ull * 131072ull];

// ---------------------------------------------------------------------------
__device__ __forceinline__ uint32_t smem_u32(const void* p) {
    uint32_t a;
    asm("{ .reg .u64 t; cvta.to.shared.u64 t, %1; cvt.u32.u64 %0, t; }" : "=r"(a) : "l"(p));
    return a;
}
__device__ __forceinline__ void mma16816(float* c,
                                         uint32_t a0, uint32_t a1, uint32_t a2, uint32_t a3,
                                         uint32_t b0, uint32_t b1) {
    asm volatile(
        "mma.sync.aligned.m16n8k16.row.col.f32.bf16.bf16.f32 "
        "{%0,%1,%2,%3},{%4,%5,%6,%7},{%8,%9},{%0,%1,%2,%3};"
        : "+f"(c[0]), "+f"(c[1]), "+f"(c[2]), "+f"(c[3])
        : "r"(a0), "r"(a1), "r"(a2), "r"(a3), "r"(b0), "r"(b1));
}
__device__ __forceinline__ void mma16816h(float* c,
                                          uint32_t a0, uint32_t a1, uint32_t a2, uint32_t a3,
                                          uint32_t b0, uint32_t b1) {
    asm volatile(
        "mma.sync.aligned.m16n8k16.row.col.f32.f16.f16.f32 "
        "{%0,%1,%2,%3},{%4,%5,%6,%7},{%8,%9},{%0,%1,%2,%3};"
        : "+f"(c[0]), "+f"(c[1]), "+f"(c[2]), "+f"(c[3])
        : "r"(a0), "r"(a1), "r"(a2), "r"(a3), "r"(b0), "r"(b1));
}
__device__ __forceinline__ void ldsm4(uint32_t* r, uint32_t a) {
    asm volatile("ldmatrix.sync.aligned.m8n8.x4.shared.b16 {%0,%1,%2,%3}, [%4];"
        : "=r"(r[0]), "=r"(r[1]), "=r"(r[2]), "=r"(r[3]) : "r"(a));
}
__device__ __forceinline__ void ldsm4t(uint32_t* r, uint32_t a) {
    asm volatile("ldmatrix.sync.aligned.m8n8.x4.trans.shared.b16 {%0,%1,%2,%3}, [%4];"
        : "=r"(r[0]), "=r"(r[1]), "=r"(r[2]), "=r"(r[3]) : "r"(a));
}
__device__ __forceinline__ void cp16(uint32_t saddr, const void* g) {
    asm volatile("cp.async.cg.shared.global [%0], [%1], 16;" :: "r"(saddr), "l"(g));
}
__device__ __forceinline__ void sts16z(uint32_t a) {
    asm volatile("st.shared.v4.u32 [%0], {%1,%1,%1,%1};" :: "r"(a), "r"(0u));
}
#define CP_COMMIT() asm volatile("cp.async.commit_group;" ::: "memory")
#define CP_WAIT1()  asm volatile("cp.async.wait_group 1;" ::: "memory")
#define CP_WAIT0()  asm volatile("cp.async.wait_group 0;" ::: "memory")

// ---------------------------------------------------------------------------
struct WP { const float* p[13]; };

__global__ void prep_w(WP wp, __nv_bfloat16* dst) {
    const int mid = blockIdx.y;
    const float* W = wp.p[mid];
    __nv_bfloat16* hi = dst + (size_t)mid * 131072;
    __nv_bfloat16* lo = hi + 65536;
    int idx0 = blockIdx.x * 1024 + threadIdx.x;
    #pragma unroll
    for (int i = 0; i < 4; i++) {
        int idx = idx0 + i * 256;
        int k = idx >> 8, n = idx & 255;
        float x = W[idx];
        __nv_bfloat16 h = __float2bfloat16(x);
        hi[n * 256 + k] = h;
        lo[n * 256 + k] = __float2bfloat16(x - __bfloat162float(h));
    }
}

__global__ void conv_split(const float* __restrict__ X, __nv_bfloat16* __restrict__ Osp,
                           size_t planeEl) {
    int i = (blockIdx.x * 256 + threadIdx.x) * 4;
    float4 a = *(const float4*)(X + i);
    __nv_bfloat162 h0 = __floats2bfloat162_rn(a.x, a.y);
    __nv_bfloat162 h1 = __floats2bfloat162_rn(a.z, a.w);
    float r0 = a.x - __bfloat162float(__low2bfloat16(h0));
    float r1 = a.y - __bfloat162float(__high2bfloat16(h0));
    float r2 = a.z - __bfloat162float(__low2bfloat16(h1));
    float r3 = a.w - __bfloat162float(__high2bfloat16(h1));
    __nv_bfloat162 l0 = __floats2bfloat162_rn(r0, r1);
    __nv_bfloat162 l1 = __floats2bfloat162_rn(r2, r3);
    *(__nv_bfloat162*)(Osp + i) = h0;
    *(__nv_bfloat162*)(Osp + i + 2) = h1;
    *(__nv_bfloat162*)(Osp + planeEl + i) = l0;
    *(__nv_bfloat162*)(Osp + planeEl + i + 2) = l1;
}

// ---------------------------------------------------------------------------
// GEMM (unchanged from R12)
// ---------------------------------------------------------------------------
#define KC   32
#define ST2  40
#define APL2 (64 * ST2 * 2)
#define BPL2 (256 * ST2 * 2)
#define STG2 (2 * APL2 + 2 * BPL2)
#define GEMM_DYN (2 * STG2)

__device__ __forceinline__ void issue_chunkA(const __nv_bfloat16* __restrict__ Asp,
                                             size_t planeEl, int bm, int kc,
                                             uint32_t aSt, int tid) {
    #pragma unroll
    for (int i = 0; i < 2; i++) {
        int it = tid + i * 256;
        int p = it >> 8, rem = it & 255, r = rem >> 2, k8 = (rem & 3) << 3;
        uint32_t d = aSt + p * APL2 + (uint32_t)(r * ST2 + k8) * 2;
        cp16(d, Asp + p * planeEl + (size_t)(bm + r) * 256 + kc * KC + k8);
    }
}
__device__ __forceinline__ void issue_chunkB(const __nv_bfloat16* __restrict__ Whi,
                                             int kc, uint32_t bSt, int tid) {
    const __nv_bfloat16* Wlo = Whi + 65536;
    #pragma unroll
    for (int i = 0; i < 8; i++) {
        int it = tid + i * 256;
        int p = it >> 10, rem = it & 1023, n = rem >> 2, k8 = (rem & 3) << 3;
        uint32_t d = bSt + p * BPL2 + (uint32_t)(n * ST2 + k8) * 2;
        cp16(d, (p ? Wlo : Whi) + n * 256 + kc * KC + k8);
    }
}

__device__ __forceinline__ void mma_chunk32(
    uint32_t aSt, uint32_t bSt, uint32_t aLM, uint32_t bLM, int wid, float acc[4][4][4])
{
    #pragma unroll
    for (int ks = 0; ks < 2; ks++) {
        #pragma unroll
        for (int pass = 0; pass < 3; pass++) {
            const uint32_t aB = aSt + ((pass == 2) ? APL2 : 0) + ks * 32 + aLM;
            const uint32_t bB = bSt + ((pass == 1) ? BPL2 : 0) + ks * 32 + bLM;
            uint32_t af[4][4];
            #pragma unroll
            for (int mf = 0; mf < 4; mf++)
                ldsm4(af[mf], aB + (mf * 16) * (ST2 * 2));
            uint32_t bfr[4][2];
            #pragma unroll
            for (int nb = 0; nb < 2; nb++) {
                uint32_t t[4];
                ldsm4(t, bB + (wid * 32 + nb * 16) * (ST2 * 2));
                bfr[2 * nb][0] = t[0]; bfr[2 * nb][1] = t[1];
                bfr[2 * nb + 1][0] = t[2]; bfr[2 * nb + 1][1] = t[3];
            }
            #pragma unroll
            for (int mf = 0; mf < 4; mf++)
                #pragma unroll
                for (int nf = 0; nf < 4; nf++)
                    mma16816(acc[mf][nf], af[mf][0], af[mf][1], af[mf][2], af[mf][3],
                             bfr[nf][0], bfr[nf][1]);
        }
    }
}

__device__ __forceinline__ void split_store(__nv_bfloat16* Cr, size_t planeEl,
                                            int c, float v0, float v1) {
    __nv_bfloat162 hp = __floats2bfloat162_rn(v0, v1);
    float r0 = v0 - __bfloat162float(__low2bfloat16(hp));
    float r1 = v1 - __bfloat162float(__high2bfloat16(hp));
    __nv_bfloat162 lp = __floats2bfloat162_rn(r0, r1);
    *(__nv_bfloat162*)(Cr + c) = hp;
    *(__nv_bfloat162*)(Cr + planeEl + c) = lp;
}

__global__ __launch_bounds__(256, 2) void gemm_tc(
    const __nv_bfloat16* __restrict__ Asp, const __nv_bfloat16* __restrict__ Wsp,
    const float* __restrict__ bias,
    const __nv_bfloat16* __restrict__ residSp, const float* __restrict__ residF,
    const float* __restrict__ lng, const float* __restrict__ lnb,
    __nv_bfloat16* __restrict__ OutSp, float* __restrict__ OutF,
    size_t planeEl, int relu)
{
    extern __shared__ char dsm[];
    __shared__ float s_bias[256], s_g[256], s_b[256];
    __shared__ float s_sum[64], s_ssq[64];

    const int tid = threadIdx.x;
    const int wid = tid >> 5, lane = tid & 31;
    const int lq = lane >> 2, lr = lane & 3;
    const int bm = blockIdx.x * 64;

    const uint32_t base = smem_u32(dsm);
    const uint32_t aLM = ((uint32_t)((lane & 15) * ST2) + ((lane >> 4) << 3)) * 2;
    const uint32_t bLM = ((uint32_t)((((lane >> 4) << 3) + (lane & 7)) * ST2) + (((lane >> 3) & 1) << 3)) * 2;

    issue_chunkA(Asp, planeEl, bm, 0, base, tid);
    issue_chunkB(Wsp, 0, base + 2 * APL2, tid);
    CP_COMMIT();

    s_bias[tid] = bias ? bias[tid] : 0.f;
    if (lng) { s_g[tid] = lng[tid]; s_b[tid] = lnb[tid]; }
    if (tid < 64) { s_sum[tid] = 0.f; s_ssq[tid] = 0.f; }

    float acc[4][4][4];
    #pragma unroll
    for (int mf = 0; mf < 4; mf++)
        #pragma unroll
        for (int nf = 0; nf < 4; nf++)
            #pragma unroll
            for (int j = 0; j < 4; j++) acc[mf][nf][j] = 0.f;

    for (int c = 0; c < 8; c++) {
        if (c < 7) {
            uint32_t st = base + ((c + 1) & 1) * STG2;
            issue_chunkA(Asp, planeEl, bm, c + 1, st, tid);
            issue_chunkB(Wsp, c + 1, st + 2 * APL2, tid);
            CP_COMMIT();
        }
        if (c < 7) CP_WAIT1(); else CP_WAIT0();
        __syncthreads();
        uint32_t st = base + (c & 1) * STG2;
        mma_chunk32(st, st + 2 * APL2, aLM, bLM, wid, acc);
        __syncthreads();
    }

    if (lng) {
        #pragma unroll
        for (int mf = 0; mf < 4; mf++) {
            #pragma unroll
            for (int h = 0; h < 2; h++) {
                int r = mf * 16 + lq + h * 8;
                float ps = 0.f, pq = 0.f;
                #pragma unroll
                for (int nf = 0; nf < 4; nf++) {
                    int c = wid * 32 + nf * 8 + lr * 2;
                    float rv0, rv1;
                    if (residF) {
                        float2 t = *(const float2*)(residF + (size_t)(bm + r) * 256 + c);
                        rv0 = t.x; rv1 = t.y;
                    } else {
                        __nv_bfloat162 h2 = *(const __nv_bfloat162*)(residSp + (size_t)(bm + r) * 256 + c);
                        __nv_bfloat162 l2 = *(const __nv_bfloat162*)(residSp + planeEl + (size_t)(bm + r) * 256 + c);
                        rv0 = __bfloat162float(__low2bfloat16(h2)) + __bfloat162float(__low2bfloat16(l2));
                        rv1 = __bfloat162float(__high2bfloat16(h2)) + __bfloat162float(__high2bfloat16(l2));
                    }
                    float v0 = acc[mf][nf][h * 2 + 0] + s_bias[c] + rv0;
                    float v1 = acc[mf][nf][h * 2 + 1] + s_bias[c + 1] + rv1;
                    acc[mf][nf][h * 2 + 0] = v0;
                    acc[mf][nf][h * 2 + 1] = v1;
                    ps += v0 + v1;
                    pq += v0 * v0 + v1 * v1;
                }
                ps += __shfl_xor_sync(0xffffffffu, ps, 1);
                ps += __shfl_xor_sync(0xffffffffu, ps, 2);
                pq += __shfl_xor_sync(0xffffffffu, pq, 1);
                pq += __shfl_xor_sync(0xffffffffu, pq, 2);
                if (lr == 0) {
                    atomicAdd(&s_sum[r], ps);
                    atomicAdd(&s_ssq[r], pq);
                }
            }
        }
        __syncthreads();
        if (tid < 64) {
            float mu = s_sum[tid] * (1.f / 256.f);
            float var = s_ssq[tid] * (1.f / 256.f) - mu * mu;
            s_sum[tid] = mu;
            s_ssq[tid] = rsqrtf(var + 1e-5f);
        }
        __syncthreads();
        #pragma unroll
        for (int mf = 0; mf < 4; mf++) {
            #pragma unroll
            for (int h = 0; h < 2; h++) {
                int r = mf * 16 + lq + h * 8;
                float mu = s_sum[r], rs = s_ssq[r];
                #pragma unroll
                for (int nf = 0; nf < 4; nf++) {
                    int c = wid * 32 + nf * 8 + lr * 2;
                    float v0 = (acc[mf][nf][h * 2 + 0] - mu) * rs * s_g[c] + s_b[c];
                    float v1 = (acc[mf][nf][h * 2 + 1] - mu) * rs * s_g[c + 1] + s_b[c + 1];
                    if (OutF)
                        *(float2*)(OutF + (size_t)(bm + r) * 256 + c) = make_float2(v0, v1);
                    else
                        split_store(OutSp + (size_t)(bm + r) * 256, planeEl, c, v0, v1);
                }
            }
        }
    } else {
        #pragma unroll
        for (int mf = 0; mf < 4; mf++) {
            #pragma unroll
            for (int h = 0; h < 2; h++) {
                int r = mf * 16 + lq + h * 8;
                #pragma unroll
                for (int nf = 0; nf < 4; nf++) {
                    int c = wid * 32 + nf * 8 + lr * 2;
                    float v0 = acc[mf][nf][h * 2 + 0] + s_bias[c];
                    float v1 = acc[mf][nf][h * 2 + 1] + s_bias[c + 1];
                    if (relu) { v0 = fmaxf(v0, 0.f); v1 = fmaxf(v1, 0.f); }
                    split_store(OutSp + (size_t)(bm + r) * 256, planeEl, c, v0, v1);
                }
            }
        }
    }
}

// ---------------------------------------------------------------------------
// Fused QKV (unchanged except Q scale includes log2(e))
// ---------------------------------------------------------------------------
__global__ __launch_bounds__(256, 2) void qkv_tc(
    const __nv_bfloat16* __restrict__ Asp,
    const __nv_bfloat16* __restrict__ Wq_, const __nv_bfloat16* __restrict__ Wk_,
    const __nv_bfloat16* __restrict__ Wv_,
    __nv_bfloat16* __restrict__ Qs, __nv_bfloat16* __restrict__ Ks,
    __half* __restrict__ Vs, size_t planeEl)
{
    extern __shared__ char dsm[];
    const int tid = threadIdx.x;
    const int wid = tid >> 5, lane = tid & 31;
    const int lq = lane >> 2, lr = lane & 3;
    const int bm = blockIdx.x * 64;

    const uint32_t base = smem_u32(dsm);
    const uint32_t aLM = ((uint32_t)((lane & 15) * ST2) + ((lane >> 4) << 3)) * 2;
    const uint32_t bLM = ((uint32_t)((((lane >> 4) << 3) + (lane & 7)) * ST2) + (((lane >> 3) & 1) << 3)) * 2;

    const __nv_bfloat16* Ws[3] = {Wq_, Wk_, Wv_};

    issue_chunkA(Asp, planeEl, bm, 0, base, tid);
    issue_chunkB(Ws[0], 0, base + 2 * APL2, tid);
    CP_COMMIT();

    float acc[4][4][4];

    for (int c = 0; c < 24; c++) {
        if (c + 1 < 24) {
            uint32_t st = base + ((c + 1) & 1) * STG2;
            issue_chunkA(Asp, planeEl, bm, (c + 1) & 7, st, tid);
            issue_chunkB(Ws[(c + 1) >> 3], (c + 1) & 7, st + 2 * APL2, tid);
            CP_COMMIT();
        }
        if (c + 1 < 24) CP_WAIT1(); else CP_WAIT0();
        __syncthreads();
        if ((c & 7) == 0) {
            #pragma unroll
            for (int mf = 0; mf < 4; mf++)
                #pragma unroll
                for (int nf = 0; nf < 4; nf++)
                    #pragma unroll
                    for (int j = 0; j < 4; j++) acc[mf][nf][j] = 0.f;
        }
        uint32_t st = base + (c & 1) * STG2;
        mma_chunk32(st, st + 2 * APL2, aLM, bLM, wid, acc);
        __syncthreads();

        if ((c & 7) == 7) {
            int m = c >> 3;
            if (m < 2) {
                float scale = (m == 0) ? 0.125f * 1.44269504f : 1.0f;
                __nv_bfloat16* Out = (m == 0) ? Qs : Ks;
                #pragma unroll
                for (int mf = 0; mf < 4; mf++)
                    #pragma unroll
                    for (int h = 0; h < 2; h++) {
                        int r = mf * 16 + lq + h * 8;
                        #pragma unroll
                        for (int nf = 0; nf < 4; nf++) {
                            int cc = wid * 32 + nf * 8 + lr * 2;
                            split_store(Out + (size_t)(bm + r) * 256, planeEl, cc,
                                        acc[mf][nf][h * 2 + 0] * scale,
                                        acc[mf][nf][h * 2 + 1] * scale);
                        }
                    }
            } else {
                #pragma unroll
                for (int mf = 0; mf < 4; mf++)
                    #pragma unroll
                    for (int h = 0; h < 2; h++) {
                        int r = mf * 16 + lq + h * 8;
                        __half* Cr = Vs + (size_t)(bm + r) * 256;
                        #pragma unroll
                        for (int nf = 0; nf < 4; nf++) {
                            int cc = wid * 32 + nf * 8 + lr * 2;
                            float v0 = acc[mf][nf][h * 2 + 0];
                            float v1 = acc[mf][nf][h * 2 + 1];
                            __half2 hp = __floats2half2_rn(v0, v1);
                            float r0 = v0 - __half2float(__low2half(hp));
                            float r1 = v1 - __half2float(__high2half(hp));
                            __half2 lp = __floats2half2_rn(r0, r1);
                            *(__half2*)(Cr + cc) = hp;
                            *(__half2*)(Cr + planeEl + cc) = lp;
                        }
                    }
            }
        }
    }
}

// ---------------------------------------------------------------------------
// Flash-style attention: online softmax, no score buffer, 2 CTAs/SM.
// smem: Q[2 planes] + KV stages[2][4 planes] + P[1] = 101376 B.
// ---------------------------------------------------------------------------
#define APAD 72
#define PL1  (64 * APAD * 2)        // 9216 B per plane
#define KVST4 (4 * PL1)             // 36864 per stage (Khi,Klo,Vhi,Vlo)
#define ATTN_DYN (2 * PL1 + 2 * KVST4 + PL1)   // 101376

__device__ __forceinline__ void issue_q(const __nv_bfloat16* Qsp, size_t planeEl,
                                        size_t rowB, int q0, int col0, int S,
                                        uint32_t dst, int tid) {
    #pragma unroll
    for (int i = 0; i < 4; i++) {
        int it = tid + i * 256;
        int p = it >> 9, r = (it >> 3) & 63, c8 = (it & 7) << 3;
        uint32_t d = dst + p * PL1 + (uint32_t)(r * APAD + c8) * 2;
        if (q0 + r < S)
            cp16(d, Qsp + p * planeEl + (rowB + q0 + r) * 256 + col0 + c8);
        else
            sts16z(d);
    }
}
__device__ __forceinline__ void issue_kv4(const __nv_bfloat16* Ksp, const __half* Vsp,
                                          size_t planeEl, size_t rowB, int k0, int col0,
                                          int S, uint32_t stage, int tid) {
    #pragma unroll
    for (int i = 0; i < 8; i++) {
        int it = tid + i * 256;
        int p = it >> 9, r = (it >> 3) & 63, c8 = (it & 7) << 3;
        uint32_t d = stage + p * PL1 + (uint32_t)(r * APAD + c8) * 2;
        if (k0 + r < S) {
            const void* g;
            if (p < 2) g = Ksp + p * planeEl + (rowB + k0 + r) * 256 + col0 + c8;
            else       g = Vsp + (p - 2) * planeEl + (rowB + k0 + r) * 256 + col0 + c8;
            cp16(d, g);
        } else sts16z(d);
    }
}

__global__ __launch_bounds__(256, 2) void attn_tc(
    const __nv_bfloat16* __restrict__ Qsp, const __nv_bfloat16* __restrict__ Ksp,
    const __half* __restrict__ Vsp, size_t plane,
    const float* __restrict__ AW, const int* __restrict__ Kcls,
    __nv_bfloat16* __restrict__ Osp, int S)
{
    extern __shared__ char smraw[];
    __shared__ float tw[6];
    __shared__ float redbuf[2][64];
    __shared__ int   cdiv[512];

    const int b = blockIdx.z, h = blockIdx.y, q0 = blockIdx.x * 64;
    const int tid = threadIdx.x, wid = tid >> 5, lane = tid & 31;
    const int lq = lane >> 2, lr = lane & 3;
    const int wm = wid >> 1, wn = wid & 1;
    const int Kc = *Kcls;
    const int NK = S - 1;
    const size_t rowB = (size_t)b * S;
    const int col0 = h * 64;

    const uint32_t sQB  = smem_u32(smraw);
    const uint32_t sKVB = sQB + 2 * PL1;
    const uint32_t sPB  = sKVB + 2 * KVST4;
    const uint32_t aLM = ((uint32_t)((lane & 15) * APAD) + ((lane >> 4) << 3)) * 2;
    const uint32_t bLM = ((uint32_t)((((lane >> 4) << 3) + (lane & 7)) * APAD) + (((lane >> 3) & 1) << 3)) * 2;
    const uint32_t vLM = ((uint32_t)(((((lane >> 3) & 1) << 3) + (lane & 7)) * APAD) + (((lane >> 4) & 1) << 3)) * 2;

    const int SP = (S + 63) >> 6;

    issue_q(Qsp, plane, rowB, q0, col0, S, sQB, tid);
    issue_kv4(Ksp, Vsp, plane, rowB, 0, col0, S, sKVB, tid);
    CP_COMMIT();

    if (tid < 6) tw[tid] = tanhf(AW[h * 6 + tid]);
    cdiv[tid] = tid / Kc;
    cdiv[tid + 256] = (tid + 256) / Kc;

    // per-thread rows
    const int r0 = wm * 16 + lq, r1 = r0 + 8;
    const int qg0 = q0 + r0, qg1 = q0 + r1;

    float m0 = -1e30f, m1 = -1e30f, sum0 = 0.f, sum1 = 0.f;
    float oacc[4][4];
    #pragma unroll
    for (int j = 0; j < 4; j++)
        #pragma unroll
        for (int e = 0; e < 4; e++) oacc[j][e] = 0.f;

    // row gate params (precomputed after tw is written — need a sync first;
    // fold into first loop iteration via lazy init)
    float gOut0, gIn0, gDiag0, gLast0, gOut1, gIn1, gDiag1, gLast1;
    int lo0, hi0, lo1, hi1, qdv0, qdv1;
    qdv0 = qg0 / Kc; qdv1 = qg1 / Kc;

    for (int t = 0; t < SP; t++) {
        int k0 = t * 64;
        if (t + 1 < SP) {
            issue_kv4(Ksp, Vsp, plane, rowB, (t + 1) * 64, col0, S,
                      sKVB + ((t + 1) & 1) * KVST4, tid);
            CP_COMMIT();
        }
        if (t + 1 < SP) CP_WAIT1(); else CP_WAIT0();
        __syncthreads();

        if (t == 0) {
            bool isQ0 = (qg0 == NK), isQ1 = (qg1 == NK);
            lo0 = isQ0 ? -1 : qdv0 * Kc; hi0 = isQ0 ? -1 : lo0 + Kc;
            lo1 = isQ1 ? -1 : qdv1 * Kc; hi1 = isQ1 ? -1 : lo1 + Kc;
            gOut0 = isQ0 ? tw[4] : tw[2]; gIn0 = isQ0 ? tw[4] : tw[1];
            gDiag0 = isQ0 ? tw[5] : tw[0]; gLast0 = isQ0 ? tw[5] : tw[3];
            gOut1 = isQ1 ? tw[4] : tw[2]; gIn1 = isQ1 ? tw[4] : tw[1];
            gDiag1 = isQ1 ? tw[5] : tw[0]; gLast1 = isQ1 ? tw[5] : tw[3];
        }

        const uint32_t kvSt = sKVB + (t & 1) * KVST4;

        // ---- scores (base-2 domain; L2E folded into Q) ----
        float acc[4][4] = {};
        #pragma unroll
        for (int pass = 0; pass < 3; pass++) {
            const uint32_t aB = sQB + (pass == 2 ? PL1 : 0) + (wm * 16) * (APAD * 2) + aLM;
            const uint32_t bB = kvSt + (pass == 1 ? PL1 : 0) + bLM;
            #pragma unroll
            for (int ks = 0; ks < 4; ks++) {
                uint32_t af[4];
                ldsm4(af, aB + ks * 32);
                #pragma unroll
                for (int nb = 0; nb < 2; nb++) {
                    uint32_t bf4[4];
                    ldsm4(bf4, bB + (wn * 32 + nb * 16) * (APAD * 2) + ks * 32);
                    mma16816(acc[nb * 2], af[0], af[1], af[2], af[3], bf4[0], bf4[1]);
                    mma16816(acc[nb * 2 + 1], af[0], af[1], af[2], af[3], bf4[2], bf4[3]);
                }
            }
        }

        // mask out-of-range columns
        #pragma unroll
        for (int j = 0; j < 4; j++) {
            int c = k0 + wn * 32 + j * 8 + lr * 2;
            if (c >= S)     { acc[j][0] = -1e30f; acc[j][2] = -1e30f; }
            if (c + 1 >= S) { acc[j][1] = -1e30f; acc[j][3] = -1e30f; }
        }

        // chunk max per row
        float mx0 = -1e30f, mx1 = -1e30f;
        #pragma unroll
        for (int j = 0; j < 4; j++) {
            mx0 = fmaxf(mx0, fmaxf(acc[j][0], acc[j][1]));
            mx1 = fmaxf(mx1, fmaxf(acc[j][2], acc[j][3]));
        }
        mx0 = fmaxf(mx0, __shfl_xor_sync(0xffffffffu, mx0, 1));
        mx0 = fmaxf(mx0, __shfl_xor_sync(0xffffffffu, mx0, 2));
        mx1 = fmaxf(mx1, __shfl_xor_sync(0xffffffffu, mx1, 1));
        mx1 = fmaxf(mx1, __shfl_xor_sync(0xffffffffu, mx1, 2));
        if (lr == 0) { redbuf[wn][r0] = mx0; redbuf[wn][r1] = mx1; }
        __syncthreads();
        float mn0 = fmaxf(m0, fmaxf(redbuf[0][r0], redbuf[1][r0]));
        float mn1 = fmaxf(m1, fmaxf(redbuf[0][r1], redbuf[1][r1]));
        float sc0 = exp2f(m0 - mn0), sc1 = exp2f(m1 - mn1);
        m0 = mn0; m1 = mn1;
        sum0 *= sc0; sum1 *= sc1;
        #pragma unroll
        for (int j = 0; j < 4; j++) {
            oacc[j][0] *= sc0; oacc[j][1] *= sc0;
            oacc[j][2] *= sc1; oacc[j][3] *= sc1;
        }

        // exp + gate -> P (f16) to smem
        __half* sP = (__half*)(smraw + (sPB - sQB));
        #pragma unroll
        for (int j = 0; j < 4; j++) {
            int lc = wn * 32 + j * 8 + lr * 2;
            int c = k0 + lc;
            __half2 e0 = h2exp2(__floats2half2_rn(acc[j][0] - mn0, acc[j][1] - mn0));
            __half2 e1 = h2exp2(__floats2half2_rn(acc[j][2] - mn1, acc[j][3] - mn1));
            float2 f0 = __half22float2(e0), f1 = __half22float2(e1);
            sum0 += f0.x + f0.y;
            sum1 += f1.x + f1.y;
            int cd0 = cdiv[c & 511], cd1 = cdiv[(c + 1) & 511];
            float ga = (c >= lo0 && c < hi0) ? gIn0 : gOut0;
            float gb = (c + 1 >= lo0 && c + 1 < hi0) ? gIn0 : gOut0;
            if (cd0 == qdv0 && lo0 >= 0) ga = (c >= lo0 && c < hi0) ? gIn0 : ga;
            if (c == qg0) ga = gDiag0;
            if (c + 1 == qg0) gb = gDiag0;
            if (c == NK) ga = gLast0;
            if (c + 1 == NK) gb = gLast0;
            float gc = (c >= lo1 && c < hi1) ? gIn1 : gOut1;
            float gd = (c + 1 >= lo1 && c + 1 < hi1) ? gIn1 : gOut1;
            if (c == qg1) gc = gDiag1;
            if (c + 1 == qg1) gd = gDiag1;
            if (c == NK) gc = gLast1;
            if (c + 1 == NK) gd = gLast1;
            __half2 p0 = __hmul2(e0, __floats2half2_rn(ga, gb));
            __half2 p1 = __hmul2(e1, __floats2half2_rn(gc, gd));
            *(__half2*)(sP + r0 * APAD + lc) = p0;
            *(__half2*)(sP + r1 * APAD + lc) = p1;
            (void)cd0; (void)cd1;
        }
        __syncthreads();

        // ---- P @ V (f16, 2 passes hi/lo) ----
        const uint32_t aB2 = sPB + (wm * 16) * (APAD * 2) + aLM;
        #pragma unroll
        for (int pass = 0; pass < 2; pass++) {
            const uint32_t bB = kvSt + (2 + pass) * PL1 + vLM;
            #pragma unroll
            for (int ks = 0; ks < 4; ks++) {
                uint32_t af[4];
                ldsm4(af, aB2 + ks * 32);
                #pragma unroll
                for (int nb = 0; nb < 2; nb++) {
                    uint32_t bf4[4];
                    ldsm4t(bf4, bB + (wn * 32 + nb * 16) * 2 + ks * 16 * (APAD * 2));
                    mma16816h(oacc[nb * 2], af[0], af[1], af[2], af[3], bf4[0], bf4[1]);
                    mma16816h(oacc[nb * 2 + 1], af[0], af[1], af[2], af[3], bf4[2], bf4[3]);
                }
            }
        }
    }

    // final sum across lr-quad and the two wn warps
    sum0 += __shfl_xor_sync(0xffffffffu, sum0, 1);
    sum0 += __shfl_xor_sync(0xffffffffu, sum0, 2);
    sum1 += __shfl_xor_sync(0xffffffffu, sum1, 1);
    sum1 += __shfl_xor_sync(0xffffffffu, sum1, 2);
    __syncthreads();
    if (lr == 0) { redbuf[wn][r0] = sum0; redbuf[wn][r1] = sum1; }
    __syncthreads();
    float inv0 = 1.f / (redbuf[0][r0] + redbuf[1][r0]);
    float inv1 = 1.f / (redbuf[0][r1] + redbuf[1][r1]);

    #pragma unroll
    for (int j = 0; j < 4; j++) {
        int col = col0 + wn * 32 + j * 8 + lr * 2;
        if (qg0 < S)
            split_store(Osp + (rowB + qg0) * 256, plane, col,
                        oacc[j][0] * inv0, oacc[j][1] * inv0);
        if (qg1 < S)
            split_store(Osp + (rowB + qg1) * 256, plane, col,
                        oacc[j][2] * inv1, oacc[j][3] * inv1);
    }
}

// ---------------------------------------------------------------------------
extern "C" void kernel_launch(void* const* d_in, const int* in_sizes, int n_in,
                              void* d_out, int out_size) {
    const float* samples  = (const float*)d_in[0];
    const float* Wq       = (const float*)d_in[1];
    const float* Wk       = (const float*)d_in[2];
    const float* Wv       = (const float*)d_in[3];
    const float* attn_w   = (const float*)d_in[4];
    const float* mha_fc_w = (const float*)d_in[5];
    const float* mha_fc_b = (const float*)d_in[6];
    const float* mha_ln_g = (const float*)d_in[7];
    const float* mha_ln_b = (const float*)d_in[8];
    const float* d_fc1_w  = (const float*)d_in[9];
    const float* d_fc1_b  = (const float*)d_in[10];
    const float* d_fc2_w  = (const float*)d_in[11];
    const float* d_fc2_b  = (const float*)d_in[12];
    const float* d_ln_g   = (const float*)d_in[13];
    const float* d_ln_b   = (const float*)d_in[14];
    const float* out_fc_w = (const float*)d_in[15];
    const float* out_fc_b = (const float*)d_in[16];
    const float* out_ln_g = (const float*)d_in[17];
    const float* out_ln_b = (const float*)d_in[18];
    const int*   Kptr     = (const int*)d_in[20];

    const int S = in_sizes[0] / (BATCH * DMODEL);
    const int M = BATCH * S;
    const size_t plane = (size_t)M * 256;

    float* base = nullptr;
    cudaGetSymbolAddress((void**)&base, g_scratch);
    __nv_bfloat16* xsp = (__nv_bfloat16*)(base + 0 * CHUNK);
    __nv_bfloat16* qsp = (__nv_bfloat16*)(base + 1 * CHUNK);
    __nv_bfloat16* ksp = (__nv_bfloat16*)(base + 2 * CHUNK);
    __half*        vsp = (__half*)(base + 3 * CHUNK);
    __nv_bfloat16* aosp = (__nv_bfloat16*)(base + 4 * CHUNK);

    __nv_bfloat16* wsp = nullptr;
    cudaGetSymbolAddress((void**)&wsp, g_wsplit);

    cudaFuncSetAttribute(attn_tc, cudaFuncAttributeMaxDynamicSharedMemorySize, ATTN_DYN);
    cudaFuncSetAttribute(gemm_tc, cudaFuncAttributeMaxDynamicSharedMemorySize, GEMM_DYN);
    cudaFuncSetAttribute(qkv_tc, cudaFuncAttributeMaxDynamicSharedMemorySize, GEMM_DYN);

    WP wp;
    wp.p[0] = Wq;        wp.p[1] = Wq + 65536;
    wp.p[2] = Wk;        wp.p[3] = Wk + 65536;
    wp.p[4] = Wv;        wp.p[5] = Wv + 65536;
    wp.p[6] = mha_fc_w;  wp.p[7] = mha_fc_w + 65536;
    wp.p[8] = d_fc1_w;   wp.p[9] = d_fc1_w + 65536;
    wp.p[10] = d_fc2_w;  wp.p[11] = d_fc2_w + 65536;
    wp.p[12] = out_fc_w;
    prep_w<<<dim3(64, 13), 256>>>(wp, wsp);
    conv_split<<<M / 4, 256>>>(samples, xsp, plane);

    dim3 ga((S + 63) / 64, NHEAD, BATCH);
    const int GR = (M + 63) / 64;

    for (int l = 0; l < 2; l++) {
        qkv_tc<<<GR, 256, GEMM_DYN>>>(xsp,
                                      wsp + (size_t)(0 + l) * 131072,
                                      wsp + (size_t)(2 + l) * 131072,
                                      wsp + (size_t)(4 + l) * 131072,
                                      qsp, ksp, vsp, plane);
        attn_tc<<<ga, 256, ATTN_DYN>>>(qsp, ksp, vsp, plane,
                                       attn_w + l * 24, Kptr, aosp, S);
        gemm_tc<<<GR, 256, GEMM_DYN>>>(aosp, wsp + (size_t)(6 + l) * 131072,
                                       mha_fc_b + l * 256, xsp, nullptr,
                                       mha_ln_g + l * 256, mha_ln_b + l * 256,
                                       xsp, nullptr, plane, 0);
        gemm_tc<<<GR, 256, GEMM_DYN>>>(xsp, wsp + (size_t)(8 + l) * 131072,
                                       d_fc1_b + l * 256, nullptr, nullptr,
                                       nullptr, nullptr, qsp, nullptr, plane, 1);
        gemm_tc<<<GR, 256, GEMM_DYN>>>(qsp, wsp + (size_t)(10 + l) * 131072,
                                       d_fc2_b + l * 256, xsp, nullptr,
                                       d_ln_g + l * 256, d_ln_b + l * 256,
                                       xsp, nullptr, plane, 0);
    }
    gemm_tc<<<GR, 256, GEMM_DYN>>>(xsp, wsp + (size_t)12 * 131072,
                                   out_fc_b, nullptr, samples,
                                   out_ln_g, out_ln_b,
                                   nullptr, (float*)d_out, plane, 0);
}

// round 14
// speedup vs baseline: 3.4391x; 1.0669x over previous
#include <cuda_runtime.h>
#include <cuda_bf16.h>
#include <cuda_fp16.h>
#include <math.h>
#include <stdint.h>

#define DMODEL 256
#define BATCH  128
#define NHEAD  4
#define DK     64

#define CHUNK (128ull * 512ull * 256ull)
__device__ float g_scratch[5ull * CHUNK];
__device__ __nv_bfloat16 g_wsplit[13ull * 131072ull];

// ---------------------------------------------------------------------------
__device__ __forceinline__ uint32_t smem_u32(const void* p) {
    uint32_t a;
    asm("{ .reg .u64 t; cvta.to.shared.u64 t, %1; cvt.u32.u64 %0, t; }" : "=r"(a) : "l"(p));
    return a;
}
__device__ __forceinline__ void mma16816(float* c,
                                         uint32_t a0, uint32_t a1, uint32_t a2, uint32_t a3,
                                         uint32_t b0, uint32_t b1) {
    asm volatile(
        "mma.sync.aligned.m16n8k16.row.col.f32.bf16.bf16.f32 "
        "{%0,%1,%2,%3},{%4,%5,%6,%7},{%8,%9},{%0,%1,%2,%3};"
        : "+f"(c[0]), "+f"(c[1]), "+f"(c[2]), "+f"(c[3])
        : "r"(a0), "r"(a1), "r"(a2), "r"(a3), "r"(b0), "r"(b1));
}
__device__ __forceinline__ void mma16816h(float* c,
                                          uint32_t a0, uint32_t a1, uint32_t a2, uint32_t a3,
                                          uint32_t b0, uint32_t b1) {
    asm volatile(
        "mma.sync.aligned.m16n8k16.row.col.f32.f16.f16.f32 "
        "{%0,%1,%2,%3},{%4,%5,%6,%7},{%8,%9},{%0,%1,%2,%3};"
        : "+f"(c[0]), "+f"(c[1]), "+f"(c[2]), "+f"(c[3])
        : "r"(a0), "r"(a1), "r"(a2), "r"(a3), "r"(b0), "r"(b1));
}
__device__ __forceinline__ void ldsm4(uint32_t* r, uint32_t a) {
    asm volatile("ldmatrix.sync.aligned.m8n8.x4.shared.b16 {%0,%1,%2,%3}, [%4];"
        : "=r"(r[0]), "=r"(r[1]), "=r"(r[2]), "=r"(r[3]) : "r"(a));
}
__device__ __forceinline__ void ldsm4t(uint32_t* r, uint32_t a) {
    asm volatile("ldmatrix.sync.aligned.m8n8.x4.trans.shared.b16 {%0,%1,%2,%3}, [%4];"
        : "=r"(r[0]), "=r"(r[1]), "=r"(r[2]), "=r"(r[3]) : "r"(a));
}
__device__ __forceinline__ void cp16(uint32_t saddr, const void* g) {
    asm volatile("cp.async.cg.shared.global [%0], [%1], 16;" :: "r"(saddr), "l"(g));
}
__device__ __forceinline__ void sts16z(uint32_t a) {
    asm volatile("st.shared.v4.u32 [%0], {%1,%1,%1,%1};" :: "r"(a), "r"(0u));
}
#define CP_COMMIT() asm volatile("cp.async.commit_group;" ::: "memory")
#define CP_WAIT1()  asm volatile("cp.async.wait_group 1;" ::: "memory")
#define CP_WAIT0()  asm volatile("cp.async.wait_group 0;" ::: "memory")

// ---------------------------------------------------------------------------
struct WP { const float* p[13]; };

__global__ void prep_w(WP wp, __nv_bfloat16* dst) {
    const int mid = blockIdx.y;
    const float* W = wp.p[mid];
    __nv_bfloat16* hi = dst + (size_t)mid * 131072;
    __nv_bfloat16* lo = hi + 65536;
    int idx0 = blockIdx.x * 1024 + threadIdx.x;
    #pragma unroll
    for (int i = 0; i < 4; i++) {
        int idx = idx0 + i * 256;
        int k = idx >> 8, n = idx & 255;
        float x = W[idx];
        __nv_bfloat16 h = __float2bfloat16(x);
        hi[n * 256 + k] = h;
        lo[n * 256 + k] = __float2bfloat16(x - __bfloat162float(h));
    }
}

__global__ void conv_split(const float* __restrict__ X, __nv_bfloat16* __restrict__ Osp,
                           size_t planeEl) {
    int i = (blockIdx.x * 256 + threadIdx.x) * 4;
    float4 a = *(const float4*)(X + i);
    __nv_bfloat162 h0 = __floats2bfloat162_rn(a.x, a.y);
    __nv_bfloat162 h1 = __floats2bfloat162_rn(a.z, a.w);
    float r0 = a.x - __bfloat162float(__low2bfloat16(h0));
    float r1 = a.y - __bfloat162float(__high2bfloat16(h0));
    float r2 = a.z - __bfloat162float(__low2bfloat16(h1));
    float r3 = a.w - __bfloat162float(__high2bfloat16(h1));
    __nv_bfloat162 l0 = __floats2bfloat162_rn(r0, r1);
    __nv_bfloat162 l1 = __floats2bfloat162_rn(r2, r3);
    *(__nv_bfloat162*)(Osp + i) = h0;
    *(__nv_bfloat162*)(Osp + i + 2) = h1;
    *(__nv_bfloat162*)(Osp + planeEl + i) = l0;
    *(__nv_bfloat162*)(Osp + planeEl + i + 2) = l1;
}

// ---------------------------------------------------------------------------
// GEMM (fragment-sharing mainloop)
// ---------------------------------------------------------------------------
#define KC   32
#define ST2  40
#define APL2 (64 * ST2 * 2)
#define BPL2 (256 * ST2 * 2)
#define STG2 (2 * APL2 + 2 * BPL2)
#define GEMM_DYN (2 * STG2)

__device__ __forceinline__ void issue_chunkA(const __nv_bfloat16* __restrict__ Asp,
                                             size_t planeEl, int bm, int kc,
                                             uint32_t aSt, int tid) {
    #pragma unroll
    for (int i = 0; i < 2; i++) {
        int it = tid + i * 256;
        int p = it >> 8, rem = it & 255, r = rem >> 2, k8 = (rem & 3) << 3;
        uint32_t d = aSt + p * APL2 + (uint32_t)(r * ST2 + k8) * 2;
        cp16(d, Asp + p * planeEl + (size_t)(bm + r) * 256 + kc * KC + k8);
    }
}
__device__ __forceinline__ void issue_chunkB(const __nv_bfloat16* __restrict__ Whi,
                                             int kc, uint32_t bSt, int tid) {
    const __nv_bfloat16* Wlo = Whi + 65536;
    #pragma unroll
    for (int i = 0; i < 8; i++) {
        int it = tid + i * 256;
        int p = it >> 10, rem = it & 1023, n = rem >> 2, k8 = (rem & 3) << 3;
        uint32_t d = bSt + p * BPL2 + (uint32_t)(n * ST2 + k8) * 2;
        cp16(d, (p ? Wlo : Whi) + n * 256 + kc * KC + k8);
    }
}

__device__ __forceinline__ void mma_chunk32(
    uint32_t aSt, uint32_t bSt, uint32_t aLM, uint32_t bLM, int wid, float acc[4][4][4])
{
    #pragma unroll
    for (int ks = 0; ks < 2; ks++) {
        uint32_t ah[4][4], al[4][4];
        #pragma unroll
        for (int mf = 0; mf < 4; mf++) {
            ldsm4(ah[mf], aSt + ks * 32 + aLM + (mf * 16) * (ST2 * 2));
            ldsm4(al[mf], aSt + APL2 + ks * 32 + aLM + (mf * 16) * (ST2 * 2));
        }
        #pragma unroll
        for (int nb = 0; nb < 2; nb++) {
            uint32_t bh[4], bl[4];
            ldsm4(bh, bSt + ks * 32 + bLM + (wid * 32 + nb * 16) * (ST2 * 2));
            ldsm4(bl, bSt + BPL2 + ks * 32 + bLM + (wid * 32 + nb * 16) * (ST2 * 2));
            #pragma unroll
            for (int mf = 0; mf < 4; mf++) {
                mma16816(acc[mf][2*nb],   ah[mf][0], ah[mf][1], ah[mf][2], ah[mf][3], bh[0], bh[1]);
                mma16816(acc[mf][2*nb],   ah[mf][0], ah[mf][1], ah[mf][2], ah[mf][3], bl[0], bl[1]);
                mma16816(acc[mf][2*nb],   al[mf][0], al[mf][1], al[mf][2], al[mf][3], bh[0], bh[1]);
                mma16816(acc[mf][2*nb+1], ah[mf][0], ah[mf][1], ah[mf][2], ah[mf][3], bh[2], bh[3]);
                mma16816(acc[mf][2*nb+1], ah[mf][0], ah[mf][1], ah[mf][2], ah[mf][3], bl[2], bl[3]);
                mma16816(acc[mf][2*nb+1], al[mf][0], al[mf][1], al[mf][2], al[mf][3], bh[2], bh[3]);
            }
        }
    }
}

__device__ __forceinline__ void split_store(__nv_bfloat16* Cr, size_t planeEl,
                                            int c, float v0, float v1) {
    __nv_bfloat162 hp = __floats2bfloat162_rn(v0, v1);
    float r0 = v0 - __bfloat162float(__low2bfloat16(hp));
    float r1 = v1 - __bfloat162float(__high2bfloat16(hp));
    __nv_bfloat162 lp = __floats2bfloat162_rn(r0, r1);
    *(__nv_bfloat162*)(Cr + c) = hp;
    *(__nv_bfloat162*)(Cr + planeEl + c) = lp;
}

__global__ __launch_bounds__(256, 2) void gemm_tc(
    const __nv_bfloat16* __restrict__ Asp, const __nv_bfloat16* __restrict__ Wsp,
    const float* __restrict__ bias,
    const __nv_bfloat16* __restrict__ residSp, const float* __restrict__ residF,
    const float* __restrict__ lng, const float* __restrict__ lnb,
    __nv_bfloat16* __restrict__ OutSp, float* __restrict__ OutF,
    size_t planeEl, int relu)
{
    extern __shared__ char dsm[];
    __shared__ float s_bias[256], s_g[256], s_b[256];
    __shared__ float s_sum[64], s_ssq[64];

    const int tid = threadIdx.x;
    const int wid = tid >> 5, lane = tid & 31;
    const int lq = lane >> 2, lr = lane & 3;
    const int bm = blockIdx.x * 64;

    const uint32_t base = smem_u32(dsm);
    const uint32_t aLM = ((uint32_t)((lane & 15) * ST2) + ((lane >> 4) << 3)) * 2;
    const uint32_t bLM = ((uint32_t)((((lane >> 4) << 3) + (lane & 7)) * ST2) + (((lane >> 3) & 1) << 3)) * 2;

    issue_chunkA(Asp, planeEl, bm, 0, base, tid);
    issue_chunkB(Wsp, 0, base + 2 * APL2, tid);
    CP_COMMIT();

    s_bias[tid] = bias ? bias[tid] : 0.f;
    if (lng) { s_g[tid] = lng[tid]; s_b[tid] = lnb[tid]; }
    if (tid < 64) { s_sum[tid] = 0.f; s_ssq[tid] = 0.f; }

    float acc[4][4][4];
    #pragma unroll
    for (int mf = 0; mf < 4; mf++)
        #pragma unroll
        for (int nf = 0; nf < 4; nf++)
            #pragma unroll
            for (int j = 0; j < 4; j++) acc[mf][nf][j] = 0.f;

    for (int c = 0; c < 8; c++) {
        if (c < 7) {
            uint32_t st = base + ((c + 1) & 1) * STG2;
            issue_chunkA(Asp, planeEl, bm, c + 1, st, tid);
            issue_chunkB(Wsp, c + 1, st + 2 * APL2, tid);
            CP_COMMIT();
        }
        if (c < 7) CP_WAIT1(); else CP_WAIT0();
        __syncthreads();
        uint32_t st = base + (c & 1) * STG2;
        mma_chunk32(st, st + 2 * APL2, aLM, bLM, wid, acc);
        __syncthreads();
    }

    if (lng) {
        #pragma unroll
        for (int mf = 0; mf < 4; mf++) {
            #pragma unroll
            for (int h = 0; h < 2; h++) {
                int r = mf * 16 + lq + h * 8;
                float ps = 0.f, pq = 0.f;
                #pragma unroll
                for (int nf = 0; nf < 4; nf++) {
                    int c = wid * 32 + nf * 8 + lr * 2;
                    float rv0, rv1;
                    if (residF) {
                        float2 t = *(const float2*)(residF + (size_t)(bm + r) * 256 + c);
                        rv0 = t.x; rv1 = t.y;
                    } else {
                        __nv_bfloat162 h2 = *(const __nv_bfloat162*)(residSp + (size_t)(bm + r) * 256 + c);
                        __nv_bfloat162 l2 = *(const __nv_bfloat162*)(residSp + planeEl + (size_t)(bm + r) * 256 + c);
                        rv0 = __bfloat162float(__low2bfloat16(h2)) + __bfloat162float(__low2bfloat16(l2));
                        rv1 = __bfloat162float(__high2bfloat16(h2)) + __bfloat162float(__high2bfloat16(l2));
                    }
                    float v0 = acc[mf][nf][h * 2 + 0] + s_bias[c] + rv0;
                    float v1 = acc[mf][nf][h * 2 + 1] + s_bias[c + 1] + rv1;
                    acc[mf][nf][h * 2 + 0] = v0;
                    acc[mf][nf][h * 2 + 1] = v1;
                    ps += v0 + v1;
                    pq += v0 * v0 + v1 * v1;
                }
                ps += __shfl_xor_sync(0xffffffffu, ps, 1);
                ps += __shfl_xor_sync(0xffffffffu, ps, 2);
                pq += __shfl_xor_sync(0xffffffffu, pq, 1);
                pq += __shfl_xor_sync(0xffffffffu, pq, 2);
                if (lr == 0) {
                    atomicAdd(&s_sum[r], ps);
                    atomicAdd(&s_ssq[r], pq);
                }
            }
        }
        __syncthreads();
        if (tid < 64) {
            float mu = s_sum[tid] * (1.f / 256.f);
            float var = s_ssq[tid] * (1.f / 256.f) - mu * mu;
            s_sum[tid] = mu;
            s_ssq[tid] = rsqrtf(var + 1e-5f);
        }
        __syncthreads();
        #pragma unroll
        for (int mf = 0; mf < 4; mf++) {
            #pragma unroll
            for (int h = 0; h < 2; h++) {
                int r = mf * 16 + lq + h * 8;
                float mu = s_sum[r], rs = s_ssq[r];
                #pragma unroll
                for (int nf = 0; nf < 4; nf++) {
                    int c = wid * 32 + nf * 8 + lr * 2;
                    float v0 = (acc[mf][nf][h * 2 + 0] - mu) * rs * s_g[c] + s_b[c];
                    float v1 = (acc[mf][nf][h * 2 + 1] - mu) * rs * s_g[c + 1] + s_b[c + 1];
                    if (OutF)
                        *(float2*)(OutF + (size_t)(bm + r) * 256 + c) = make_float2(v0, v1);
                    else
                        split_store(OutSp + (size_t)(bm + r) * 256, planeEl, c, v0, v1);
                }
            }
        }
    } else {
        #pragma unroll
        for (int mf = 0; mf < 4; mf++) {
            #pragma unroll
            for (int h = 0; h < 2; h++) {
                int r = mf * 16 + lq + h * 8;
                #pragma unroll
                for (int nf = 0; nf < 4; nf++) {
                    int c = wid * 32 + nf * 8 + lr * 2;
                    float v0 = acc[mf][nf][h * 2 + 0] + s_bias[c];
                    float v1 = acc[mf][nf][h * 2 + 1] + s_bias[c + 1];
                    if (relu) { v0 = fmaxf(v0, 0.f); v1 = fmaxf(v1, 0.f); }
                    split_store(OutSp + (size_t)(bm + r) * 256, planeEl, c, v0, v1);
                }
            }
        }
    }
}

// ---------------------------------------------------------------------------
// Fused QKV; V stored single-plane f16.
// ---------------------------------------------------------------------------
__global__ __launch_bounds__(256, 2) void qkv_tc(
    const __nv_bfloat16* __restrict__ Asp,
    const __nv_bfloat16* __restrict__ Wq_, const __nv_bfloat16* __restrict__ Wk_,
    const __nv_bfloat16* __restrict__ Wv_,
    __nv_bfloat16* __restrict__ Qs, __nv_bfloat16* __restrict__ Ks,
    __half* __restrict__ Vs, size_t planeEl)
{
    extern __shared__ char dsm[];
    const int tid = threadIdx.x;
    const int wid = tid >> 5, lane = tid & 31;
    const int lq = lane >> 2, lr = lane & 3;
    const int bm = blockIdx.x * 64;

    const uint32_t base = smem_u32(dsm);
    const uint32_t aLM = ((uint32_t)((lane & 15) * ST2) + ((lane >> 4) << 3)) * 2;
    const uint32_t bLM = ((uint32_t)((((lane >> 4) << 3) + (lane & 7)) * ST2) + (((lane >> 3) & 1) << 3)) * 2;

    const __nv_bfloat16* Ws[3] = {Wq_, Wk_, Wv_};

    issue_chunkA(Asp, planeEl, bm, 0, base, tid);
    issue_chunkB(Ws[0], 0, base + 2 * APL2, tid);
    CP_COMMIT();

    float acc[4][4][4];

    for (int c = 0; c < 24; c++) {
        if (c + 1 < 24) {
            uint32_t st = base + ((c + 1) & 1) * STG2;
            issue_chunkA(Asp, planeEl, bm, (c + 1) & 7, st, tid);
            issue_chunkB(Ws[(c + 1) >> 3], (c + 1) & 7, st + 2 * APL2, tid);
            CP_COMMIT();
        }
        if (c + 1 < 24) CP_WAIT1(); else CP_WAIT0();
        __syncthreads();
        if ((c & 7) == 0) {
            #pragma unroll
            for (int mf = 0; mf < 4; mf++)
                #pragma unroll
                for (int nf = 0; nf < 4; nf++)
                    #pragma unroll
                    for (int j = 0; j < 4; j++) acc[mf][nf][j] = 0.f;
        }
        uint32_t st = base + (c & 1) * STG2;
        mma_chunk32(st, st + 2 * APL2, aLM, bLM, wid, acc);
        __syncthreads();

        if ((c & 7) == 7) {
            int m = c >> 3;
            if (m < 2) {
                float scale = (m == 0) ? 0.125f * 1.44269504f : 1.0f;
                __nv_bfloat16* Out = (m == 0) ? Qs : Ks;
                #pragma unroll
                for (int mf = 0; mf < 4; mf++)
                    #pragma unroll
                    for (int h = 0; h < 2; h++) {
                        int r = mf * 16 + lq + h * 8;
                        #pragma unroll
                        for (int nf = 0; nf < 4; nf++) {
                            int cc = wid * 32 + nf * 8 + lr * 2;
                            split_store(Out + (size_t)(bm + r) * 256, planeEl, cc,
                                        acc[mf][nf][h * 2 + 0] * scale,
                                        acc[mf][nf][h * 2 + 1] * scale);
                        }
                    }
            } else {
                #pragma unroll
                for (int mf = 0; mf < 4; mf++)
                    #pragma unroll
                    for (int h = 0; h < 2; h++) {
                        int r = mf * 16 + lq + h * 8;
                        __half* Cr = Vs + (size_t)(bm + r) * 256;
                        #pragma unroll
                        for (int nf = 0; nf < 4; nf++) {
                            int cc = wid * 32 + nf * 8 + lr * 2;
                            *(__half2*)(Cr + cc) =
                                __floats2half2_rn(acc[mf][nf][h * 2 + 0],
                                                  acc[mf][nf][h * 2 + 1]);
                        }
                    }
            }
        }
    }
}

// ---------------------------------------------------------------------------
// Flash attention: 3-plane KV stages (Khi,Klo,V-f16), fragment-sharing QK,
// single-pass PV.
// ---------------------------------------------------------------------------
#define APAD 72
#define PL1  (64 * APAD * 2)
#define KVST3 (3 * PL1)
#define ATTN_DYN (2 * PL1 + 2 * KVST3 + PL1)   // 82944

__device__ __forceinline__ void issue_q(const __nv_bfloat16* Qsp, size_t planeEl,
                                        size_t rowB, int q0, int col0, int S,
                                        uint32_t dst, int tid) {
    #pragma unroll
    for (int i = 0; i < 4; i++) {
        int it = tid + i * 256;
        int p = it >> 9, r = (it >> 3) & 63, c8 = (it & 7) << 3;
        uint32_t d = dst + p * PL1 + (uint32_t)(r * APAD + c8) * 2;
        if (q0 + r < S)
            cp16(d, Qsp + p * planeEl + (rowB + q0 + r) * 256 + col0 + c8);
        else
            sts16z(d);
    }
}
__device__ __forceinline__ void issue_kv3(const __nv_bfloat16* Ksp, const __half* Vsp,
                                          size_t planeEl, size_t rowB, int k0, int col0,
                                          int S, uint32_t stage, int tid) {
    #pragma unroll
    for (int i = 0; i < 6; i++) {
        int it = tid + i * 256;
        int p = it >> 9, r = (it >> 3) & 63, c8 = (it & 7) << 3;
        uint32_t d = stage + p * PL1 + (uint32_t)(r * APAD + c8) * 2;
        if (k0 + r < S) {
            const void* g;
            if (p < 2) g = Ksp + p * planeEl + (rowB + k0 + r) * 256 + col0 + c8;
            else       g = Vsp + (rowB + k0 + r) * 256 + col0 + c8;
            cp16(d, g);
        } else sts16z(d);
    }
}

__global__ __launch_bounds__(256, 2) void attn_tc(
    const __nv_bfloat16* __restrict__ Qsp, const __nv_bfloat16* __restrict__ Ksp,
    const __half* __restrict__ Vsp, size_t plane,
    const float* __restrict__ AW, const int* __restrict__ Kcls,
    __nv_bfloat16* __restrict__ Osp, int S)
{
    extern __shared__ char smraw[];
    __shared__ float tw[6];
    __shared__ float redbuf[2][64];

    const int b = blockIdx.z, h = blockIdx.y, q0 = blockIdx.x * 64;
    const int tid = threadIdx.x, wid = tid >> 5, lane = tid & 31;
    const int lq = lane >> 2, lr = lane & 3;
    const int wm = wid >> 1, wn = wid & 1;
    const int Kc = *Kcls;
    const int NK = S - 1;
    const size_t rowB = (size_t)b * S;
    const int col0 = h * 64;

    const uint32_t sQB  = smem_u32(smraw);
    const uint32_t sKVB = sQB + 2 * PL1;
    const uint32_t sPB  = sKVB + 2 * KVST3;
    const uint32_t aLM = ((uint32_t)((lane & 15) * APAD) + ((lane >> 4) << 3)) * 2;
    const uint32_t bLM = ((uint32_t)((((lane >> 4) << 3) + (lane & 7)) * APAD) + (((lane >> 3) & 1) << 3)) * 2;
    const uint32_t vLM = ((uint32_t)(((((lane >> 3) & 1) << 3) + (lane & 7)) * APAD) + (((lane >> 4) & 1) << 3)) * 2;

    const int SP = (S + 63) >> 6;

    issue_q(Qsp, plane, rowB, q0, col0, S, sQB, tid);
    issue_kv3(Ksp, Vsp, plane, rowB, 0, col0, S, sKVB, tid);
    CP_COMMIT();

    if (tid < 6) tw[tid] = tanhf(AW[h * 6 + tid]);

    const int r0 = wm * 16 + lq, r1 = r0 + 8;
    const int qg0 = q0 + r0, qg1 = q0 + r1;

    float m0 = -1e30f, m1 = -1e30f, sum0 = 0.f, sum1 = 0.f;
    float oacc[4][4];
    #pragma unroll
    for (int j = 0; j < 4; j++)
        #pragma unroll
        for (int e = 0; e < 4; e++) oacc[j][e] = 0.f;

    float gOut0, gIn0, gDiag0, gLast0, gOut1, gIn1, gDiag1, gLast1;
    int lo0, hi0, lo1, hi1;
    const int qdv0 = qg0 / Kc, qdv1 = qg1 / Kc;

    for (int t = 0; t < SP; t++) {
        int k0 = t * 64;
        if (t + 1 < SP) {
            issue_kv3(Ksp, Vsp, plane, rowB, (t + 1) * 64, col0, S,
                      sKVB + ((t + 1) & 1) * KVST3, tid);
            CP_COMMIT();
        }
        if (t + 1 < SP) CP_WAIT1(); else CP_WAIT0();
        __syncthreads();

        if (t == 0) {
            bool isQ0 = (qg0 == NK), isQ1 = (qg1 == NK);
            lo0 = isQ0 ? -1 : qdv0 * Kc; hi0 = isQ0 ? -1 : lo0 + Kc;
            lo1 = isQ1 ? -1 : qdv1 * Kc; hi1 = isQ1 ? -1 : lo1 + Kc;
            gOut0 = isQ0 ? tw[4] : tw[2]; gIn0 = isQ0 ? tw[4] : tw[1];
            gDiag0 = isQ0 ? tw[5] : tw[0]; gLast0 = isQ0 ? tw[5] : tw[3];
            gOut1 = isQ1 ? tw[4] : tw[2]; gIn1 = isQ1 ? tw[4] : tw[1];
            gDiag1 = isQ1 ? tw[5] : tw[0]; gLast1 = isQ1 ? tw[5] : tw[3];
        }

        const uint32_t kvSt = sKVB + (t & 1) * KVST3;

        // ---- scores: fragment-sharing 3-combo ----
        float acc[4][4] = {};
        #pragma unroll
        for (int ks = 0; ks < 4; ks++) {
            uint32_t qh[4], ql[4];
            ldsm4(qh, sQB + (wm * 16) * (APAD * 2) + aLM + ks * 32);
            ldsm4(ql, sQB + PL1 + (wm * 16) * (APAD * 2) + aLM + ks * 32);
            #pragma unroll
            for (int nb = 0; nb < 2; nb++) {
                uint32_t kh[4], kl[4];
                ldsm4(kh, kvSt + (wn * 32 + nb * 16) * (APAD * 2) + bLM + ks * 32);
                ldsm4(kl, kvSt + PL1 + (wn * 32 + nb * 16) * (APAD * 2) + bLM + ks * 32);
                mma16816(acc[2*nb],   qh[0], qh[1], qh[2], qh[3], kh[0], kh[1]);
                mma16816(acc[2*nb],   qh[0], qh[1], qh[2], qh[3], kl[0], kl[1]);
                mma16816(acc[2*nb],   ql[0], ql[1], ql[2], ql[3], kh[0], kh[1]);
                mma16816(acc[2*nb+1], qh[0], qh[1], qh[2], qh[3], kh[2], kh[3]);
                mma16816(acc[2*nb+1], qh[0], qh[1], qh[2], qh[3], kl[2], kl[3]);
                mma16816(acc[2*nb+1], ql[0], ql[1], ql[2], ql[3], kh[2], kh[3]);
            }
        }

        #pragma unroll
        for (int j = 0; j < 4; j++) {
            int c = k0 + wn * 32 + j * 8 + lr * 2;
            if (c >= S)     { acc[j][0] = -1e30f; acc[j][2] = -1e30f; }
            if (c + 1 >= S) { acc[j][1] = -1e30f; acc[j][3] = -1e30f; }
        }

        float mx0 = -1e30f, mx1 = -1e30f;
        #pragma unroll
        for (int j = 0; j < 4; j++) {
            mx0 = fmaxf(mx0, fmaxf(acc[j][0], acc[j][1]));
            mx1 = fmaxf(mx1, fmaxf(acc[j][2], acc[j][3]));
        }
        mx0 = fmaxf(mx0, __shfl_xor_sync(0xffffffffu, mx0, 1));
        mx0 = fmaxf(mx0, __shfl_xor_sync(0xffffffffu, mx0, 2));
        mx1 = fmaxf(mx1, __shfl_xor_sync(0xffffffffu, mx1, 1));
        mx1 = fmaxf(mx1, __shfl_xor_sync(0xffffffffu, mx1, 2));
        if (lr == 0) { redbuf[wn][r0] = mx0; redbuf[wn][r1] = mx1; }
        __syncthreads();
        float mn0 = fmaxf(m0, fmaxf(redbuf[0][r0], redbuf[1][r0]));
        float mn1 = fmaxf(m1, fmaxf(redbuf[0][r1], redbuf[1][r1]));
        float sc0 = exp2f(m0 - mn0), sc1 = exp2f(m1 - mn1);
        m0 = mn0; m1 = mn1;
        sum0 *= sc0; sum1 *= sc1;
        #pragma unroll
        for (int j = 0; j < 4; j++) {
            oacc[j][0] *= sc0; oacc[j][1] *= sc0;
            oacc[j][2] *= sc1; oacc[j][3] *= sc1;
        }

        __half* sP = (__half*)(smraw + (sPB - sQB));
        #pragma unroll
        for (int j = 0; j < 4; j++) {
            int lc = wn * 32 + j * 8 + lr * 2;
            int c = k0 + lc;
            __half2 e0 = h2exp2(__floats2half2_rn(acc[j][0] - mn0, acc[j][1] - mn0));
            __half2 e1 = h2exp2(__floats2half2_rn(acc[j][2] - mn1, acc[j][3] - mn1));
            float2 f0 = __half22float2(e0), f1 = __half22float2(e1);
            sum0 += f0.x + f0.y;
            sum1 += f1.x + f1.y;
            float ga = (c >= lo0 && c < hi0) ? gIn0 : gOut0;
            float gb = (c + 1 >= lo0 && c + 1 < hi0) ? gIn0 : gOut0;
            if (c == qg0) ga = gDiag0;
            if (c + 1 == qg0) gb = gDiag0;
            if (c == NK) ga = gLast0;
            if (c + 1 == NK) gb = gLast0;
            float gc = (c >= lo1 && c < hi1) ? gIn1 : gOut1;
            float gd = (c + 1 >= lo1 && c + 1 < hi1) ? gIn1 : gOut1;
            if (c == qg1) gc = gDiag1;
            if (c + 1 == qg1) gd = gDiag1;
            if (c == NK) gc = gLast1;
            if (c + 1 == NK) gd = gLast1;
            __half2 p0 = __hmul2(e0, __floats2half2_rn(ga, gb));
            __half2 p1 = __hmul2(e1, __floats2half2_rn(gc, gd));
            *(__half2*)(sP + r0 * APAD + lc) = p0;
            *(__half2*)(sP + r1 * APAD + lc) = p1;
        }
        __syncthreads();

        // ---- P @ V (single f16 pass) ----
        const uint32_t aB2 = sPB + (wm * 16) * (APAD * 2) + aLM;
        const uint32_t bB = kvSt + 2 * PL1 + vLM;
        #pragma unroll
        for (int ks = 0; ks < 4; ks++) {
            uint32_t af[4];
            ldsm4(af, aB2 + ks * 32);
            #pragma unroll
            for (int nb = 0; nb < 2; nb++) {
                uint32_t bf4[4];
                ldsm4t(bf4, bB + (wn * 32 + nb * 16) * 2 + ks * 16 * (APAD * 2));
                mma16816h(oacc[nb * 2], af[0], af[1], af[2], af[3], bf4[0], bf4[1]);
                mma16816h(oacc[nb * 2 + 1], af[0], af[1], af[2], af[3], bf4[2], bf4[3]);
            }
        }
    }

    sum0 += __shfl_xor_sync(0xffffffffu, sum0, 1);
    sum0 += __shfl_xor_sync(0xffffffffu, sum0, 2);
    sum1 += __shfl_xor_sync(0xffffffffu, sum1, 1);
    sum1 += __shfl_xor_sync(0xffffffffu, sum1, 2);
    __syncthreads();
    if (lr == 0) { redbuf[wn][r0] = sum0; redbuf[wn][r1] = sum1; }
    __syncthreads();
    float inv0 = 1.f / (redbuf[0][r0] + redbuf[1][r0]);
    float inv1 = 1.f / (redbuf[0][r1] + redbuf[1][r1]);

    #pragma unroll
    for (int j = 0; j < 4; j++) {
        int col = col0 + wn * 32 + j * 8 + lr * 2;
        if (qg0 < S)
            split_store(Osp + (rowB + qg0) * 256, plane, col,
                        oacc[j][0] * inv0, oacc[j][1] * inv0);
        if (qg1 < S)
            split_store(Osp + (rowB + qg1) * 256, plane, col,
                        oacc[j][2] * inv1, oacc[j][3] * inv1);
    }
}

// ---------------------------------------------------------------------------
extern "C" void kernel_launch(void* const* d_in, const int* in_sizes, int n_in,
                              void* d_out, int out_size) {
    const float* samples  = (const float*)d_in[0];
    const float* Wq       = (const float*)d_in[1];
    const float* Wk       = (const float*)d_in[2];
    const float* Wv       = (const float*)d_in[3];
    const float* attn_w   = (const float*)d_in[4];
    const float* mha_fc_w = (const float*)d_in[5];
    const float* mha_fc_b = (const float*)d_in[6];
    const float* mha_ln_g = (const float*)d_in[7];
    const float* mha_ln_b = (const float*)d_in[8];
    const float* d_fc1_w  = (const float*)d_in[9];
    const float* d_fc1_b  = (const float*)d_in[10];
    const float* d_fc2_w  = (const float*)d_in[11];
    const float* d_fc2_b  = (const float*)d_in[12];
    const float* d_ln_g   = (const float*)d_in[13];
    const float* d_ln_b   = (const float*)d_in[14];
    const float* out_fc_w = (const float*)d_in[15];
    const float* out_fc_b = (const float*)d_in[16];
    const float* out_ln_g = (const float*)d_in[17];
    const float* out_ln_b = (const float*)d_in[18];
    const int*   Kptr     = (const int*)d_in[20];

    const int S = in_sizes[0] / (BATCH * DMODEL);
    const int M = BATCH * S;
    const size_t plane = (size_t)M * 256;

    float* base = nullptr;
    cudaGetSymbolAddress((void**)&base, g_scratch);
    __nv_bfloat16* xsp = (__nv_bfloat16*)(base + 0 * CHUNK);
    __nv_bfloat16* qsp = (__nv_bfloat16*)(base + 1 * CHUNK);
    __nv_bfloat16* ksp = (__nv_bfloat16*)(base + 2 * CHUNK);
    __half*        vsp = (__half*)(base + 3 * CHUNK);
    __nv_bfloat16* aosp = (__nv_bfloat16*)(base + 4 * CHUNK);

    __nv_bfloat16* wsp = nullptr;
    cudaGetSymbolAddress((void**)&wsp, g_wsplit);

    cudaFuncSetAttribute(attn_tc, cudaFuncAttributeMaxDynamicSharedMemorySize, ATTN_DYN);
    cudaFuncSetAttribute(gemm_tc, cudaFuncAttributeMaxDynamicSharedMemorySize, GEMM_DYN);
    cudaFuncSetAttribute(qkv_tc, cudaFuncAttributeMaxDynamicSharedMemorySize, GEMM_DYN);

    WP wp;
    wp.p[0] = Wq;        wp.p[1] = Wq + 65536;
    wp.p[2] = Wk;        wp.p[3] = Wk + 65536;
    wp.p[4] = Wv;        wp.p[5] = Wv + 65536;
    wp.p[6] = mha_fc_w;  wp.p[7] = mha_fc_w + 65536;
    wp.p[8] = d_fc1_w;   wp.p[9] = d_fc1_w + 65536;
    wp.p[10] = d_fc2_w;  wp.p[11] = d_fc2_w + 65536;
    wp.p[12] = out_fc_w;
    prep_w<<<dim3(64, 13), 256>>>(wp, wsp);
    conv_split<<<M / 4, 256>>>(samples, xsp, plane);

    dim3 ga((S + 63) / 64, NHEAD, BATCH);
    const int GR = (M + 63) / 64;

    for (int l = 0; l < 2; l++) {
        qkv_tc<<<GR, 256, GEMM_DYN>>>(xsp,
                                      wsp + (size_t)(0 + l) * 131072,
                                      wsp + (size_t)(2 + l) * 131072,
                                      wsp + (size_t)(4 + l) * 131072,
                                      qsp, ksp, vsp, plane);
        attn_tc<<<ga, 256, ATTN_DYN>>>(qsp, ksp, vsp, plane,
                                       attn_w + l * 24, Kptr, aosp, S);
        gemm_tc<<<GR, 256, GEMM_DYN>>>(aosp, wsp + (size_t)(6 + l) * 131072,
                                       mha_fc_b + l * 256, xsp, nullptr,
                                       mha_ln_g + l * 256, mha_ln_b + l * 256,
                                       xsp, nullptr, plane, 0);
        gemm_tc<<<GR, 256, GEMM_DYN>>>(xsp, wsp + (size_t)(8 + l) * 131072,
                                       d_fc1_b + l * 256, nullptr, nullptr,
                                       nullptr, nullptr, qsp, nullptr, plane, 1);
        gemm_tc<<<GR, 256, GEMM_DYN>>>(qsp, wsp + (size_t)(10 + l) * 131072,
                                       d_fc2_b + l * 256, xsp, nullptr,
                                       d_ln_g + l * 256, d_ln_b + l * 256,
                                       xsp, nullptr, plane, 0);
    }
    gemm_tc<<<GR, 256, GEMM_DYN>>>(xsp, wsp + (size_t)12 * 131072,
                                   out_fc_b, nullptr, samples,
                                   out_ln_g, out_ln_b,
                                   nullptr, (float*)d_out, plane, 0);
}

// round 15
// speedup vs baseline: 3.5116x; 1.0211x over previous
#include <cuda_runtime.h>
#include <cuda_bf16.h>
#include <cuda_fp16.h>
#include <math.h>
#include <stdint.h>

#define DMODEL 256
#define BATCH  128
#define NHEAD  4
#define DK     64

#define CHUNK (128ull * 512ull * 256ull)
__device__ float g_scratch[5ull * CHUNK];
__device__ __nv_bfloat16 g_wsplit[13ull * 131072ull];

// ---------------------------------------------------------------------------
__device__ __forceinline__ uint32_t smem_u32(const void* p) {
    uint32_t a;
    asm("{ .reg .u64 t; cvta.to.shared.u64 t, %1; cvt.u32.u64 %0, t; }" : "=r"(a) : "l"(p));
    return a;
}
__device__ __forceinline__ void mma16816(float* c,
                                         uint32_t a0, uint32_t a1, uint32_t a2, uint32_t a3,
                                         uint32_t b0, uint32_t b1) {
    asm volatile(
        "mma.sync.aligned.m16n8k16.row.col.f32.bf16.bf16.f32 "
        "{%0,%1,%2,%3},{%4,%5,%6,%7},{%8,%9},{%0,%1,%2,%3};"
        : "+f"(c[0]), "+f"(c[1]), "+f"(c[2]), "+f"(c[3])
        : "r"(a0), "r"(a1), "r"(a2), "r"(a3), "r"(b0), "r"(b1));
}
__device__ __forceinline__ void mma16816h(float* c,
                                          uint32_t a0, uint32_t a1, uint32_t a2, uint32_t a3,
                                          uint32_t b0, uint32_t b1) {
    asm volatile(
        "mma.sync.aligned.m16n8k16.row.col.f32.f16.f16.f32 "
        "{%0,%1,%2,%3},{%4,%5,%6,%7},{%8,%9},{%0,%1,%2,%3};"
        : "+f"(c[0]), "+f"(c[1]), "+f"(c[2]), "+f"(c[3])
        : "r"(a0), "r"(a1), "r"(a2), "r"(a3), "r"(b0), "r"(b1));
}
__device__ __forceinline__ void ldsm4(uint32_t* r, uint32_t a) {
    asm volatile("ldmatrix.sync.aligned.m8n8.x4.shared.b16 {%0,%1,%2,%3}, [%4];"
        : "=r"(r[0]), "=r"(r[1]), "=r"(r[2]), "=r"(r[3]) : "r"(a));
}
__device__ __forceinline__ void ldsm4t(uint32_t* r, uint32_t a) {
    asm volatile("ldmatrix.sync.aligned.m8n8.x4.trans.shared.b16 {%0,%1,%2,%3}, [%4];"
        : "=r"(r[0]), "=r"(r[1]), "=r"(r[2]), "=r"(r[3]) : "r"(a));
}
__device__ __forceinline__ void cp16(uint32_t saddr, const void* g) {
    asm volatile("cp.async.cg.shared.global [%0], [%1], 16;" :: "r"(saddr), "l"(g));
}
__device__ __forceinline__ void sts16z(uint32_t a) {
    asm volatile("st.shared.v4.u32 [%0], {%1,%1,%1,%1};" :: "r"(a), "r"(0u));
}
#define CP_COMMIT() asm volatile("cp.async.commit_group;" ::: "memory")
#define CP_WAIT1()  asm volatile("cp.async.wait_group 1;" ::: "memory")
#define CP_WAIT0()  asm volatile("cp.async.wait_group 0;" ::: "memory")

// ---------------------------------------------------------------------------
struct WP { const float* p[13]; };

__global__ void prep_w(WP wp, __nv_bfloat16* dst) {
    const int mid = blockIdx.y;
    const float* W = wp.p[mid];
    __nv_bfloat16* hi = dst + (size_t)mid * 131072;
    __nv_bfloat16* lo = hi + 65536;
    int idx0 = blockIdx.x * 1024 + threadIdx.x;
    #pragma unroll
    for (int i = 0; i < 4; i++) {
        int idx = idx0 + i * 256;
        int k = idx >> 8, n = idx & 255;
        float x = W[idx];
        __nv_bfloat16 h = __float2bfloat16(x);
        hi[n * 256 + k] = h;
        lo[n * 256 + k] = __float2bfloat16(x - __bfloat162float(h));
    }
}

__global__ void conv_split(const float* __restrict__ X, __nv_bfloat16* __restrict__ Osp,
                           size_t planeEl) {
    int i = (blockIdx.x * 256 + threadIdx.x) * 4;
    float4 a = *(const float4*)(X + i);
    __nv_bfloat162 h0 = __floats2bfloat162_rn(a.x, a.y);
    __nv_bfloat162 h1 = __floats2bfloat162_rn(a.z, a.w);
    float r0 = a.x - __bfloat162float(__low2bfloat16(h0));
    float r1 = a.y - __bfloat162float(__high2bfloat16(h0));
    float r2 = a.z - __bfloat162float(__low2bfloat16(h1));
    float r3 = a.w - __bfloat162float(__high2bfloat16(h1));
    __nv_bfloat162 l0 = __floats2bfloat162_rn(r0, r1);
    __nv_bfloat162 l1 = __floats2bfloat162_rn(r2, r3);
    *(__nv_bfloat162*)(Osp + i) = h0;
    *(__nv_bfloat162*)(Osp + i + 2) = h1;
    *(__nv_bfloat162*)(Osp + planeEl + i) = l0;
    *(__nv_bfloat162*)(Osp + planeEl + i + 2) = l1;
}

// ---------------------------------------------------------------------------
// GEMM (unchanged from R14)
// ---------------------------------------------------------------------------
#define KC   32
#define ST2  40
#define APL2 (64 * ST2 * 2)
#define BPL2 (256 * ST2 * 2)
#define STG2 (2 * APL2 + 2 * BPL2)
#define GEMM_DYN (2 * STG2)

__device__ __forceinline__ void issue_chunkA(const __nv_bfloat16* __restrict__ Asp,
                                             size_t planeEl, int bm, int kc,
                                             uint32_t aSt, int tid) {
    #pragma unroll
    for (int i = 0; i < 2; i++) {
        int it = tid + i * 256;
        int p = it >> 8, rem = it & 255, r = rem >> 2, k8 = (rem & 3) << 3;
        uint32_t d = aSt + p * APL2 + (uint32_t)(r * ST2 + k8) * 2;
        cp16(d, Asp + p * planeEl + (size_t)(bm + r) * 256 + kc * KC + k8);
    }
}
__device__ __forceinline__ void issue_chunkB(const __nv_bfloat16* __restrict__ Whi,
                                             int kc, uint32_t bSt, int tid) {
    const __nv_bfloat16* Wlo = Whi + 65536;
    #pragma unroll
    for (int i = 0; i < 8; i++) {
        int it = tid + i * 256;
        int p = it >> 10, rem = it & 1023, n = rem >> 2, k8 = (rem & 3) << 3;
        uint32_t d = bSt + p * BPL2 + (uint32_t)(n * ST2 + k8) * 2;
        cp16(d, (p ? Wlo : Whi) + n * 256 + kc * KC + k8);
    }
}

__device__ __forceinline__ void mma_chunk32(
    uint32_t aSt, uint32_t bSt, uint32_t aLM, uint32_t bLM, int wid, float acc[4][4][4])
{
    #pragma unroll
    for (int ks = 0; ks < 2; ks++) {
        uint32_t ah[4][4], al[4][4];
        #pragma unroll
        for (int mf = 0; mf < 4; mf++) {
            ldsm4(ah[mf], aSt + ks * 32 + aLM + (mf * 16) * (ST2 * 2));
            ldsm4(al[mf], aSt + APL2 + ks * 32 + aLM + (mf * 16) * (ST2 * 2));
        }
        #pragma unroll
        for (int nb = 0; nb < 2; nb++) {
            uint32_t bh[4], bl[4];
            ldsm4(bh, bSt + ks * 32 + bLM + (wid * 32 + nb * 16) * (ST2 * 2));
            ldsm4(bl, bSt + BPL2 + ks * 32 + bLM + (wid * 32 + nb * 16) * (ST2 * 2));
            #pragma unroll
            for (int mf = 0; mf < 4; mf++) {
                mma16816(acc[mf][2*nb],   ah[mf][0], ah[mf][1], ah[mf][2], ah[mf][3], bh[0], bh[1]);
                mma16816(acc[mf][2*nb],   ah[mf][0], ah[mf][1], ah[mf][2], ah[mf][3], bl[0], bl[1]);
                mma16816(acc[mf][2*nb],   al[mf][0], al[mf][1], al[mf][2], al[mf][3], bh[0], bh[1]);
                mma16816(acc[mf][2*nb+1], ah[mf][0], ah[mf][1], ah[mf][2], ah[mf][3], bh[2], bh[3]);
                mma16816(acc[mf][2*nb+1], ah[mf][0], ah[mf][1], ah[mf][2], ah[mf][3], bl[2], bl[3]);
                mma16816(acc[mf][2*nb+1], al[mf][0], al[mf][1], al[mf][2], al[mf][3], bh[2], bh[3]);
            }
        }
    }
}

__device__ __forceinline__ void split_store(__nv_bfloat16* Cr, size_t planeEl,
                                            int c, float v0, float v1) {
    __nv_bfloat162 hp = __floats2bfloat162_rn(v0, v1);
    float r0 = v0 - __bfloat162float(__low2bfloat16(hp));
    float r1 = v1 - __bfloat162float(__high2bfloat16(hp));
    __nv_bfloat162 lp = __floats2bfloat162_rn(r0, r1);
    *(__nv_bfloat162*)(Cr + c) = hp;
    *(__nv_bfloat162*)(Cr + planeEl + c) = lp;
}

__global__ __launch_bounds__(256, 2) void gemm_tc(
    const __nv_bfloat16* __restrict__ Asp, const __nv_bfloat16* __restrict__ Wsp,
    const float* __restrict__ bias,
    const __nv_bfloat16* __restrict__ residSp, const float* __restrict__ residF,
    const float* __restrict__ lng, const float* __restrict__ lnb,
    __nv_bfloat16* __restrict__ OutSp, float* __restrict__ OutF,
    size_t planeEl, int relu)
{
    extern __shared__ char dsm[];
    __shared__ float s_bias[256], s_g[256], s_b[256];
    __shared__ float s_sum[64], s_ssq[64];

    const int tid = threadIdx.x;
    const int wid = tid >> 5, lane = tid & 31;
    const int lq = lane >> 2, lr = lane & 3;
    const int bm = blockIdx.x * 64;

    const uint32_t base = smem_u32(dsm);
    const uint32_t aLM = ((uint32_t)((lane & 15) * ST2) + ((lane >> 4) << 3)) * 2;
    const uint32_t bLM = ((uint32_t)((((lane >> 4) << 3) + (lane & 7)) * ST2) + (((lane >> 3) & 1) << 3)) * 2;

    issue_chunkA(Asp, planeEl, bm, 0, base, tid);
    issue_chunkB(Wsp, 0, base + 2 * APL2, tid);
    CP_COMMIT();

    s_bias[tid] = bias ? bias[tid] : 0.f;
    if (lng) { s_g[tid] = lng[tid]; s_b[tid] = lnb[tid]; }
    if (tid < 64) { s_sum[tid] = 0.f; s_ssq[tid] = 0.f; }

    float acc[4][4][4];
    #pragma unroll
    for (int mf = 0; mf < 4; mf++)
        #pragma unroll
        for (int nf = 0; nf < 4; nf++)
            #pragma unroll
            for (int j = 0; j < 4; j++) acc[mf][nf][j] = 0.f;

    for (int c = 0; c < 8; c++) {
        if (c < 7) {
            uint32_t st = base + ((c + 1) & 1) * STG2;
            issue_chunkA(Asp, planeEl, bm, c + 1, st, tid);
            issue_chunkB(Wsp, c + 1, st + 2 * APL2, tid);
            CP_COMMIT();
        }
        if (c < 7) CP_WAIT1(); else CP_WAIT0();
        __syncthreads();
        uint32_t st = base + (c & 1) * STG2;
        mma_chunk32(st, st + 2 * APL2, aLM, bLM, wid, acc);
        __syncthreads();
    }

    if (lng) {
        #pragma unroll
        for (int mf = 0; mf < 4; mf++) {
            #pragma unroll
            for (int h = 0; h < 2; h++) {
                int r = mf * 16 + lq + h * 8;
                float ps = 0.f, pq = 0.f;
                #pragma unroll
                for (int nf = 0; nf < 4; nf++) {
                    int c = wid * 32 + nf * 8 + lr * 2;
                    float rv0, rv1;
                    if (residF) {
                        float2 t = *(const float2*)(residF + (size_t)(bm + r) * 256 + c);
                        rv0 = t.x; rv1 = t.y;
                    } else {
                        __nv_bfloat162 h2 = *(const __nv_bfloat162*)(residSp + (size_t)(bm + r) * 256 + c);
                        __nv_bfloat162 l2 = *(const __nv_bfloat162*)(residSp + planeEl + (size_t)(bm + r) * 256 + c);
                        rv0 = __bfloat162float(__low2bfloat16(h2)) + __bfloat162float(__low2bfloat16(l2));
                        rv1 = __bfloat162float(__high2bfloat16(h2)) + __bfloat162float(__high2bfloat16(l2));
                    }
                    float v0 = acc[mf][nf][h * 2 + 0] + s_bias[c] + rv0;
                    float v1 = acc[mf][nf][h * 2 + 1] + s_bias[c + 1] + rv1;
                    acc[mf][nf][h * 2 + 0] = v0;
                    acc[mf][nf][h * 2 + 1] = v1;
                    ps += v0 + v1;
                    pq += v0 * v0 + v1 * v1;
                }
                ps += __shfl_xor_sync(0xffffffffu, ps, 1);
                ps += __shfl_xor_sync(0xffffffffu, ps, 2);
                pq += __shfl_xor_sync(0xffffffffu, pq, 1);
                pq += __shfl_xor_sync(0xffffffffu, pq, 2);
                if (lr == 0) {
                    atomicAdd(&s_sum[r], ps);
                    atomicAdd(&s_ssq[r], pq);
                }
            }
        }
        __syncthreads();
        if (tid < 64) {
            float mu = s_sum[tid] * (1.f / 256.f);
            float var = s_ssq[tid] * (1.f / 256.f) - mu * mu;
            s_sum[tid] = mu;
            s_ssq[tid] = rsqrtf(var + 1e-5f);
        }
        __syncthreads();
        #pragma unroll
        for (int mf = 0; mf < 4; mf++) {
            #pragma unroll
            for (int h = 0; h < 2; h++) {
                int r = mf * 16 + lq + h * 8;
                float mu = s_sum[r], rs = s_ssq[r];
                #pragma unroll
                for (int nf = 0; nf < 4; nf++) {
                    int c = wid * 32 + nf * 8 + lr * 2;
                    float v0 = (acc[mf][nf][h * 2 + 0] - mu) * rs * s_g[c] + s_b[c];
                    float v1 = (acc[mf][nf][h * 2 + 1] - mu) * rs * s_g[c + 1] + s_b[c + 1];
                    if (OutF)
                        *(float2*)(OutF + (size_t)(bm + r) * 256 + c) = make_float2(v0, v1);
                    else
                        split_store(OutSp + (size_t)(bm + r) * 256, planeEl, c, v0, v1);
                }
            }
        }
    } else {
        #pragma unroll
        for (int mf = 0; mf < 4; mf++) {
            #pragma unroll
            for (int h = 0; h < 2; h++) {
                int r = mf * 16 + lq + h * 8;
                #pragma unroll
                for (int nf = 0; nf < 4; nf++) {
                    int c = wid * 32 + nf * 8 + lr * 2;
                    float v0 = acc[mf][nf][h * 2 + 0] + s_bias[c];
                    float v1 = acc[mf][nf][h * 2 + 1] + s_bias[c + 1];
                    if (relu) { v0 = fmaxf(v0, 0.f); v1 = fmaxf(v1, 0.f); }
                    split_store(OutSp + (size_t)(bm + r) * 256, planeEl, c, v0, v1);
                }
            }
        }
    }
}

// ---------------------------------------------------------------------------
// Fused QKV (unchanged from R14)
// ---------------------------------------------------------------------------
__global__ __launch_bounds__(256, 2) void qkv_tc(
    const __nv_bfloat16* __restrict__ Asp,
    const __nv_bfloat16* __restrict__ Wq_, const __nv_bfloat16* __restrict__ Wk_,
    const __nv_bfloat16* __restrict__ Wv_,
    __nv_bfloat16* __restrict__ Qs, __nv_bfloat16* __restrict__ Ks,
    __half* __restrict__ Vs, size_t planeEl)
{
    extern __shared__ char dsm[];
    const int tid = threadIdx.x;
    const int wid = tid >> 5, lane = tid & 31;
    const int lq = lane >> 2, lr = lane & 3;
    const int bm = blockIdx.x * 64;

    const uint32_t base = smem_u32(dsm);
    const uint32_t aLM = ((uint32_t)((lane & 15) * ST2) + ((lane >> 4) << 3)) * 2;
    const uint32_t bLM = ((uint32_t)((((lane >> 4) << 3) + (lane & 7)) * ST2) + (((lane >> 3) & 1) << 3)) * 2;

    const __nv_bfloat16* Ws[3] = {Wq_, Wk_, Wv_};

    issue_chunkA(Asp, planeEl, bm, 0, base, tid);
    issue_chunkB(Ws[0], 0, base + 2 * APL2, tid);
    CP_COMMIT();

    float acc[4][4][4];

    for (int c = 0; c < 24; c++) {
        if (c + 1 < 24) {
            uint32_t st = base + ((c + 1) & 1) * STG2;
            issue_chunkA(Asp, planeEl, bm, (c + 1) & 7, st, tid);
            issue_chunkB(Ws[(c + 1) >> 3], (c + 1) & 7, st + 2 * APL2, tid);
            CP_COMMIT();
        }
        if (c + 1 < 24) CP_WAIT1(); else CP_WAIT0();
        __syncthreads();
        if ((c & 7) == 0) {
            #pragma unroll
            for (int mf = 0; mf < 4; mf++)
                #pragma unroll
                for (int nf = 0; nf < 4; nf++)
                    #pragma unroll
                    for (int j = 0; j < 4; j++) acc[mf][nf][j] = 0.f;
        }
        uint32_t st = base + (c & 1) * STG2;
        mma_chunk32(st, st + 2 * APL2, aLM, bLM, wid, acc);
        __syncthreads();

        if ((c & 7) == 7) {
            int m = c >> 3;
            if (m < 2) {
                float scale = (m == 0) ? 0.125f * 1.44269504f : 1.0f;
                __nv_bfloat16* Out = (m == 0) ? Qs : Ks;
                #pragma unroll
                for (int mf = 0; mf < 4; mf++)
                    #pragma unroll
                    for (int h = 0; h < 2; h++) {
                        int r = mf * 16 + lq + h * 8;
                        #pragma unroll
                        for (int nf = 0; nf < 4; nf++) {
                            int cc = wid * 32 + nf * 8 + lr * 2;
                            split_store(Out + (size_t)(bm + r) * 256, planeEl, cc,
                                        acc[mf][nf][h * 2 + 0] * scale,
                                        acc[mf][nf][h * 2 + 1] * scale);
                        }
                    }
            } else {
                #pragma unroll
                for (int mf = 0; mf < 4; mf++)
                    #pragma unroll
                    for (int h = 0; h < 2; h++) {
                        int r = mf * 16 + lq + h * 8;
                        __half* Cr = Vs + (size_t)(bm + r) * 256;
                        #pragma unroll
                        for (int nf = 0; nf < 4; nf++) {
                            int cc = wid * 32 + nf * 8 + lr * 2;
                            *(__half2*)(Cr + cc) =
                                __floats2half2_rn(acc[mf][nf][h * 2 + 0],
                                                  acc[mf][nf][h * 2 + 1]);
                        }
                    }
            }
        }
    }
}

// ---------------------------------------------------------------------------
// Flash attention: P kept in registers (C-frag -> A-frag repack), per-warp
// key-half PV accumulation + end reduction.
// ---------------------------------------------------------------------------
#define APAD 72
#define PL1  (64 * APAD * 2)
#define KVST3 (3 * PL1)
#define REDST (64 * 68 * 4)
#define ATTN_DYN (2 * PL1 + 2 * KVST3 + REDST)   // 90112

__device__ __forceinline__ void issue_q(const __nv_bfloat16* Qsp, size_t planeEl,
                                        size_t rowB, int q0, int col0, int S,
                                        uint32_t dst, int tid) {
    #pragma unroll
    for (int i = 0; i < 4; i++) {
        int it = tid + i * 256;
        int p = it >> 9, r = (it >> 3) & 63, c8 = (it & 7) << 3;
        uint32_t d = dst + p * PL1 + (uint32_t)(r * APAD + c8) * 2;
        if (q0 + r < S)
            cp16(d, Qsp + p * planeEl + (rowB + q0 + r) * 256 + col0 + c8);
        else
            sts16z(d);
    }
}
__device__ __forceinline__ void issue_kv3(const __nv_bfloat16* Ksp, const __half* Vsp,
                                          size_t planeEl, size_t rowB, int k0, int col0,
                                          int S, uint32_t stage, int tid) {
    #pragma unroll
    for (int i = 0; i < 6; i++) {
        int it = tid + i * 256;
        int p = it >> 9, r = (it >> 3) & 63, c8 = (it & 7) << 3;
        uint32_t d = stage + p * PL1 + (uint32_t)(r * APAD + c8) * 2;
        if (k0 + r < S) {
            const void* g;
            if (p < 2) g = Ksp + p * planeEl + (rowB + k0 + r) * 256 + col0 + c8;
            else       g = Vsp + (rowB + k0 + r) * 256 + col0 + c8;
            cp16(d, g);
        } else sts16z(d);
    }
}

__global__ __launch_bounds__(256, 2) void attn_tc(
    const __nv_bfloat16* __restrict__ Qsp, const __nv_bfloat16* __restrict__ Ksp,
    const __half* __restrict__ Vsp, size_t plane,
    const float* __restrict__ AW, const int* __restrict__ Kcls,
    __nv_bfloat16* __restrict__ Osp, int S)
{
    extern __shared__ char smraw[];
    __shared__ float tw[6];
    __shared__ float redbuf[2][64];

    const int b = blockIdx.z, h = blockIdx.y, q0 = blockIdx.x * 64;
    const int tid = threadIdx.x, wid = tid >> 5, lane = tid & 31;
    const int lq = lane >> 2, lr = lane & 3;
    const int wm = wid >> 1, wn = wid & 1;
    const int Kc = *Kcls;
    const unsigned KcU = (unsigned)Kc;
    const int NK = S - 1;
    const size_t rowB = (size_t)b * S;
    const int col0 = h * 64;

    const uint32_t sQB  = smem_u32(smraw);
    const uint32_t sKVB = sQB + 2 * PL1;
    const uint32_t sRED = sKVB + 2 * KVST3;
    const uint32_t aLM = ((uint32_t)((lane & 15) * APAD) + ((lane >> 4) << 3)) * 2;
    const uint32_t bLM = ((uint32_t)((((lane >> 4) << 3) + (lane & 7)) * APAD) + (((lane >> 3) & 1) << 3)) * 2;
    const uint32_t vLM = ((uint32_t)(((((lane >> 3) & 1) << 3) + (lane & 7)) * APAD) + (((lane >> 4) & 1) << 3)) * 2;

    const int SP = (S + 63) >> 6;

    issue_q(Qsp, plane, rowB, q0, col0, S, sQB, tid);
    issue_kv3(Ksp, Vsp, plane, rowB, 0, col0, S, sKVB, tid);
    CP_COMMIT();

    if (tid < 6) tw[tid] = tanhf(AW[h * 6 + tid]);

    const int r0 = wm * 16 + lq, r1 = r0 + 8;
    const int qg0 = q0 + r0, qg1 = q0 + r1;

    float m0 = -1e30f, m1 = -1e30f, sum0 = 0.f, sum1 = 0.f;
    float oacc[8][4];
    #pragma unroll
    for (int j = 0; j < 8; j++)
        #pragma unroll
        for (int e = 0; e < 4; e++) oacc[j][e] = 0.f;

    float gOut0, gIn0, gDiag0, gLast0, gOut1, gIn1, gDiag1, gLast1;
    const int lo0 = (qg0 / Kc) * Kc;
    const int lo1 = (qg1 / Kc) * Kc;

    for (int t = 0; t < SP; t++) {
        int k0 = t * 64;
        if (t + 1 < SP) {
            issue_kv3(Ksp, Vsp, plane, rowB, (t + 1) * 64, col0, S,
                      sKVB + ((t + 1) & 1) * KVST3, tid);
            CP_COMMIT();
        }
        if (t + 1 < SP) CP_WAIT1(); else CP_WAIT0();
        __syncthreads();

        if (t == 0) {
            bool isQ0 = (qg0 == NK), isQ1 = (qg1 == NK);
            gOut0 = isQ0 ? tw[4] : tw[2]; gIn0 = isQ0 ? tw[4] : tw[1];
            gDiag0 = isQ0 ? tw[5] : tw[0]; gLast0 = isQ0 ? tw[5] : tw[3];
            gOut1 = isQ1 ? tw[4] : tw[2]; gIn1 = isQ1 ? tw[4] : tw[1];
            gDiag1 = isQ1 ? tw[5] : tw[0]; gLast1 = isQ1 ? tw[5] : tw[3];
        }

        const uint32_t kvSt = sKVB + (t & 1) * KVST3;

        // ---- scores: fragment-sharing 3-combo ----
        float acc[4][4] = {};
        #pragma unroll
        for (int ks = 0; ks < 4; ks++) {
            uint32_t qh[4], ql[4];
            ldsm4(qh, sQB + (wm * 16) * (APAD * 2) + aLM + ks * 32);
            ldsm4(ql, sQB + PL1 + (wm * 16) * (APAD * 2) + aLM + ks * 32);
            #pragma unroll
            for (int nb = 0; nb < 2; nb++) {
                uint32_t kh[4], kl[4];
                ldsm4(kh, kvSt + (wn * 32 + nb * 16) * (APAD * 2) + bLM + ks * 32);
                ldsm4(kl, kvSt + PL1 + (wn * 32 + nb * 16) * (APAD * 2) + bLM + ks * 32);
                mma16816(acc[2*nb],   qh[0], qh[1], qh[2], qh[3], kh[0], kh[1]);
                mma16816(acc[2*nb],   qh[0], qh[1], qh[2], qh[3], kl[0], kl[1]);
                mma16816(acc[2*nb],   ql[0], ql[1], ql[2], ql[3], kh[0], kh[1]);
                mma16816(acc[2*nb+1], qh[0], qh[1], qh[2], qh[3], kh[2], kh[3]);
                mma16816(acc[2*nb+1], qh[0], qh[1], qh[2], qh[3], kl[2], kl[3]);
                mma16816(acc[2*nb+1], ql[0], ql[1], ql[2], ql[3], kh[2], kh[3]);
            }
        }

        #pragma unroll
        for (int j = 0; j < 4; j++) {
            int c = k0 + wn * 32 + j * 8 + lr * 2;
            if (c >= S)     { acc[j][0] = -1e30f; acc[j][2] = -1e30f; }
            if (c + 1 >= S) { acc[j][1] = -1e30f; acc[j][3] = -1e30f; }
        }

        float mx0 = -1e30f, mx1 = -1e30f;
        #pragma unroll
        for (int j = 0; j < 4; j++) {
            mx0 = fmaxf(mx0, fmaxf(acc[j][0], acc[j][1]));
            mx1 = fmaxf(mx1, fmaxf(acc[j][2], acc[j][3]));
        }
        mx0 = fmaxf(mx0, __shfl_xor_sync(0xffffffffu, mx0, 1));
        mx0 = fmaxf(mx0, __shfl_xor_sync(0xffffffffu, mx0, 2));
        mx1 = fmaxf(mx1, __shfl_xor_sync(0xffffffffu, mx1, 1));
        mx1 = fmaxf(mx1, __shfl_xor_sync(0xffffffffu, mx1, 2));
        if (lr == 0) { redbuf[wn][r0] = mx0; redbuf[wn][r1] = mx1; }
        __syncthreads();
        float mn0 = fmaxf(m0, fmaxf(redbuf[0][r0], redbuf[1][r0]));
        float mn1 = fmaxf(m1, fmaxf(redbuf[0][r1], redbuf[1][r1]));
        float sc0 = exp2f(m0 - mn0), sc1 = exp2f(m1 - mn1);
        m0 = mn0; m1 = mn1;
        sum0 *= sc0; sum1 *= sc1;
        #pragma unroll
        for (int j = 0; j < 8; j++) {
            oacc[j][0] *= sc0; oacc[j][1] *= sc0;
            oacc[j][2] *= sc1; oacc[j][3] *= sc1;
        }

        // ---- exp + gate -> P fragments in REGISTERS ----
        uint32_t pf[2][4];
        #pragma unroll
        for (int j = 0; j < 4; j++) {
            int c = k0 + wn * 32 + j * 8 + lr * 2;
            __half2 e0 = h2exp2(__floats2half2_rn(acc[j][0] - mn0, acc[j][1] - mn0));
            __half2 e1 = h2exp2(__floats2half2_rn(acc[j][2] - mn1, acc[j][3] - mn1));
            float2 f0 = __half22float2(e0), f1 = __half22float2(e1);
            sum0 += f0.x + f0.y;
            sum1 += f1.x + f1.y;
            float ga = ((unsigned)(c - lo0) < KcU) ? gIn0 : gOut0;
            float gb = ((unsigned)(c + 1 - lo0) < KcU) ? gIn0 : gOut0;
            if (c == qg0) ga = gDiag0;
            if (c + 1 == qg0) gb = gDiag0;
            if (c == NK) ga = gLast0;
            if (c + 1 == NK) gb = gLast0;
            float gc = ((unsigned)(c - lo1) < KcU) ? gIn1 : gOut1;
            float gd = ((unsigned)(c + 1 - lo1) < KcU) ? gIn1 : gOut1;
            if (c == qg1) gc = gDiag1;
            if (c + 1 == qg1) gd = gDiag1;
            if (c == NK) gc = gLast1;
            if (c + 1 == NK) gd = gLast1;
            __half2 p0 = __hmul2(e0, __floats2half2_rn(ga, gb));
            __half2 p1 = __hmul2(e1, __floats2half2_rn(gc, gd));
            pf[j >> 1][(j & 1) * 2 + 0] = *(uint32_t*)&p0;
            pf[j >> 1][(j & 1) * 2 + 1] = *(uint32_t*)&p1;
        }

        // ---- P @ V: this warp's 32 keys, all 64 d-cols ----
        #pragma unroll
        for (int ksP = 0; ksP < 2; ksP++) {
            #pragma unroll
            for (int nf = 0; nf < 4; nf++) {
                uint32_t bf4[4];
                ldsm4t(bf4, kvSt + 2 * PL1 + vLM + (nf * 16) * 2 +
                             (wn * 32 + ksP * 16) * (APAD * 2));
                mma16816h(oacc[2*nf],   pf[ksP][0], pf[ksP][1], pf[ksP][2], pf[ksP][3],
                          bf4[0], bf4[1]);
                mma16816h(oacc[2*nf+1], pf[ksP][0], pf[ksP][1], pf[ksP][2], pf[ksP][3],
                          bf4[2], bf4[3]);
            }
        }
    }

    // final: sums + cross-warp (wn) PV reduction share the same syncs
    sum0 += __shfl_xor_sync(0xffffffffu, sum0, 1);
    sum0 += __shfl_xor_sync(0xffffffffu, sum0, 2);
    sum1 += __shfl_xor_sync(0xffffffffu, sum1, 1);
    sum1 += __shfl_xor_sync(0xffffffffu, sum1, 2);
    __syncthreads();
    float* red = (float*)(smraw + (sRED - sQB));
    if (lr == 0) { redbuf[wn][r0] = sum0; redbuf[wn][r1] = sum1; }
    if (wn == 1) {
        #pragma unroll
        for (int m = 0; m < 8; m++) {
            int d = (m >> 1) * 16 + (m & 1) * 8 + lr * 2;
            *(float2*)(red + r0 * 68 + d) = make_float2(oacc[m][0], oacc[m][1]);
            *(float2*)(red + r1 * 68 + d) = make_float2(oacc[m][2], oacc[m][3]);
        }
    }
    __syncthreads();
    if (wn == 0) {
        float inv0 = 1.f / (redbuf[0][r0] + redbuf[1][r0]);
        float inv1 = 1.f / (redbuf[0][r1] + redbuf[1][r1]);
        #pragma unroll
        for (int m = 0; m < 8; m++) {
            int d = (m >> 1) * 16 + (m & 1) * 8 + lr * 2;
            float2 t0 = *(float2*)(red + r0 * 68 + d);
            float2 t1 = *(float2*)(red + r1 * 68 + d);
            float v0 = (oacc[m][0] + t0.x) * inv0;
            float v1 = (oacc[m][1] + t0.y) * inv0;
            float v2 = (oacc[m][2] + t1.x) * inv1;
            float v3 = (oacc[m][3] + t1.y) * inv1;
            if (qg0 < S) split_store(Osp + (rowB + qg0) * 256, plane, col0 + d, v0, v1);
            if (qg1 < S) split_store(Osp + (rowB + qg1) * 256, plane, col0 + d, v2, v3);
        }
    }
}

// ---------------------------------------------------------------------------
extern "C" void kernel_launch(void* const* d_in, const int* in_sizes, int n_in,
                              void* d_out, int out_size) {
    const float* samples  = (const float*)d_in[0];
    const float* Wq       = (const float*)d_in[1];
    const float* Wk       = (const float*)d_in[2];
    const float* Wv       = (const float*)d_in[3];
    const float* attn_w   = (const float*)d_in[4];
    const float* mha_fc_w = (const float*)d_in[5];
    const float* mha_fc_b = (const float*)d_in[6];
    const float* mha_ln_g = (const float*)d_in[7];
    const float* mha_ln_b = (const float*)d_in[8];
    const float* d_fc1_w  = (const float*)d_in[9];
    const float* d_fc1_b  = (const float*)d_in[10];
    const float* d_fc2_w  = (const float*)d_in[11];
    const float* d_fc2_b  = (const float*)d_in[12];
    const float* d_ln_g   = (const float*)d_in[13];
    const float* d_ln_b   = (const float*)d_in[14];
    const float* out_fc_w = (const float*)d_in[15];
    const float* out_fc_b = (const float*)d_in[16];
    const float* out_ln_g = (const float*)d_in[17];
    const float* out_ln_b = (const float*)d_in[18];
    const int*   Kptr     = (const int*)d_in[20];

    const int S = in_sizes[0] / (BATCH * DMODEL);
    const int M = BATCH * S;
    const size_t plane = (size_t)M * 256;

    float* base = nullptr;
    cudaGetSymbolAddress((void**)&base, g_scratch);
    __nv_bfloat16* xsp = (__nv_bfloat16*)(base + 0 * CHUNK);
    __nv_bfloat16* qsp = (__nv_bfloat16*)(base + 1 * CHUNK);
    __nv_bfloat16* ksp = (__nv_bfloat16*)(base + 2 * CHUNK);
    __half*        vsp = (__half*)(base + 3 * CHUNK);
    __nv_bfloat16* aosp = (__nv_bfloat16*)(base + 4 * CHUNK);

    __nv_bfloat16* wsp = nullptr;
    cudaGetSymbolAddress((void**)&wsp, g_wsplit);

    cudaFuncSetAttribute(attn_tc, cudaFuncAttributeMaxDynamicSharedMemorySize, ATTN_DYN);
    cudaFuncSetAttribute(gemm_tc, cudaFuncAttributeMaxDynamicSharedMemorySize, GEMM_DYN);
    cudaFuncSetAttribute(qkv_tc, cudaFuncAttributeMaxDynamicSharedMemorySize, GEMM_DYN);

    WP wp;
    wp.p[0] = Wq;        wp.p[1] = Wq + 65536;
    wp.p[2] = Wk;        wp.p[3] = Wk + 65536;
    wp.p[4] = Wv;        wp.p[5] = Wv + 65536;
    wp.p[6] = mha_fc_w;  wp.p[7] = mha_fc_w + 65536;
    wp.p[8] = d_fc1_w;   wp.p[9] = d_fc1_w + 65536;
    wp.p[10] = d_fc2_w;  wp.p[11] = d_fc2_w + 65536;
    wp.p[12] = out_fc_w;
    prep_w<<<dim3(64, 13), 256>>>(wp, wsp);
    conv_split<<<M / 4, 256>>>(samples, xsp, plane);

    dim3 ga((S + 63) / 64, NHEAD, BATCH);
    const int GR = (M + 63) / 64;

    for (int l = 0; l < 2; l++) {
        qkv_tc<<<GR, 256, GEMM_DYN>>>(xsp,
                                      wsp + (size_t)(0 + l) * 131072,
                                      wsp + (size_t)(2 + l) * 131072,
                                      wsp + (size_t)(4 + l) * 131072,
                                      qsp, ksp, vsp, plane);
        attn_tc<<<ga, 256, ATTN_DYN>>>(qsp, ksp, vsp, plane,
                                       attn_w + l * 24, Kptr, aosp, S);
        gemm_tc<<<GR, 256, GEMM_DYN>>>(aosp, wsp + (size_t)(6 + l) * 131072,
                                       mha_fc_b + l * 256, xsp, nullptr,
                                       mha_ln_g + l * 256, mha_ln_b + l * 256,
                                       xsp, nullptr, plane, 0);
        gemm_tc<<<GR, 256, GEMM_DYN>>>(xsp, wsp + (size_t)(8 + l) * 131072,
                                       d_fc1_b + l * 256, nullptr, nullptr,
                                       nullptr, nullptr, qsp, nullptr, plane, 1);
        gemm_tc<<<GR, 256, GEMM_DYN>>>(qsp, wsp + (size_t)(10 + l) * 131072,
                                       d_fc2_b + l * 256, xsp, nullptr,
                                       d_ln_g + l * 256, d_ln_b + l * 256,
                                       xsp, nullptr, plane, 0);
    }
    gemm_tc<<<GR, 256, GEMM_DYN>>>(xsp, wsp + (size_t)12 * 131072,
                                   out_fc_b, nullptr, samples,
                                   out_ln_g, out_ln_b,
                                   nullptr, (float*)d_out, plane, 0);
}

// round 17
// speedup vs baseline: 3.6817x; 1.0484x over previous
#include <cuda_runtime.h>
#include <cuda_bf16.h>
#include <cuda_fp16.h>
#include <math.h>
#include <stdint.h>

#define DMODEL 256
#define BATCH  128
#define NHEAD  4
#define DK     64

#define CHUNK (128ull * 512ull * 256ull)
__device__ float g_scratch[5ull * CHUNK];
__device__ __nv_bfloat16 g_wsplit[13ull * 131072ull];

// ---------------------------------------------------------------------------
__device__ __forceinline__ uint32_t smem_u32(const void* p) {
    uint32_t a;
    asm("{ .reg .u64 t; cvta.to.shared.u64 t, %1; cvt.u32.u64 %0, t; }" : "=r"(a) : "l"(p));
    return a;
}
__device__ __forceinline__ void mma16816(float* c,
                                         uint32_t a0, uint32_t a1, uint32_t a2, uint32_t a3,
                                         uint32_t b0, uint32_t b1) {
    asm volatile(
        "mma.sync.aligned.m16n8k16.row.col.f32.bf16.bf16.f32 "
        "{%0,%1,%2,%3},{%4,%5,%6,%7},{%8,%9},{%0,%1,%2,%3};"
        : "+f"(c[0]), "+f"(c[1]), "+f"(c[2]), "+f"(c[3])
        : "r"(a0), "r"(a1), "r"(a2), "r"(a3), "r"(b0), "r"(b1));
}
__device__ __forceinline__ void mma16816h(float* c,
                                          uint32_t a0, uint32_t a1, uint32_t a2, uint32_t a3,
                                          uint32_t b0, uint32_t b1) {
    asm volatile(
        "mma.sync.aligned.m16n8k16.row.col.f32.f16.f16.f32 "
        "{%0,%1,%2,%3},{%4,%5,%6,%7},{%8,%9},{%0,%1,%2,%3};"
        : "+f"(c[0]), "+f"(c[1]), "+f"(c[2]), "+f"(c[3])
        : "r"(a0), "r"(a1), "r"(a2), "r"(a3), "r"(b0), "r"(b1));
}
__device__ __forceinline__ void ldsm4(uint32_t* r, uint32_t a) {
    asm volatile("ldmatrix.sync.aligned.m8n8.x4.shared.b16 {%0,%1,%2,%3}, [%4];"
        : "=r"(r[0]), "=r"(r[1]), "=r"(r[2]), "=r"(r[3]) : "r"(a));
}
__device__ __forceinline__ void ldsm4t(uint32_t* r, uint32_t a) {
    asm volatile("ldmatrix.sync.aligned.m8n8.x4.trans.shared.b16 {%0,%1,%2,%3}, [%4];"
        : "=r"(r[0]), "=r"(r[1]), "=r"(r[2]), "=r"(r[3]) : "r"(a));
}
__device__ __forceinline__ void cp16(uint32_t saddr, const void* g) {
    asm volatile("cp.async.cg.shared.global [%0], [%1], 16;" :: "r"(saddr), "l"(g));
}
__device__ __forceinline__ void sts16z(uint32_t a) {
    asm volatile("st.shared.v4.u32 [%0], {%1,%1,%1,%1};" :: "r"(a), "r"(0u));
}
#define CP_COMMIT() asm volatile("cp.async.commit_group;" ::: "memory")
#define CP_WAIT0()  asm volatile("cp.async.wait_group 0;" ::: "memory")

// ---------------------------------------------------------------------------
struct WP { const float* p[13]; };

__global__ void prep_w(WP wp, __nv_bfloat16* dst) {
    const int mid = blockIdx.y;
    const float* W = wp.p[mid];
    __nv_bfloat16* hi = dst + (size_t)mid * 131072;
    __nv_bfloat16* lo = hi + 65536;
    int idx0 = blockIdx.x * 1024 + threadIdx.x;
    #pragma unroll
    for (int i = 0; i < 4; i++) {
        int idx = idx0 + i * 256;
        int k = idx >> 8, n = idx & 255;
        float x = W[idx];
        __nv_bfloat16 h = __float2bfloat16(x);
        hi[n * 256 + k] = h;
        lo[n * 256 + k] = __float2bfloat16(x - __bfloat162float(h));
    }
}

__global__ void conv_split(const float* __restrict__ X, __nv_bfloat16* __restrict__ Osp,
                           size_t planeEl) {
    int i = (blockIdx.x * 256 + threadIdx.x) * 4;
    float4 a = *(const float4*)(X + i);
    __nv_bfloat162 h0 = __floats2bfloat162_rn(a.x, a.y);
    __nv_bfloat162 h1 = __floats2bfloat162_rn(a.z, a.w);
    float r0 = a.x - __bfloat162float(__low2bfloat16(h0));
    float r1 = a.y - __bfloat162float(__high2bfloat16(h0));
    float r2 = a.z - __bfloat162float(__low2bfloat16(h1));
    float r3 = a.w - __bfloat162float(__high2bfloat16(h1));
    __nv_bfloat162 l0 = __floats2bfloat162_rn(r0, r1);
    __nv_bfloat162 l1 = __floats2bfloat162_rn(r2, r3);
    *(__nv_bfloat162*)(Osp + i) = h0;
    *(__nv_bfloat162*)(Osp + i + 2) = h1;
    *(__nv_bfloat162*)(Osp + planeEl + i) = l0;
    *(__nv_bfloat162*)(Osp + planeEl + i + 2) = l1;
}

// ---------------------------------------------------------------------------
// GEMM: single-sync multistage pipeline.
// ---------------------------------------------------------------------------
#define KC   32
#define ST2  40
#define APL2 (64 * ST2 * 2)
#define BPL2 (256 * ST2 * 2)
#define STG2 (2 * APL2 + 2 * BPL2)
#define GEMM_DYN (2 * STG2)

__device__ __forceinline__ void issue_chunkA(const __nv_bfloat16* __restrict__ Asp,
                                             size_t planeEl, int bm, int kc,
                                             uint32_t aSt, int tid) {
    #pragma unroll
    for (int i = 0; i < 2; i++) {
        int it = tid + i * 256;
        int p = it >> 8, rem = it & 255, r = rem >> 2, k8 = (rem & 3) << 3;
        uint32_t d = aSt + p * APL2 + (uint32_t)(r * ST2 + k8) * 2;
        cp16(d, Asp + p * planeEl + (size_t)(bm + r) * 256 + kc * KC + k8);
    }
}
__device__ __forceinline__ void issue_chunkB(const __nv_bfloat16* __restrict__ Whi,
                                             int kc, uint32_t bSt, int tid) {
    const __nv_bfloat16* Wlo = Whi + 65536;
    #pragma unroll
    for (int i = 0; i < 8; i++) {
        int it = tid + i * 256;
        int p = it >> 10, rem = it & 1023, n = rem >> 2, k8 = (rem & 3) << 3;
        uint32_t d = bSt + p * BPL2 + (uint32_t)(n * ST2 + k8) * 2;
        cp16(d, (p ? Wlo : Whi) + n * 256 + kc * KC + k8);
    }
}

__device__ __forceinline__ void mma_chunk32(
    uint32_t aSt, uint32_t bSt, uint32_t aLM, uint32_t bLM, int wid, float acc[4][4][4])
{
    #pragma unroll
    for (int ks = 0; ks < 2; ks++) {
        uint32_t ah[4][4], al[4][4];
        #pragma unroll
        for (int mf = 0; mf < 4; mf++) {
            ldsm4(ah[mf], aSt + ks * 32 + aLM + (mf * 16) * (ST2 * 2));
            ldsm4(al[mf], aSt + APL2 + ks * 32 + aLM + (mf * 16) * (ST2 * 2));
        }
        #pragma unroll
        for (int nb = 0; nb < 2; nb++) {
            uint32_t bh[4], bl[4];
            ldsm4(bh, bSt + ks * 32 + bLM + (wid * 32 + nb * 16) * (ST2 * 2));
            ldsm4(bl, bSt + BPL2 + ks * 32 + bLM + (wid * 32 + nb * 16) * (ST2 * 2));
            #pragma unroll
            for (int mf = 0; mf < 4; mf++) {
                mma16816(acc[mf][2*nb],   ah[mf][0], ah[mf][1], ah[mf][2], ah[mf][3], bh[0], bh[1]);
                mma16816(acc[mf][2*nb],   ah[mf][0], ah[mf][1], ah[mf][2], ah[mf][3], bl[0], bl[1]);
                mma16816(acc[mf][2*nb],   al[mf][0], al[mf][1], al[mf][2], al[mf][3], bh[0], bh[1]);
                mma16816(acc[mf][2*nb+1], ah[mf][0], ah[mf][1], ah[mf][2], ah[mf][3], bh[2], bh[3]);
                mma16816(acc[mf][2*nb+1], ah[mf][0], ah[mf][1], ah[mf][2], ah[mf][3], bl[2], bl[3]);
                mma16816(acc[mf][2*nb+1], al[mf][0], al[mf][1], al[mf][2], al[mf][3], bh[2], bh[3]);
            }
        }
    }
}

__device__ __forceinline__ void split_store(__nv_bfloat16* Cr, size_t planeEl,
                                            int c, float v0, float v1) {
    __nv_bfloat162 hp = __floats2bfloat162_rn(v0, v1);
    float r0 = v0 - __bfloat162float(__low2bfloat16(hp));
    float r1 = v1 - __bfloat162float(__high2bfloat16(hp));
    __nv_bfloat162 lp = __floats2bfloat162_rn(r0, r1);
    *(__nv_bfloat162*)(Cr + c) = hp;
    *(__nv_bfloat162*)(Cr + planeEl + c) = lp;
}

__global__ __launch_bounds__(256, 2) void gemm_tc(
    const __nv_bfloat16* __restrict__ Asp, const __nv_bfloat16* __restrict__ Wsp,
    const float* __restrict__ bias,
    const __nv_bfloat16* __restrict__ residSp, const float* __restrict__ residF,
    const float* __restrict__ lng, const float* __restrict__ lnb,
    __nv_bfloat16* __restrict__ OutSp, float* __restrict__ OutF,
    size_t planeEl, int relu)
{
    extern __shared__ char dsm[];
    __shared__ float s_bias[256], s_g[256], s_b[256];
    __shared__ float s_part[2][8][64];
    __shared__ float s_sum[64], s_ssq[64];

    const int tid = threadIdx.x;
    const int wid = tid >> 5, lane = tid & 31;
    const int lq = lane >> 2, lr = lane & 3;
    const int bm = blockIdx.x * 64;

    const uint32_t base = smem_u32(dsm);
    const uint32_t aLM = ((uint32_t)((lane & 15) * ST2) + ((lane >> 4) << 3)) * 2;
    const uint32_t bLM = ((uint32_t)((((lane >> 4) << 3) + (lane & 7)) * ST2) + (((lane >> 3) & 1) << 3)) * 2;

    issue_chunkA(Asp, planeEl, bm, 0, base, tid);
    issue_chunkB(Wsp, 0, base + 2 * APL2, tid);
    CP_COMMIT();

    s_bias[tid] = bias ? bias[tid] : 0.f;
    if (lng) { s_g[tid] = lng[tid]; s_b[tid] = lnb[tid]; }

    float acc[4][4][4];
    #pragma unroll
    for (int mf = 0; mf < 4; mf++)
        #pragma unroll
        for (int nf = 0; nf < 4; nf++)
            #pragma unroll
            for (int j = 0; j < 4; j++) acc[mf][nf][j] = 0.f;

    for (int c = 0; c < 8; c++) {
        CP_WAIT0();
        __syncthreads();
        if (c < 7) {
            uint32_t st = base + ((c + 1) & 1) * STG2;
            issue_chunkA(Asp, planeEl, bm, c + 1, st, tid);
            issue_chunkB(Wsp, c + 1, st + 2 * APL2, tid);
            CP_COMMIT();
        }
        uint32_t st = base + (c & 1) * STG2;
        mma_chunk32(st, st + 2 * APL2, aLM, bLM, wid, acc);
    }
    __syncthreads();

    if (lng) {
        #pragma unroll
        for (int mf = 0; mf < 4; mf++) {
            #pragma unroll
            for (int h = 0; h < 2; h++) {
                int r = mf * 16 + lq + h * 8;
                float ps = 0.f, pq = 0.f;
                #pragma unroll
                for (int nf = 0; nf < 4; nf++) {
                    int c = wid * 32 + nf * 8 + lr * 2;
                    float rv0, rv1;
                    if (residF) {
                        float2 t = *(const float2*)(residF + (size_t)(bm + r) * 256 + c);
                        rv0 = t.x; rv1 = t.y;
                    } else {
                        __nv_bfloat162 h2 = *(const __nv_bfloat162*)(residSp + (size_t)(bm + r) * 256 + c);
                        __nv_bfloat162 l2 = *(const __nv_bfloat162*)(residSp + planeEl + (size_t)(bm + r) * 256 + c);
                        rv0 = __bfloat162float(__low2bfloat16(h2)) + __bfloat162float(__low2bfloat16(l2));
                        rv1 = __bfloat162float(__high2bfloat16(h2)) + __bfloat162float(__high2bfloat16(l2));
                    }
                    float v0 = acc[mf][nf][h * 2 + 0] + s_bias[c] + rv0;
                    float v1 = acc[mf][nf][h * 2 + 1] + s_bias[c + 1] + rv1;
                    acc[mf][nf][h * 2 + 0] = v0;
                    acc[mf][nf][h * 2 + 1] = v1;
                    ps += v0 + v1;
                    pq += v0 * v0 + v1 * v1;
                }
                ps += __shfl_xor_sync(0xffffffffu, ps, 1);
                ps += __shfl_xor_sync(0xffffffffu, ps, 2);
                pq += __shfl_xor_sync(0xffffffffu, pq, 1);
                pq += __shfl_xor_sync(0xffffffffu, pq, 2);
                if (lr == 0) { s_part[0][wid][r] = ps; s_part[1][wid][r] = pq; }
            }
        }
        __syncthreads();
        if (tid < 64) {
            float ts = 0.f, tq = 0.f;
            #pragma unroll
            for (int w = 0; w < 8; w++) { ts += s_part[0][w][tid]; tq += s_part[1][w][tid]; }
            float mu = ts * (1.f / 256.f);
            float var = tq * (1.f / 256.f) - mu * mu;
            s_sum[tid] = mu;
            s_ssq[tid] = rsqrtf(var + 1e-5f);
        }
        __syncthreads();
        #pragma unroll
        for (int mf = 0; mf < 4; mf++) {
            #pragma unroll
            for (int h = 0; h < 2; h++) {
                int r = mf * 16 + lq + h * 8;
                float mu = s_sum[r], rs = s_ssq[r];
                #pragma unroll
                for (int nf = 0; nf < 4; nf++) {
                    int c = wid * 32 + nf * 8 + lr * 2;
                    float v0 = (acc[mf][nf][h * 2 + 0] - mu) * rs * s_g[c] + s_b[c];
                    float v1 = (acc[mf][nf][h * 2 + 1] - mu) * rs * s_g[c + 1] + s_b[c + 1];
                    if (OutF)
                        *(float2*)(OutF + (size_t)(bm + r) * 256 + c) = make_float2(v0, v1);
                    else
                        split_store(OutSp + (size_t)(bm + r) * 256, planeEl, c, v0, v1);
                }
            }
        }
    } else {
        #pragma unroll
        for (int mf = 0; mf < 4; mf++) {
            #pragma unroll
            for (int h = 0; h < 2; h++) {
                int r = mf * 16 + lq + h * 8;
                #pragma unroll
                for (int nf = 0; nf < 4; nf++) {
                    int c = wid * 32 + nf * 8 + lr * 2;
                    float v0 = acc[mf][nf][h * 2 + 0] + s_bias[c];
                    float v1 = acc[mf][nf][h * 2 + 1] + s_bias[c + 1];
                    if (relu) { v0 = fmaxf(v0, 0.f); v1 = fmaxf(v1, 0.f); }
                    split_store(OutSp + (size_t)(bm + r) * 256, planeEl, c, v0, v1);
                }
            }
        }
    }
}

// ---------------------------------------------------------------------------
// Fused QKV, single-sync pipeline.
// ---------------------------------------------------------------------------
__global__ __launch_bounds__(256, 2) void qkv_tc(
    const __nv_bfloat16* __restrict__ Asp,
    const __nv_bfloat16* __restrict__ Wq_, const __nv_bfloat16* __restrict__ Wk_,
    const __nv_bfloat16* __restrict__ Wv_,
    __nv_bfloat16* __restrict__ Qs, __nv_bfloat16* __restrict__ Ks,
    __half* __restrict__ Vs, size_t planeEl)
{
    extern __shared__ char dsm[];
    const int tid = threadIdx.x;
    const int wid = tid >> 5, lane = tid & 31;
    const int lq = lane >> 2, lr = lane & 3;
    const int bm = blockIdx.x * 64;

    const uint32_t base = smem_u32(dsm);
    const uint32_t aLM = ((uint32_t)((lane & 15) * ST2) + ((lane >> 4) << 3)) * 2;
    const uint32_t bLM = ((uint32_t)((((lane >> 4) << 3) + (lane & 7)) * ST2) + (((lane >> 3) & 1) << 3)) * 2;

    const __nv_bfloat16* Ws[3] = {Wq_, Wk_, Wv_};

    issue_chunkA(Asp, planeEl, bm, 0, base, tid);
    issue_chunkB(Ws[0], 0, base + 2 * APL2, tid);
    CP_COMMIT();

    float acc[4][4][4];

    for (int c = 0; c < 24; c++) {
        CP_WAIT0();
        __syncthreads();
        if (c + 1 < 24) {
            uint32_t st = base + ((c + 1) & 1) * STG2;
            issue_chunkA(Asp, planeEl, bm, (c + 1) & 7, st, tid);
            issue_chunkB(Ws[(c + 1) >> 3], (c + 1) & 7, st + 2 * APL2, tid);
            CP_COMMIT();
        }
        if ((c & 7) == 0) {
            #pragma unroll
            for (int mf = 0; mf < 4; mf++)
                #pragma unroll
                for (int nf = 0; nf < 4; nf++)
                    #pragma unroll
                    for (int j = 0; j < 4; j++) acc[mf][nf][j] = 0.f;
        }
        uint32_t st = base + (c & 1) * STG2;
        mma_chunk32(st, st + 2 * APL2, aLM, bLM, wid, acc);

        if ((c & 7) == 7) {
            int m = c >> 3;
            if (m < 2) {
                float scale = (m == 0) ? 0.125f * 1.44269504f : 1.0f;
                __nv_bfloat16* Out = (m == 0) ? Qs : Ks;
                #pragma unroll
                for (int mf = 0; mf < 4; mf++)
                    #pragma unroll
                    for (int h = 0; h < 2; h++) {
                        int r = mf * 16 + lq + h * 8;
                        #pragma unroll
                        for (int nf = 0; nf < 4; nf++) {
                            int cc = wid * 32 + nf * 8 + lr * 2;
                            split_store(Out + (size_t)(bm + r) * 256, planeEl, cc,
                                        acc[mf][nf][h * 2 + 0] * scale,
                                        acc[mf][nf][h * 2 + 1] * scale);
                        }
                    }
            } else {
                #pragma unroll
                for (int mf = 0; mf < 4; mf++)
                    #pragma unroll
                    for (int h = 0; h < 2; h++) {
                        int r = mf * 16 + lq + h * 8;
                        __half* Cr = Vs + (size_t)(bm + r) * 256;
                        #pragma unroll
                        for (int nf = 0; nf < 4; nf++) {
                            int cc = wid * 32 + nf * 8 + lr * 2;
                            *(__half2*)(Cr + cc) =
                                __floats2half2_rn(acc[mf][nf][h * 2 + 0],
                                                  acc[mf][nf][h * 2 + 1]);
                        }
                    }
            }
        }
    }
}

// ---------------------------------------------------------------------------
// Flash attention: race-free single-sync pipeline, uniform-branch gate fixups.
// ---------------------------------------------------------------------------
#define APAD 72
#define PL1  (64 * APAD * 2)
#define KVST3 (3 * PL1)
#define REDST (64 * 68 * 4)
#define ATTN_DYN (2 * PL1 + 2 * KVST3 + REDST)

__device__ __forceinline__ void issue_q(const __nv_bfloat16* Qsp, size_t planeEl,
                                        size_t rowB, int q0, int col0, int S,
                                        uint32_t dst, int tid) {
    #pragma unroll
    for (int i = 0; i < 4; i++) {
        int it = tid + i * 256;
        int p = it >> 9, r = (it >> 3) & 63, c8 = (it & 7) << 3;
        uint32_t d = dst + p * PL1 + (uint32_t)(r * APAD + c8) * 2;
        if (q0 + r < S)
            cp16(d, Qsp + p * planeEl + (rowB + q0 + r) * 256 + col0 + c8);
        else
            sts16z(d);
    }
}
__device__ __forceinline__ void issue_kv3(const __nv_bfloat16* Ksp, const __half* Vsp,
                                          size_t planeEl, size_t rowB, int k0, int col0,
                                          int S, uint32_t stage, int tid) {
    #pragma unroll
    for (int i = 0; i < 6; i++) {
        int it = tid + i * 256;
        int p = it >> 9, r = (it >> 3) & 63, c8 = (it & 7) << 3;
        uint32_t d = stage + p * PL1 + (uint32_t)(r * APAD + c8) * 2;
        if (k0 + r < S) {
            const void* g;
            if (p < 2) g = Ksp + p * planeEl + (rowB + k0 + r) * 256 + col0 + c8;
            else       g = Vsp + (rowB + k0 + r) * 256 + col0 + c8;
            cp16(d, g);
        } else sts16z(d);
    }
}

__global__ __launch_bounds__(256, 2) void attn_tc(
    const __nv_bfloat16* __restrict__ Qsp, const __nv_bfloat16* __restrict__ Ksp,
    const __half* __restrict__ Vsp, size_t plane,
    const float* __restrict__ AW, const int* __restrict__ Kcls,
    __nv_bfloat16* __restrict__ Osp, int S)
{
    extern __shared__ char smraw[];
    __shared__ float tw[6];
    __shared__ float redbuf[2][64];

    const int b = blockIdx.z, h = blockIdx.y, q0 = blockIdx.x * 64;
    const int tid = threadIdx.x, wid = tid >> 5, lane = tid & 31;
    const int lq = lane >> 2, lr = lane & 3;
    const int wm = wid >> 1, wn = wid & 1;
    const int Kc = *Kcls;
    const unsigned KcU = (unsigned)Kc;
    const int NK = S - 1;
    const size_t rowB = (size_t)b * S;
    const int col0 = h * 64;

    const uint32_t sQB  = smem_u32(smraw);
    const uint32_t sKVB = sQB + 2 * PL1;
    const uint32_t sRED = sKVB + 2 * KVST3;
    const uint32_t aLM = ((uint32_t)((lane & 15) * APAD) + ((lane >> 4) << 3)) * 2;
    const uint32_t bLM = ((uint32_t)((((lane >> 4) << 3) + (lane & 7)) * APAD) + (((lane >> 3) & 1) << 3)) * 2;
    const uint32_t vLM = ((uint32_t)(((((lane >> 3) & 1) << 3) + (lane & 7)) * APAD) + (((lane >> 4) & 1) << 3)) * 2;

    const int SP = (S + 63) >> 6;

    issue_q(Qsp, plane, rowB, q0, col0, S, sQB, tid);
    issue_kv3(Ksp, Vsp, plane, rowB, 0, col0, S, sKVB, tid);
    CP_COMMIT();

    if (tid < 6) tw[tid] = tanhf(AW[h * 6 + tid]);

    const int r0 = wm * 16 + lq, r1 = r0 + 8;
    const int qg0 = q0 + r0, qg1 = q0 + r1;

    float m0 = -1e30f, m1 = -1e30f, sum0 = 0.f, sum1 = 0.f;
    float oacc[8][4];
    #pragma unroll
    for (int j = 0; j < 8; j++)
        #pragma unroll
        for (int e = 0; e < 4; e++) oacc[j][e] = 0.f;

    float gOut0, gIn0, gDiag0, gLast0, gOut1, gIn1, gDiag1, gLast1;
    const int lo0 = (qg0 / Kc) * Kc;
    const int lo1 = (qg1 / Kc) * Kc;

    for (int t = 0; t < SP; t++) {
        int k0 = t * 64;
        CP_WAIT0();
        __syncthreads();
        if (t + 1 < SP) {
            issue_kv3(Ksp, Vsp, plane, rowB, (t + 1) * 64, col0, S,
                      sKVB + ((t + 1) & 1) * KVST3, tid);
            CP_COMMIT();
        }

        if (t == 0) {
            bool isQ0 = (qg0 == NK), isQ1 = (qg1 == NK);
            gOut0 = isQ0 ? tw[4] : tw[2]; gIn0 = isQ0 ? tw[4] : tw[1];
            gDiag0 = isQ0 ? tw[5] : tw[0]; gLast0 = isQ0 ? tw[5] : tw[3];
            gOut1 = isQ1 ? tw[4] : tw[2]; gIn1 = isQ1 ? tw[4] : tw[1];
            gDiag1 = isQ1 ? tw[5] : tw[0]; gLast1 = isQ1 ? tw[5] : tw[3];
        }

        const uint32_t kvSt = sKVB + (t & 1) * KVST3;

        // ---- scores: fragment-sharing 3-combo ----
        float acc[4][4] = {};
        #pragma unroll
        for (int ks = 0; ks < 4; ks++) {
            uint32_t qh[4], ql[4];
            ldsm4(qh, sQB + (wm * 16) * (APAD * 2) + aLM + ks * 32);
            ldsm4(ql, sQB + PL1 + (wm * 16) * (APAD * 2) + aLM + ks * 32);
            #pragma unroll
            for (int nb = 0; nb < 2; nb++) {
                uint32_t kh[4], kl[4];
                ldsm4(kh, kvSt + (wn * 32 + nb * 16) * (APAD * 2) + bLM + ks * 32);
                ldsm4(kl, kvSt + PL1 + (wn * 32 + nb * 16) * (APAD * 2) + bLM + ks * 32);
                mma16816(acc[2*nb],   qh[0], qh[1], qh[2], qh[3], kh[0], kh[1]);
                mma16816(acc[2*nb],   qh[0], qh[1], qh[2], qh[3], kl[0], kl[1]);
                mma16816(acc[2*nb],   ql[0], ql[1], ql[2], ql[3], kh[0], kh[1]);
                mma16816(acc[2*nb+1], qh[0], qh[1], qh[2], qh[3], kh[2], kh[3]);
                mma16816(acc[2*nb+1], qh[0], qh[1], qh[2], qh[3], kl[2], kl[3]);
                mma16816(acc[2*nb+1], ql[0], ql[1], ql[2], ql[3], kh[2], kh[3]);
            }
        }

        const bool lastChunk = (t == SP - 1);
        const bool diagChunk = (t == blockIdx.x);

        if (lastChunk) {
            #pragma unroll
            for (int j = 0; j < 4; j++) {
                int c = k0 + wn * 32 + j * 8 + lr * 2;
                if (c >= S)     { acc[j][0] = -1e30f; acc[j][2] = -1e30f; }
                if (c + 1 >= S) { acc[j][1] = -1e30f; acc[j][3] = -1e30f; }
            }
        }

        float mx0 = -1e30f, mx1 = -1e30f;
        #pragma unroll
        for (int j = 0; j < 4; j++) {
            mx0 = fmaxf(mx0, fmaxf(acc[j][0], acc[j][1]));
            mx1 = fmaxf(mx1, fmaxf(acc[j][2], acc[j][3]));
        }
        mx0 = fmaxf(mx0, __shfl_xor_sync(0xffffffffu, mx0, 1));
        mx0 = fmaxf(mx0, __shfl_xor_sync(0xffffffffu, mx0, 2));
        mx1 = fmaxf(mx1, __shfl_xor_sync(0xffffffffu, mx1, 1));
        mx1 = fmaxf(mx1, __shfl_xor_sync(0xffffffffu, mx1, 2));
        if (lr == 0) { redbuf[wn][r0] = mx0; redbuf[wn][r1] = mx1; }
        __syncthreads();
        float mn0 = fmaxf(m0, fmaxf(redbuf[0][r0], redbuf[1][r0]));
        float mn1 = fmaxf(m1, fmaxf(redbuf[0][r1], redbuf[1][r1]));
        float sc0 = exp2f(m0 - mn0), sc1 = exp2f(m1 - mn1);
        m0 = mn0; m1 = mn1;
        sum0 *= sc0; sum1 *= sc1;
        #pragma unroll
        for (int j = 0; j < 8; j++) {
            oacc[j][0] *= sc0; oacc[j][1] *= sc0;
            oacc[j][2] *= sc1; oacc[j][3] *= sc1;
        }

        // ---- exp + gate -> P fragments in registers ----
        uint32_t pf[2][4];
        #pragma unroll
        for (int j = 0; j < 4; j++) {
            int c = k0 + wn * 32 + j * 8 + lr * 2;
            __half2 e0 = h2exp2(__floats2half2_rn(acc[j][0] - mn0, acc[j][1] - mn0));
            __half2 e1 = h2exp2(__floats2half2_rn(acc[j][2] - mn1, acc[j][3] - mn1));
            float2 f0 = __half22float2(e0), f1 = __half22float2(e1);
            sum0 += f0.x + f0.y;
            sum1 += f1.x + f1.y;
            float ga = ((unsigned)(c - lo0) < KcU) ? gIn0 : gOut0;
            float gb = ((unsigned)(c + 1 - lo0) < KcU) ? gIn0 : gOut0;
            float gc = ((unsigned)(c - lo1) < KcU) ? gIn1 : gOut1;
            float gd = ((unsigned)(c + 1 - lo1) < KcU) ? gIn1 : gOut1;
            if (diagChunk) {
                if (c == qg0) ga = gDiag0;
                if (c + 1 == qg0) gb = gDiag0;
                if (c == qg1) gc = gDiag1;
                if (c + 1 == qg1) gd = gDiag1;
            }
            if (lastChunk) {
                if (c == NK) { ga = gLast0; gc = gLast1; }
                if (c + 1 == NK) { gb = gLast0; gd = gLast1; }
            }
            __half2 p0 = __hmul2(e0, __floats2half2_rn(ga, gb));
            __half2 p1 = __hmul2(e1, __floats2half2_rn(gc, gd));
            pf[j >> 1][(j & 1) * 2 + 0] = *(uint32_t*)&p0;
            pf[j >> 1][(j & 1) * 2 + 1] = *(uint32_t*)&p1;
        }

        // ---- P @ V ----
        #pragma unroll
        for (int ksP = 0; ksP < 2; ksP++) {
            #pragma unroll
            for (int nf = 0; nf < 4; nf++) {
                uint32_t bf4[4];
                ldsm4t(bf4, kvSt + 2 * PL1 + vLM + (nf * 16) * 2 +
                             (wn * 32 + ksP * 16) * (APAD * 2));
                mma16816h(oacc[2*nf],   pf[ksP][0], pf[ksP][1], pf[ksP][2], pf[ksP][3],
                          bf4[0], bf4[1]);
                mma16816h(oacc[2*nf+1], pf[ksP][0], pf[ksP][1], pf[ksP][2], pf[ksP][3],
                          bf4[2], bf4[3]);
            }
        }
    }

    sum0 += __shfl_xor_sync(0xffffffffu, sum0, 1);
    sum0 += __shfl_xor_sync(0xffffffffu, sum0, 2);
    sum1 += __shfl_xor_sync(0xffffffffu, sum1, 1);
    sum1 += __shfl_xor_sync(0xffffffffu, sum1, 2);
    __syncthreads();
    float* red = (float*)(smraw + (sRED - sQB));
    if (lr == 0) { redbuf[wn][r0] = sum0; redbuf[wn][r1] = sum1; }
    if (wn == 1) {
        #pragma unroll
        for (int m = 0; m < 8; m++) {
            int d = (m >> 1) * 16 + (m & 1) * 8 + lr * 2;
            *(float2*)(red + r0 * 68 + d) = make_float2(oacc[m][0], oacc[m][1]);
            *(float2*)(red + r1 * 68 + d) = make_float2(oacc[m][2], oacc[m][3]);
        }
    }
    __syncthreads();
    if (wn == 0) {
        float inv0 = 1.f / (redbuf[0][r0] + redbuf[1][r0]);
        float inv1 = 1.f / (redbuf[0][r1] + redbuf[1][r1]);
        #pragma unroll
        for (int m = 0; m < 8; m++) {
            int d = (m >> 1) * 16 + (m & 1) * 8 + lr * 2;
            float2 t0 = *(float2*)(red + r0 * 68 + d);
            float2 t1 = *(float2*)(red + r1 * 68 + d);
            float v0 = (oacc[m][0] + t0.x) * inv0;
            float v1 = (oacc[m][1] + t0.y) * inv0;
            float v2 = (oacc[m][2] + t1.x) * inv1;
            float v3 = (oacc[m][3] + t1.y) * inv1;
            if (qg0 < S) split_store(Osp + (rowB + qg0) * 256, plane, col0 + d, v0, v1);
            if (qg1 < S) split_store(Osp + (rowB + qg1) * 256, plane, col0 + d, v2, v3);
        }
    }
}

// ---------------------------------------------------------------------------
extern "C" void kernel_launch(void* const* d_in, const int* in_sizes, int n_in,
                              void* d_out, int out_size) {
    const float* samples  = (const float*)d_in[0];
    const float* Wq       = (const float*)d_in[1];
    const float* Wk       = (const float*)d_in[2];
    const float* Wv       = (const float*)d_in[3];
    const float* attn_w   = (const float*)d_in[4];
    const float* mha_fc_w = (const float*)d_in[5];
    const float* mha_fc_b = (const float*)d_in[6];
    const float* mha_ln_g = (const float*)d_in[7];
    const float* mha_ln_b = (const float*)d_in[8];
    const float* d_fc1_w  = (const float*)d_in[9];
    const float* d_fc1_b  = (const float*)d_in[10];
    const float* d_fc2_w  = (const float*)d_in[11];
    const float* d_fc2_b  = (const float*)d_in[12];
    const float* d_ln_g   = (const float*)d_in[13];
    const float* d_ln_b   = (const float*)d_in[14];
    const float* out_fc_w = (const float*)d_in[15];
    const float* out_fc_b = (const float*)d_in[16];
    const float* out_ln_g = (const float*)d_in[17];
    const float* out_ln_b = (const float*)d_in[18];
    const int*   Kptr     = (const int*)d_in[20];

    const int S = in_sizes[0] / (BATCH * DMODEL);
    const int M = BATCH * S;
    const size_t plane = (size_t)M * 256;

    float* base = nullptr;
    cudaGetSymbolAddress((void**)&base, g_scratch);
    __nv_bfloat16* xsp = (__nv_bfloat16*)(base + 0 * CHUNK);
    __nv_bfloat16* qsp = (__nv_bfloat16*)(base + 1 * CHUNK);
    __nv_bfloat16* ksp = (__nv_bfloat16*)(base + 2 * CHUNK);
    __half*        vsp = (__half*)(base + 3 * CHUNK);
    __nv_bfloat16* aosp = (__nv_bfloat16*)(base + 4 * CHUNK);

    __nv_bfloat16* wsp = nullptr;
    cudaGetSymbolAddress((void**)&wsp, g_wsplit);

    cudaFuncSetAttribute(attn_tc, cudaFuncAttributeMaxDynamicSharedMemorySize, ATTN_DYN);
    cudaFuncSetAttribute(gemm_tc, cudaFuncAttributeMaxDynamicSharedMemorySize, GEMM_DYN);
    cudaFuncSetAttribute(qkv_tc, cudaFuncAttributeMaxDynamicSharedMemorySize, GEMM_DYN);

    WP wp;
    wp.p[0] = Wq;        wp.p[1] = Wq + 65536;
    wp.p[2] = Wk;        wp.p[3] = Wk + 65536;
    wp.p[4] = Wv;        wp.p[5] = Wv + 65536;
    wp.p[6] = mha_fc_w;  wp.p[7] = mha_fc_w + 65536;
    wp.p[8] = d_fc1_w;   wp.p[9] = d_fc1_w + 65536;
    wp.p[10] = d_fc2_w;  wp.p[11] = d_fc2_w + 65536;
    wp.p[12] = out_fc_w;
    prep_w<<<dim3(64, 13), 256>>>(wp, wsp);
    conv_split<<<M / 4, 256>>>(samples, xsp, plane);

    dim3 ga((S + 63) / 64, NHEAD, BATCH);
    const int GR = (M + 63) / 64;

    for (int l = 0; l < 2; l++) {
        qkv_tc<<<GR, 256, GEMM_DYN>>>(xsp,
                                      wsp + (size_t)(0 + l) * 131072,
                                      wsp + (size_t)(2 + l) * 131072,
                                      wsp + (size_t)(4 + l) * 131072,
                                      qsp, ksp, vsp, plane);
        attn_tc<<<ga, 256, ATTN_DYN>>>(qsp, ksp, vsp, plane,
                                       attn_w + l * 24, Kptr, aosp, S);
        gemm_tc<<<GR, 256, GEMM_DYN>>>(aosp, wsp + (size_t)(6 + l) * 131072,
                                       mha_fc_b + l * 256, xsp, nullptr,
                                       mha_ln_g + l * 256, mha_ln_b + l * 256,
                                       xsp, nullptr, plane, 0);
        gemm_tc<<<GR, 256, GEMM_DYN>>>(xsp, wsp + (size_t)(8 + l) * 131072,
                                       d_fc1_b + l * 256, nullptr, nullptr,
                                       nullptr, nullptr, qsp, nullptr, plane, 1);
        gemm_tc<<<GR, 256, GEMM_DYN>>>(qsp, wsp + (size_t)(10 + l) * 131072,
                                       d_fc2_b + l * 256, xsp, nullptr,
                                       d_ln_g + l * 256, d_ln_b + l * 256,
                                       xsp, nullptr, plane, 0);
    }
    gemm_tc<<<GR, 256, GEMM_DYN>>>(xsp, wsp + (size_t)12 * 131072,
                                   out_fc_b, nullptr, samples,
                                   out_ln_g, out_ln_b,
                                   nullptr, (float*)d_out, plane, 0);
}